// round 1
// baseline (speedup 1.0000x reference)
#include <cuda_runtime.h>

// ---------------------------------------------------------------------------
// MultiHeadAttn: B=2, S=2048, D=1024, H=16, depth=64
//
// Stage 1: Qp/Kp/Vp = x @ W^T + b            (sgemm_nt_bias, row-major [M=4096, N=1024])
// Stage 2: flash attention per (b,h):        O = softmax(Q K^T / 8 + mask*(-1e9)) V
//          -> attn_products in [B,S,H,64]    (== [B,S,D] row-major = fc input)
// Stage 3: outputs = attn_products @ fc_w^T + fc_b
//
// Outputs: d_out = [ outputs (4096*1024 f32) | attn_products (4096*1024 f32) ]
// ---------------------------------------------------------------------------

#define NEG_INF (-3.402823466e38f)

static constexpr int Bb = 2;
static constexpr int Ss = 2048;
static constexpr int Dd = 1024;
static constexpr int Hh = 16;
static constexpr int DP = 64;
static constexpr int MM = Bb * Ss;  // 4096

// Scratch (allocation-free rule: device globals)
__device__ float g_Qp[(size_t)MM * Dd];
__device__ float g_Kp[(size_t)MM * Dd];
__device__ float g_Vp[(size_t)MM * Dd];
__device__ float g_attn_scratch[(size_t)MM * Dd];

// ---------------------------------------------------------------------------
// C[m,n] = sum_k A[m,k] * W[n,k] + bias[n]
// 128x128 tile, BK=8, 256 threads, 8x8 per-thread microtile.
// ---------------------------------------------------------------------------
__global__ __launch_bounds__(256, 2)
void sgemm_nt_bias(const float* __restrict__ A, const float* __restrict__ W,
                   const float* __restrict__ bias, float* __restrict__ C,
                   int M, int N, int K)
{
    __shared__ float As[8 * 128];
    __shared__ float Bs[8 * 128];

    const int tid = threadIdx.x;
    const int m0 = blockIdx.y * 128;
    const int n0 = blockIdx.x * 128;
    const int ar = tid >> 1;          // 0..127
    const int ac = (tid & 1) * 4;     // 0 or 4
    const int tx = tid & 15;
    const int ty = tid >> 4;

    const float* Aro = A + (size_t)(m0 + ar) * K + ac;
    const float* Wro = W + (size_t)(n0 + ar) * K + ac;

    float acc[8][8];
#pragma unroll
    for (int i = 0; i < 8; i++)
#pragma unroll
        for (int j = 0; j < 8; j++) acc[i][j] = 0.f;

    for (int k0 = 0; k0 < K; k0 += 8) {
        float4 av = *(const float4*)(Aro + k0);
        float4 bv = *(const float4*)(Wro + k0);
        __syncthreads();
        As[(ac + 0) * 128 + ar] = av.x;
        As[(ac + 1) * 128 + ar] = av.y;
        As[(ac + 2) * 128 + ar] = av.z;
        As[(ac + 3) * 128 + ar] = av.w;
        Bs[(ac + 0) * 128 + ar] = bv.x;
        Bs[(ac + 1) * 128 + ar] = bv.y;
        Bs[(ac + 2) * 128 + ar] = bv.z;
        Bs[(ac + 3) * 128 + ar] = bv.w;
        __syncthreads();

#pragma unroll
        for (int kk = 0; kk < 8; kk++) {
            float a[8], bb[8];
            *(float4*)(a + 0) = *(const float4*)&As[kk * 128 + ty * 8 + 0];
            *(float4*)(a + 4) = *(const float4*)&As[kk * 128 + ty * 8 + 4];
            *(float4*)(bb + 0) = *(const float4*)&Bs[kk * 128 + tx * 8 + 0];
            *(float4*)(bb + 4) = *(const float4*)&Bs[kk * 128 + tx * 8 + 4];
#pragma unroll
            for (int i = 0; i < 8; i++)
#pragma unroll
                for (int j = 0; j < 8; j++)
                    acc[i][j] += a[i] * bb[j];
        }
    }

    float bsv[8];
#pragma unroll
    for (int j = 0; j < 8; j++) bsv[j] = bias[n0 + tx * 8 + j];

#pragma unroll
    for (int i = 0; i < 8; i++) {
        float* crow = C + (size_t)(m0 + ty * 8 + i) * N + n0 + tx * 8;
#pragma unroll
        for (int j4 = 0; j4 < 8; j4 += 4) {
            float4 r;
            r.x = acc[i][j4 + 0] + bsv[j4 + 0];
            r.y = acc[i][j4 + 1] + bsv[j4 + 1];
            r.z = acc[i][j4 + 2] + bsv[j4 + 2];
            r.w = acc[i][j4 + 3] + bsv[j4 + 3];
            *(float4*)(crow + j4) = r;
        }
    }
}

// ---------------------------------------------------------------------------
// Flash attention. One CTA = 64 queries of one (b,h).
// Shared: Qs[64x64] natural, KVs[64x64] XOR-swizzled (K then V), Ps[64x64].
// Thread grid 16x16, 4x4 microtiles. Row reductions via half-warp shfl.
// ---------------------------------------------------------------------------
__device__ __forceinline__ int kvidx(int r, int c) { return r * 64 + (c ^ (r & 31)); }

__global__ __launch_bounds__(256)
void flash_attn(const float* __restrict__ Qp, const float* __restrict__ Kp,
                const float* __restrict__ Vp, const float* __restrict__ mask,
                float* __restrict__ Out)
{
    __shared__ float Qs[64 * 64];
    __shared__ float KVs[64 * 64];
    __shared__ float Ps[64 * 64];

    const int tid = threadIdx.x;
    const int tx = tid & 15;
    const int ty = tid >> 4;
    const int q0 = blockIdx.x * 64;
    const int h = blockIdx.y;
    const int b = blockIdx.z;

    // Load Q tile [64 q x 64 d] (row-major slice of Qp at column offset h*64)
    {
        const float* qbase = Qp + ((size_t)b * Ss + q0) * Dd + h * DP;
#pragma unroll
        for (int it = 0; it < 4; it++) {
            int u = it * 256 + tid;
            int r = u >> 4, c4 = u & 15;
            float4 v = *(const float4*)(qbase + (size_t)r * Dd + c4 * 4);
            *(float4*)&Qs[r * 64 + c4 * 4] = v;
        }
    }

    float o[4][4] = {};
    float mrow[4], lrow[4];
#pragma unroll
    for (int i = 0; i < 4; i++) { mrow[i] = NEG_INF; lrow[i] = 0.f; }

    const float* mbase = mask + (((size_t)b * Hh + h) * Ss + q0) * Ss;

    for (int kb = 0; kb < Ss / 64; kb++) {
        __syncthreads();  // KVs free (prev iter PV reads done)
        {   // load K tile (swizzled)
            const float* kbase = Kp + ((size_t)b * Ss + kb * 64) * Dd + h * DP;
#pragma unroll
            for (int it = 0; it < 4; it++) {
                int u = it * 256 + tid;
                int r = u >> 4, c4 = u & 15;
                float4 v = *(const float4*)(kbase + (size_t)r * Dd + c4 * 4);
                KVs[kvidx(r, c4 * 4 + 0)] = v.x;
                KVs[kvidx(r, c4 * 4 + 1)] = v.y;
                KVs[kvidx(r, c4 * 4 + 2)] = v.z;
                KVs[kvidx(r, c4 * 4 + 3)] = v.w;
            }
        }
        __syncthreads();

        // S = Q K^T
        float s[4][4] = {};
#pragma unroll 8
        for (int kk = 0; kk < 64; kk++) {
            float a[4], bb[4];
#pragma unroll
            for (int i = 0; i < 4; i++) a[i] = Qs[(ty * 4 + i) * 64 + kk];
#pragma unroll
            for (int j = 0; j < 4; j++) bb[j] = KVs[kvidx(tx * 4 + j, kk)];
#pragma unroll
            for (int i = 0; i < 4; i++)
#pragma unroll
                for (int j = 0; j < 4; j++)
                    s[i][j] += a[i] * bb[j];
        }

        // scale + mask
#pragma unroll
        for (int i = 0; i < 4; i++) {
            float4 mk = *(const float4*)(mbase + (size_t)(ty * 4 + i) * Ss + kb * 64 + tx * 4);
            s[i][0] = s[i][0] * 0.125f + mk.x * (-1e9f);
            s[i][1] = s[i][1] * 0.125f + mk.y * (-1e9f);
            s[i][2] = s[i][2] * 0.125f + mk.z * (-1e9f);
            s[i][3] = s[i][3] * 0.125f + mk.w * (-1e9f);
        }

        // online softmax update + write P
#pragma unroll
        for (int i = 0; i < 4; i++) {
            float rm = fmaxf(fmaxf(s[i][0], s[i][1]), fmaxf(s[i][2], s[i][3]));
#pragma unroll
            for (int off = 8; off >= 1; off >>= 1)
                rm = fmaxf(rm, __shfl_xor_sync(0xffffffffu, rm, off));
            float nm = fmaxf(mrow[i], rm);
            float scale = __expf(mrow[i] - nm);
            float rs = 0.f;
#pragma unroll
            for (int j = 0; j < 4; j++) {
                float p = __expf(s[i][j] - nm);
                s[i][j] = p;
                rs += p;
            }
#pragma unroll
            for (int off = 8; off >= 1; off >>= 1)
                rs += __shfl_xor_sync(0xffffffffu, rs, off);
            lrow[i] = lrow[i] * scale + rs;
            mrow[i] = nm;
#pragma unroll
            for (int j = 0; j < 4; j++) o[i][j] *= scale;
#pragma unroll
            for (int j = 0; j < 4; j++) Ps[(ty * 4 + i) * 64 + tx * 4 + j] = s[i][j];
        }
        __syncthreads();  // K reads + P writes done

        {   // load V tile (swizzled, same buffer)
            const float* vbase = Vp + ((size_t)b * Ss + kb * 64) * Dd + h * DP;
#pragma unroll
            for (int it = 0; it < 4; it++) {
                int u = it * 256 + tid;
                int r = u >> 4, c4 = u & 15;
                float4 v = *(const float4*)(vbase + (size_t)r * Dd + c4 * 4);
                KVs[kvidx(r, c4 * 4 + 0)] = v.x;
                KVs[kvidx(r, c4 * 4 + 1)] = v.y;
                KVs[kvidx(r, c4 * 4 + 2)] = v.z;
                KVs[kvidx(r, c4 * 4 + 3)] = v.w;
            }
        }
        __syncthreads();

        // O += P V
#pragma unroll 8
        for (int kk = 0; kk < 64; kk++) {
            float a[4], bb[4];
#pragma unroll
            for (int i = 0; i < 4; i++) a[i] = Ps[(ty * 4 + i) * 64 + kk];
#pragma unroll
            for (int j = 0; j < 4; j++) bb[j] = KVs[kvidx(kk, tx * 4 + j)];
#pragma unroll
            for (int i = 0; i < 4; i++)
#pragma unroll
                for (int j = 0; j < 4; j++)
                    o[i][j] += a[i] * bb[j];
        }
    }

    // epilogue: attn_products[b, q, h, d] = O / l
#pragma unroll
    for (int i = 0; i < 4; i++) {
        float inv = 1.f / lrow[i];
        float4 r;
        r.x = o[i][0] * inv;
        r.y = o[i][1] * inv;
        r.z = o[i][2] * inv;
        r.w = o[i][3] * inv;
        *(float4*)(Out + (((size_t)b * Ss + q0 + ty * 4 + i) * Hh + h) * DP + tx * 4) = r;
    }
}

// ---------------------------------------------------------------------------
extern "C" void kernel_launch(void* const* d_in, const int* in_sizes, int n_in,
                              void* d_out, int out_size)
{
    const float* q    = (const float*)d_in[0];
    const float* k    = (const float*)d_in[1];
    const float* v    = (const float*)d_in[2];
    const float* mask = (const float*)d_in[3];
    const float* wq_w = (const float*)d_in[4];
    const float* wq_b = (const float*)d_in[5];
    const float* wk_w = (const float*)d_in[6];
    const float* wk_b = (const float*)d_in[7];
    const float* wv_w = (const float*)d_in[8];
    const float* wv_b = (const float*)d_in[9];
    const float* fc_w = (const float*)d_in[10];
    const float* fc_b = (const float*)d_in[11];

    float *pQ, *pK, *pV, *pScr;
    cudaGetSymbolAddress((void**)&pQ, g_Qp);
    cudaGetSymbolAddress((void**)&pK, g_Kp);
    cudaGetSymbolAddress((void**)&pV, g_Vp);
    cudaGetSymbolAddress((void**)&pScr, g_attn_scratch);

    float* out_main = (float*)d_out;
    const size_t OUT1 = (size_t)MM * Dd;  // 4194304
    // outputs first, attn_products second (reference returns (outputs, attn_products))
    float* attn_out = ((size_t)out_size >= 2 * OUT1) ? (out_main + OUT1) : pScr;

    dim3 gemm_grid(Dd / 128, MM / 128);  // (8, 32)

    sgemm_nt_bias<<<gemm_grid, 256>>>(q, wq_w, wq_b, pQ, MM, Dd, Dd);
    sgemm_nt_bias<<<gemm_grid, 256>>>(k, wk_w, wk_b, pK, MM, Dd, Dd);
    sgemm_nt_bias<<<gemm_grid, 256>>>(v, wv_w, wv_b, pV, MM, Dd, Dd);

    flash_attn<<<dim3(Ss / 64, Hh, Bb), 256>>>(pQ, pK, pV, mask, attn_out);

    sgemm_nt_bias<<<gemm_grid, 256>>>(attn_out, fc_w, fc_b, out_main, MM, Dd, Dd);
}

// round 2
// speedup vs baseline: 1.2901x; 1.2901x over previous
#include <cuda_runtime.h>
#include <cstdint>

// ---------------------------------------------------------------------------
// MultiHeadAttn: B=2, S=2048, D=1024, H=16, depth=64
//
// Stage 1: Qp/Kp/Vp = x @ W^T + b      (gemm_tf32: mma.sync m16n8k8 tf32)
// Stage 2: flash attention (fp32 SIMT, unchanged from R1 passing kernel)
// Stage 3: outputs = attn @ fc_w^T + b (gemm_tf32)
// ---------------------------------------------------------------------------

#define NEG_INF (-3.402823466e38f)

static constexpr int Bb = 2;
static constexpr int Ss = 2048;
static constexpr int Dd = 1024;
static constexpr int Hh = 16;
static constexpr int DP = 64;
static constexpr int MM = Bb * Ss;  // 4096

__device__ float g_Qp[(size_t)MM * Dd];
__device__ float g_Kp[(size_t)MM * Dd];
__device__ float g_Vp[(size_t)MM * Dd];
__device__ float g_attn_scratch[(size_t)MM * Dd];

// ---------------------------------------------------------------------------
// PTX helpers
// ---------------------------------------------------------------------------
__device__ __forceinline__ uint32_t cvta_smem(const void* p) {
    return (uint32_t)__cvta_generic_to_shared(p);
}
__device__ __forceinline__ void cp_async16(uint32_t dst, const void* src) {
    asm volatile("cp.async.cg.shared.global [%0], [%1], 16;\n" :: "r"(dst), "l"(src));
}
__device__ __forceinline__ void cp_commit() {
    asm volatile("cp.async.commit_group;\n");
}
__device__ __forceinline__ void cp_wait0() {
    asm volatile("cp.async.wait_group 0;\n");
}
__device__ __forceinline__ void ldsm_x4(uint32_t& r0, uint32_t& r1, uint32_t& r2, uint32_t& r3,
                                        uint32_t addr) {
    asm volatile("ldmatrix.sync.aligned.m8n8.x4.shared.b16 {%0,%1,%2,%3}, [%4];\n"
                 : "=r"(r0), "=r"(r1), "=r"(r2), "=r"(r3) : "r"(addr));
}
__device__ __forceinline__ uint32_t f2tf32(uint32_t bits) {
    float f = __uint_as_float(bits);
    uint32_t r;
    asm volatile("cvt.rna.tf32.f32 %0, %1;\n" : "=r"(r) : "f"(f));
    return r;
}
__device__ __forceinline__ void mma_tf32(float& d0, float& d1, float& d2, float& d3,
                                         uint32_t a0, uint32_t a1, uint32_t a2, uint32_t a3,
                                         uint32_t b0, uint32_t b1) {
    asm volatile(
        "mma.sync.aligned.m16n8k8.row.col.f32.tf32.tf32.f32 "
        "{%0,%1,%2,%3}, {%4,%5,%6,%7}, {%8,%9}, {%0,%1,%2,%3};\n"
        : "+f"(d0), "+f"(d1), "+f"(d2), "+f"(d3)
        : "r"(a0), "r"(a1), "r"(a2), "r"(a3), "r"(b0), "r"(b1));
}

// ---------------------------------------------------------------------------
// tf32 tensor-core GEMM: C[m,n] = sum_k A[m,k]*W[n,k] + bias[n]
// BM=128, BN=128, BK=16, 256 threads (8 warps, 2x4), warp tile 64x32.
// smem: pad-20 row layout -> conflict-free ldmatrix; cp.async double buffer.
// ---------------------------------------------------------------------------
#define GBM 128
#define GBN 128
#define GBK 16
#define GSTR 20                      // floats per smem row (16 + 4 pad)
#define GTILE_BYTES (GBM * GSTR * 4) // one buffer

__global__ __launch_bounds__(256)
void gemm_tf32(const float* __restrict__ A, const float* __restrict__ W,
               const float* __restrict__ bias, float* __restrict__ C,
               int M, int N, int K)
{
    __shared__ __align__(16) float As[2][GBM * GSTR];
    __shared__ __align__(16) float Bs[2][GBN * GSTR];

    const int tid  = threadIdx.x;
    const int lane = tid & 31;
    const int wid  = tid >> 5;
    const int wm   = (wid & 1) * 64;   // warp m offset in tile
    const int wn   = (wid >> 1) * 32;  // warp n offset in tile
    const int m0   = blockIdx.y * GBM;
    const int n0   = blockIdx.x * GBN;

    const uint32_t sA = cvta_smem(As);
    const uint32_t sB = cvta_smem(Bs);

    // ---- gmem -> smem loader mapping: 512 float4 per tile, 2 per thread ----
    const int lr0 = tid >> 2;        // rows 0..63
    const int lg  = (tid & 3) * 4;   // k-granule offset in floats
    const float* Ap0 = A + (size_t)(m0 + lr0) * K + lg;
    const float* Ap1 = A + (size_t)(m0 + lr0 + 64) * K + lg;
    const float* Wp0 = W + (size_t)(n0 + lr0) * K + lg;
    const float* Wp1 = W + (size_t)(n0 + lr0 + 64) * K + lg;
    const uint32_t dA0 = sA + (uint32_t)((lr0 * GSTR + lg) * 4);
    const uint32_t dA1 = sA + (uint32_t)(((lr0 + 64) * GSTR + lg) * 4);
    const uint32_t dB0 = sB + (uint32_t)((lr0 * GSTR + lg) * 4);
    const uint32_t dB1 = sB + (uint32_t)(((lr0 + 64) * GSTR + lg) * 4);

    // ---- ldmatrix per-lane base addresses ----
    const int g       = lane >> 3;                 // 0..3
    const int glr     = lane & 7;
    const int row_add = ((g >> 1) << 3) + glr;     // +8 for g>=2
    const int koff    = (g & 1) << 2;              // +4 floats for odd g
    const uint32_t aBase = sA + (uint32_t)(((wm + row_add) * GSTR + koff) * 4);
    const uint32_t bBase = sB + (uint32_t)(((wn + row_add) * GSTR + koff) * 4);

    float acc[4][4][4];
#pragma unroll
    for (int i = 0; i < 4; i++)
#pragma unroll
        for (int j = 0; j < 4; j++)
#pragma unroll
            for (int c = 0; c < 4; c++) acc[i][j][c] = 0.f;

    const int NSTAGE = K / GBK;

    // prologue: stage 0
    {
        cp_async16(dA0, Ap0); cp_async16(dA1, Ap1);
        cp_async16(dB0, Wp0); cp_async16(dB1, Wp1);
        cp_commit();
    }

    for (int kt = 0; kt < NSTAGE; kt++) {
        cp_wait0();
        __syncthreads();

        if (kt + 1 < NSTAGE) {
            const int k0 = (kt + 1) * GBK;
            const uint32_t bo = (uint32_t)(((kt + 1) & 1) * GTILE_BYTES);
            cp_async16(dA0 + bo, Ap0 + k0);
            cp_async16(dA1 + bo, Ap1 + k0);
            cp_async16(dB0 + bo, Wp0 + k0);
            cp_async16(dB1 + bo, Wp1 + k0);
            cp_commit();
        }

        const uint32_t bo = (uint32_t)((kt & 1) * GTILE_BYTES);
#pragma unroll
        for (int ks = 0; ks < 2; ks++) {
            const uint32_t ao = aBase + bo + (uint32_t)(ks * 32);
            const uint32_t bb = bBase + bo + (uint32_t)(ks * 32);

            uint32_t af[4][4], bf[4][2];
#pragma unroll
            for (int mt = 0; mt < 4; mt++) {
                uint32_t r0, r1, r2, r3;
                ldsm_x4(r0, r1, r2, r3, ao + (uint32_t)(mt * 16 * GSTR * 4));
                af[mt][0] = f2tf32(r0);   // a0: (row, k0..3)
                af[mt][1] = f2tf32(r2);   // a1: (row+8, k0..3)
                af[mt][2] = f2tf32(r1);   // a2: (row, k4..7)
                af[mt][3] = f2tf32(r3);   // a3: (row+8, k4..7)
            }
#pragma unroll
            for (int p = 0; p < 2; p++) {
                uint32_t r0, r1, r2, r3;
                ldsm_x4(r0, r1, r2, r3, bb + (uint32_t)(p * 16 * GSTR * 4));
                bf[2 * p][0]     = f2tf32(r0);
                bf[2 * p][1]     = f2tf32(r1);
                bf[2 * p + 1][0] = f2tf32(r2);
                bf[2 * p + 1][1] = f2tf32(r3);
            }
#pragma unroll
            for (int mt = 0; mt < 4; mt++)
#pragma unroll
                for (int nt = 0; nt < 4; nt++)
                    mma_tf32(acc[mt][nt][0], acc[mt][nt][1], acc[mt][nt][2], acc[mt][nt][3],
                             af[mt][0], af[mt][1], af[mt][2], af[mt][3],
                             bf[nt][0], bf[nt][1]);
        }
        __syncthreads();
    }

    // epilogue
#pragma unroll
    for (int mt = 0; mt < 4; mt++) {
        const int row = m0 + wm + mt * 16 + (lane >> 2);
#pragma unroll
        for (int nt = 0; nt < 4; nt++) {
            const int col = n0 + wn + nt * 8 + (lane & 3) * 2;
            const float b0 = bias[col], b1 = bias[col + 1];
            float2 v0 = make_float2(acc[mt][nt][0] + b0, acc[mt][nt][1] + b1);
            float2 v1 = make_float2(acc[mt][nt][2] + b0, acc[mt][nt][3] + b1);
            *(float2*)&C[(size_t)row * N + col]       = v0;
            *(float2*)&C[(size_t)(row + 8) * N + col] = v1;
        }
    }
}

// ---------------------------------------------------------------------------
// Flash attention (unchanged from R1 passing kernel).
// ---------------------------------------------------------------------------
__device__ __forceinline__ int kvidx(int r, int c) { return r * 64 + (c ^ (r & 31)); }

__global__ __launch_bounds__(256)
void flash_attn(const float* __restrict__ Qp, const float* __restrict__ Kp,
                const float* __restrict__ Vp, const float* __restrict__ mask,
                float* __restrict__ Out)
{
    __shared__ float Qs[64 * 64];
    __shared__ float KVs[64 * 64];
    __shared__ float Ps[64 * 64];

    const int tid = threadIdx.x;
    const int tx = tid & 15;
    const int ty = tid >> 4;
    const int q0 = blockIdx.x * 64;
    const int h = blockIdx.y;
    const int b = blockIdx.z;

    {
        const float* qbase = Qp + ((size_t)b * Ss + q0) * Dd + h * DP;
#pragma unroll
        for (int it = 0; it < 4; it++) {
            int u = it * 256 + tid;
            int r = u >> 4, c4 = u & 15;
            float4 v = *(const float4*)(qbase + (size_t)r * Dd + c4 * 4);
            *(float4*)&Qs[r * 64 + c4 * 4] = v;
        }
    }

    float o[4][4] = {};
    float mrow[4], lrow[4];
#pragma unroll
    for (int i = 0; i < 4; i++) { mrow[i] = NEG_INF; lrow[i] = 0.f; }

    const float* mbase = mask + (((size_t)b * Hh + h) * Ss + q0) * Ss;

    for (int kb = 0; kb < Ss / 64; kb++) {
        __syncthreads();
        {
            const float* kbase = Kp + ((size_t)b * Ss + kb * 64) * Dd + h * DP;
#pragma unroll
            for (int it = 0; it < 4; it++) {
                int u = it * 256 + tid;
                int r = u >> 4, c4 = u & 15;
                float4 v = *(const float4*)(kbase + (size_t)r * Dd + c4 * 4);
                KVs[kvidx(r, c4 * 4 + 0)] = v.x;
                KVs[kvidx(r, c4 * 4 + 1)] = v.y;
                KVs[kvidx(r, c4 * 4 + 2)] = v.z;
                KVs[kvidx(r, c4 * 4 + 3)] = v.w;
            }
        }
        __syncthreads();

        float s[4][4] = {};
#pragma unroll 8
        for (int kk = 0; kk < 64; kk++) {
            float a[4], bb[4];
#pragma unroll
            for (int i = 0; i < 4; i++) a[i] = Qs[(ty * 4 + i) * 64 + kk];
#pragma unroll
            for (int j = 0; j < 4; j++) bb[j] = KVs[kvidx(tx * 4 + j, kk)];
#pragma unroll
            for (int i = 0; i < 4; i++)
#pragma unroll
                for (int j = 0; j < 4; j++)
                    s[i][j] += a[i] * bb[j];
        }

#pragma unroll
        for (int i = 0; i < 4; i++) {
            float4 mk = *(const float4*)(mbase + (size_t)(ty * 4 + i) * Ss + kb * 64 + tx * 4);
            s[i][0] = s[i][0] * 0.125f + mk.x * (-1e9f);
            s[i][1] = s[i][1] * 0.125f + mk.y * (-1e9f);
            s[i][2] = s[i][2] * 0.125f + mk.z * (-1e9f);
            s[i][3] = s[i][3] * 0.125f + mk.w * (-1e9f);
        }

#pragma unroll
        for (int i = 0; i < 4; i++) {
            float rm = fmaxf(fmaxf(s[i][0], s[i][1]), fmaxf(s[i][2], s[i][3]));
#pragma unroll
            for (int off = 8; off >= 1; off >>= 1)
                rm = fmaxf(rm, __shfl_xor_sync(0xffffffffu, rm, off));
            float nm = fmaxf(mrow[i], rm);
            float scale = __expf(mrow[i] - nm);
            float rs = 0.f;
#pragma unroll
            for (int j = 0; j < 4; j++) {
                float p = __expf(s[i][j] - nm);
                s[i][j] = p;
                rs += p;
            }
#pragma unroll
            for (int off = 8; off >= 1; off >>= 1)
                rs += __shfl_xor_sync(0xffffffffu, rs, off);
            lrow[i] = lrow[i] * scale + rs;
            mrow[i] = nm;
#pragma unroll
            for (int j = 0; j < 4; j++) o[i][j] *= scale;
#pragma unroll
            for (int j = 0; j < 4; j++) Ps[(ty * 4 + i) * 64 + tx * 4 + j] = s[i][j];
        }
        __syncthreads();

        {
            const float* vbase = Vp + ((size_t)b * Ss + kb * 64) * Dd + h * DP;
#pragma unroll
            for (int it = 0; it < 4; it++) {
                int u = it * 256 + tid;
                int r = u >> 4, c4 = u & 15;
                float4 v = *(const float4*)(vbase + (size_t)r * Dd + c4 * 4);
                KVs[kvidx(r, c4 * 4 + 0)] = v.x;
                KVs[kvidx(r, c4 * 4 + 1)] = v.y;
                KVs[kvidx(r, c4 * 4 + 2)] = v.z;
                KVs[kvidx(r, c4 * 4 + 3)] = v.w;
            }
        }
        __syncthreads();

#pragma unroll 8
        for (int kk = 0; kk < 64; kk++) {
            float a[4], bb[4];
#pragma unroll
            for (int i = 0; i < 4; i++) a[i] = Ps[(ty * 4 + i) * 64 + kk];
#pragma unroll
            for (int j = 0; j < 4; j++) bb[j] = KVs[kvidx(kk, tx * 4 + j)];
#pragma unroll
            for (int i = 0; i < 4; i++)
#pragma unroll
                for (int j = 0; j < 4; j++)
                    o[i][j] += a[i] * bb[j];
        }
    }

#pragma unroll
    for (int i = 0; i < 4; i++) {
        float inv = 1.f / lrow[i];
        float4 r;
        r.x = o[i][0] * inv;
        r.y = o[i][1] * inv;
        r.z = o[i][2] * inv;
        r.w = o[i][3] * inv;
        *(float4*)(Out + (((size_t)b * Ss + q0 + ty * 4 + i) * Hh + h) * DP + tx * 4) = r;
    }
}

// ---------------------------------------------------------------------------
extern "C" void kernel_launch(void* const* d_in, const int* in_sizes, int n_in,
                              void* d_out, int out_size)
{
    const float* q    = (const float*)d_in[0];
    const float* k    = (const float*)d_in[1];
    const float* v    = (const float*)d_in[2];
    const float* mask = (const float*)d_in[3];
    const float* wq_w = (const float*)d_in[4];
    const float* wq_b = (const float*)d_in[5];
    const float* wk_w = (const float*)d_in[6];
    const float* wk_b = (const float*)d_in[7];
    const float* wv_w = (const float*)d_in[8];
    const float* wv_b = (const float*)d_in[9];
    const float* fc_w = (const float*)d_in[10];
    const float* fc_b = (const float*)d_in[11];

    float *pQ, *pK, *pV, *pScr;
    cudaGetSymbolAddress((void**)&pQ, g_Qp);
    cudaGetSymbolAddress((void**)&pK, g_Kp);
    cudaGetSymbolAddress((void**)&pV, g_Vp);
    cudaGetSymbolAddress((void**)&pScr, g_attn_scratch);

    float* out_main = (float*)d_out;
    const size_t OUT1 = (size_t)MM * Dd;  // 4194304
    float* attn_out = ((size_t)out_size >= 2 * OUT1) ? (out_main + OUT1) : pScr;

    dim3 gemm_grid(Dd / GBN, MM / GBM);  // (8, 32)

    gemm_tf32<<<gemm_grid, 256>>>(q, wq_w, wq_b, pQ, MM, Dd, Dd);
    gemm_tf32<<<gemm_grid, 256>>>(k, wk_w, wk_b, pK, MM, Dd, Dd);
    gemm_tf32<<<gemm_grid, 256>>>(v, wv_w, wv_b, pV, MM, Dd, Dd);

    flash_attn<<<dim3(Ss / 64, Hh, Bb), 256>>>(pQ, pK, pV, mask, attn_out);

    gemm_tf32<<<gemm_grid, 256>>>(attn_out, fc_w, fc_b, out_main, MM, Dd, Dd);
}

// round 3
// speedup vs baseline: 2.4306x; 1.8840x over previous
#include <cuda_runtime.h>
#include <cstdint>

// ---------------------------------------------------------------------------
// MultiHeadAttn: B=2, S=2048, D=1024, H=16, depth=64
// Stage 1: Qp/Kp/Vp projections  (gemm_tf32, mma.sync m16n8k8)
// Stage 2: flash attention, tensor-core tf32 (QK^T split-tf32, PV plain tf32)
// Stage 3: fc output projection  (gemm_tf32)
// ---------------------------------------------------------------------------

#define NEG_INF (-3.402823466e38f)

static constexpr int Bb = 2;
static constexpr int Ss = 2048;
static constexpr int Dd = 1024;
static constexpr int Hh = 16;
static constexpr int DP = 64;
static constexpr int MM = Bb * Ss;  // 4096

__device__ float g_Qp[(size_t)MM * Dd];
__device__ float g_Kp[(size_t)MM * Dd];
__device__ float g_Vp[(size_t)MM * Dd];
__device__ float g_attn_scratch[(size_t)MM * Dd];

// ---------------------------------------------------------------------------
// PTX helpers
// ---------------------------------------------------------------------------
__device__ __forceinline__ uint32_t cvta_smem(const void* p) {
    return (uint32_t)__cvta_generic_to_shared(p);
}
__device__ __forceinline__ void cp_async16(uint32_t dst, const void* src) {
    asm volatile("cp.async.cg.shared.global [%0], [%1], 16;\n" :: "r"(dst), "l"(src));
}
__device__ __forceinline__ void cp_commit() {
    asm volatile("cp.async.commit_group;\n");
}
__device__ __forceinline__ void cp_wait0() {
    asm volatile("cp.async.wait_group 0;\n");
}
__device__ __forceinline__ void cp_wait1() {
    asm volatile("cp.async.wait_group 1;\n");
}
__device__ __forceinline__ void ldsm_x4(uint32_t& r0, uint32_t& r1, uint32_t& r2, uint32_t& r3,
                                        uint32_t addr) {
    asm volatile("ldmatrix.sync.aligned.m8n8.x4.shared.b16 {%0,%1,%2,%3}, [%4];\n"
                 : "=r"(r0), "=r"(r1), "=r"(r2), "=r"(r3) : "r"(addr));
}
__device__ __forceinline__ uint32_t f2tf32(uint32_t bits) {
    float f = __uint_as_float(bits);
    uint32_t r;
    asm volatile("cvt.rna.tf32.f32 %0, %1;\n" : "=r"(r) : "f"(f));
    return r;
}
__device__ __forceinline__ uint32_t tf32_lo(uint32_t bits, uint32_t hi) {
    float d = __uint_as_float(bits) - __uint_as_float(hi);
    uint32_t r;
    asm volatile("cvt.rna.tf32.f32 %0, %1;\n" : "=r"(r) : "f"(d));
    return r;
}
__device__ __forceinline__ void mma_tf32(float& d0, float& d1, float& d2, float& d3,
                                         uint32_t a0, uint32_t a1, uint32_t a2, uint32_t a3,
                                         uint32_t b0, uint32_t b1) {
    asm volatile(
        "mma.sync.aligned.m16n8k8.row.col.f32.tf32.tf32.f32 "
        "{%0,%1,%2,%3}, {%4,%5,%6,%7}, {%8,%9}, {%0,%1,%2,%3};\n"
        : "+f"(d0), "+f"(d1), "+f"(d2), "+f"(d3)
        : "r"(a0), "r"(a1), "r"(a2), "r"(a3), "r"(b0), "r"(b1));
}

// ---------------------------------------------------------------------------
// tf32 tensor-core GEMM (unchanged from R2 passing kernel)
// ---------------------------------------------------------------------------
#define GBM 128
#define GBN 128
#define GBK 16
#define GSTR 20
#define GTILE_BYTES (GBM * GSTR * 4)

__global__ __launch_bounds__(256)
void gemm_tf32(const float* __restrict__ A, const float* __restrict__ W,
               const float* __restrict__ bias, float* __restrict__ C,
               int M, int N, int K)
{
    __shared__ __align__(16) float As[2][GBM * GSTR];
    __shared__ __align__(16) float Bs[2][GBN * GSTR];

    const int tid  = threadIdx.x;
    const int lane = tid & 31;
    const int wid  = tid >> 5;
    const int wm   = (wid & 1) * 64;
    const int wn   = (wid >> 1) * 32;
    const int m0   = blockIdx.y * GBM;
    const int n0   = blockIdx.x * GBN;

    const uint32_t sA = cvta_smem(As);
    const uint32_t sB = cvta_smem(Bs);

    const int lr0 = tid >> 2;
    const int lg  = (tid & 3) * 4;
    const float* Ap0 = A + (size_t)(m0 + lr0) * K + lg;
    const float* Ap1 = A + (size_t)(m0 + lr0 + 64) * K + lg;
    const float* Wp0 = W + (size_t)(n0 + lr0) * K + lg;
    const float* Wp1 = W + (size_t)(n0 + lr0 + 64) * K + lg;
    const uint32_t dA0 = sA + (uint32_t)((lr0 * GSTR + lg) * 4);
    const uint32_t dA1 = sA + (uint32_t)(((lr0 + 64) * GSTR + lg) * 4);
    const uint32_t dB0 = sB + (uint32_t)((lr0 * GSTR + lg) * 4);
    const uint32_t dB1 = sB + (uint32_t)(((lr0 + 64) * GSTR + lg) * 4);

    const int g       = lane >> 3;
    const int glr     = lane & 7;
    const int row_add = ((g >> 1) << 3) + glr;
    const int koff    = (g & 1) << 2;
    const uint32_t aBase = sA + (uint32_t)(((wm + row_add) * GSTR + koff) * 4);
    const uint32_t bBase = sB + (uint32_t)(((wn + row_add) * GSTR + koff) * 4);

    float acc[4][4][4];
#pragma unroll
    for (int i = 0; i < 4; i++)
#pragma unroll
        for (int j = 0; j < 4; j++)
#pragma unroll
            for (int c = 0; c < 4; c++) acc[i][j][c] = 0.f;

    const int NSTAGE = K / GBK;

    cp_async16(dA0, Ap0); cp_async16(dA1, Ap1);
    cp_async16(dB0, Wp0); cp_async16(dB1, Wp1);
    cp_commit();

    for (int kt = 0; kt < NSTAGE; kt++) {
        cp_wait0();
        __syncthreads();

        if (kt + 1 < NSTAGE) {
            const int k0 = (kt + 1) * GBK;
            const uint32_t bo = (uint32_t)(((kt + 1) & 1) * GTILE_BYTES);
            cp_async16(dA0 + bo, Ap0 + k0);
            cp_async16(dA1 + bo, Ap1 + k0);
            cp_async16(dB0 + bo, Wp0 + k0);
            cp_async16(dB1 + bo, Wp1 + k0);
            cp_commit();
        }

        const uint32_t bo = (uint32_t)((kt & 1) * GTILE_BYTES);
#pragma unroll
        for (int ks = 0; ks < 2; ks++) {
            const uint32_t ao = aBase + bo + (uint32_t)(ks * 32);
            const uint32_t bb = bBase + bo + (uint32_t)(ks * 32);

            uint32_t af[4][4], bf[4][2];
#pragma unroll
            for (int mt = 0; mt < 4; mt++) {
                uint32_t r0, r1, r2, r3;
                ldsm_x4(r0, r1, r2, r3, ao + (uint32_t)(mt * 16 * GSTR * 4));
                af[mt][0] = f2tf32(r0);
                af[mt][1] = f2tf32(r2);
                af[mt][2] = f2tf32(r1);
                af[mt][3] = f2tf32(r3);
            }
#pragma unroll
            for (int p = 0; p < 2; p++) {
                uint32_t r0, r1, r2, r3;
                ldsm_x4(r0, r1, r2, r3, bb + (uint32_t)(p * 16 * GSTR * 4));
                bf[2 * p][0]     = f2tf32(r0);
                bf[2 * p][1]     = f2tf32(r1);
                bf[2 * p + 1][0] = f2tf32(r2);
                bf[2 * p + 1][1] = f2tf32(r3);
            }
#pragma unroll
            for (int mt = 0; mt < 4; mt++)
#pragma unroll
                for (int nt = 0; nt < 4; nt++)
                    mma_tf32(acc[mt][nt][0], acc[mt][nt][1], acc[mt][nt][2], acc[mt][nt][3],
                             af[mt][0], af[mt][1], af[mt][2], af[mt][3],
                             bf[nt][0], bf[nt][1]);
        }
        __syncthreads();
    }

#pragma unroll
    for (int mt = 0; mt < 4; mt++) {
        const int row = m0 + wm + mt * 16 + (lane >> 2);
#pragma unroll
        for (int nt = 0; nt < 4; nt++) {
            const int col = n0 + wn + nt * 8 + (lane & 3) * 2;
            const float b0 = bias[col], b1 = bias[col + 1];
            float2 v0 = make_float2(acc[mt][nt][0] + b0, acc[mt][nt][1] + b1);
            float2 v1 = make_float2(acc[mt][nt][2] + b0, acc[mt][nt][3] + b1);
            *(float2*)&C[(size_t)row * N + col]       = v0;
            *(float2*)&C[(size_t)(row + 8) * N + col] = v1;
        }
    }
}

// ---------------------------------------------------------------------------
// Tensor-core flash attention.
// CTA: 128 queries x one (b,h). 8 warps x 16 rows. Key tiles of 64.
// QK^T: split-tf32 (3 mma)  |  PV: plain tf32.
// smem (dynamic, 119KB): K double buf | Vraw double buf | Vt | P (alias Q stage)
// Row stride 68 floats -> conflict-free ldmatrix.
// ---------------------------------------------------------------------------
#define FSTR 68
#define KV_TILE (64 * FSTR)              // floats per K or V buffer
#define FLASH_SMEM_FLOATS (2*KV_TILE + 2*KV_TILE + KV_TILE + 128*FSTR)
#define FLASH_SMEM_BYTES (FLASH_SMEM_FLOATS * 4)

__global__ __launch_bounds__(256, 1)
void flash_attn_tc(const float* __restrict__ Qp, const float* __restrict__ Kp,
                   const float* __restrict__ Vp, const float* __restrict__ mask,
                   float* __restrict__ Out)
{
    extern __shared__ float fsm[];
    float* Kbuf = fsm;                       // 2 * 64*68
    float* Vraw = Kbuf + 2 * KV_TILE;        // 2 * 64*68
    float* Vt   = Vraw + 2 * KV_TILE;        // 64*68
    float* Pbuf = Vt + KV_TILE;              // 128*68 (Q staging, then P)

    const uint32_t sK = cvta_smem(Kbuf);
    const uint32_t sV = cvta_smem(Vraw);
    const uint32_t sVt = cvta_smem(Vt);
    const uint32_t sP = cvta_smem(Pbuf);

    const int tid  = threadIdx.x;
    const int lane = tid & 31;
    const int wid  = tid >> 5;
    const int wm   = wid * 16;             // warp's first query row in tile
    const int q0   = blockIdx.x * 128;
    const int h    = blockIdx.y;
    const int b    = blockIdx.z;

    const float* Qg = Qp + ((size_t)b * Ss + q0) * Dd + h * DP;
    const float* Kg = Kp + ((size_t)b * Ss) * Dd + h * DP;
    const float* Vg = Vp + ((size_t)b * Ss) * Dd + h * DP;
    const float* Mg = mask + (((size_t)b * Hh + h) * Ss + q0) * Ss;

    // ldmatrix lane mapping (validated in gemm_tf32)
    const int g       = lane >> 3;
    const int glr     = lane & 7;
    const int row_add = ((g >> 1) << 3) + glr;
    const int koff    = (g & 1) << 2;

    const int rq = lane >> 2;     // 0..7: fragment row within 8
    const int cq = lane & 3;      // fragment col quad

    // ---- prefetch K/V tile 0 ----
    {
#pragma unroll
        for (int i = 0; i < 4; i++) {
            int id = tid + 256 * i;           // 0..1023
            int row = id >> 4, col = id & 15; // 64 rows x 16 chunks
            cp_async16(sK + (uint32_t)((row * FSTR + col * 4) * 4),
                       Kg + (size_t)row * Dd + col * 4);
        }
#pragma unroll
        for (int i = 0; i < 4; i++) {
            int id = tid + 256 * i;
            int row = id >> 4, col = id & 15;
            cp_async16(sV + (uint32_t)((row * FSTR + col * 4) * 4),
                       Vg + (size_t)row * Dd + col * 4);
        }
        cp_commit();
    }

    // ---- stage Q into Pbuf, extract fragments (hi/lo) ----
#pragma unroll
    for (int i = 0; i < 8; i++) {
        int id = tid + 256 * i;               // 0..2047
        int row = id >> 4, col = id & 15;     // 128 rows x 16 chunks
        float4 v = *(const float4*)(Qg + (size_t)row * Dd + col * 4);
        *(float4*)&Pbuf[row * FSTR + col * 4] = v;
    }
    __syncthreads();

    uint32_t Qh[8][4], Ql[8][4];
    {
        const uint32_t base = sP + (uint32_t)(((wm + row_add) * FSTR + koff) * 4);
#pragma unroll
        for (int ks = 0; ks < 8; ks++) {
            uint32_t r0, r1, r2, r3;
            ldsm_x4(r0, r1, r2, r3, base + (uint32_t)(ks * 32));
            // a0=r0, a1=r2, a2=r1, a3=r3
            Qh[ks][0] = f2tf32(r0); Ql[ks][0] = tf32_lo(r0, Qh[ks][0]);
            Qh[ks][1] = f2tf32(r2); Ql[ks][1] = tf32_lo(r2, Qh[ks][1]);
            Qh[ks][2] = f2tf32(r1); Ql[ks][2] = tf32_lo(r1, Qh[ks][2]);
            Qh[ks][3] = f2tf32(r3); Ql[ks][3] = tf32_lo(r3, Qh[ks][3]);
        }
    }

    float O[8][4];
#pragma unroll
    for (int nt = 0; nt < 8; nt++)
#pragma unroll
        for (int c = 0; c < 4; c++) O[nt][c] = 0.f;
    float m0r = NEG_INF, m1r = NEG_INF, l0r = 0.f, l1r = 0.f;

    for (int kt = 0; kt < 32; kt++) {
        // prefetch next tile
        if (kt + 1 < 32) {
            const uint32_t bo = (uint32_t)(((kt + 1) & 1) * KV_TILE * 4);
            const float* kg = Kg + (size_t)(kt + 1) * 64 * Dd;
            const float* vg = Vg + (size_t)(kt + 1) * 64 * Dd;
#pragma unroll
            for (int i = 0; i < 4; i++) {
                int id = tid + 256 * i;
                int row = id >> 4, col = id & 15;
                cp_async16(sK + bo + (uint32_t)((row * FSTR + col * 4) * 4),
                           kg + (size_t)row * Dd + col * 4);
            }
#pragma unroll
            for (int i = 0; i < 4; i++) {
                int id = tid + 256 * i;
                int row = id >> 4, col = id & 15;
                cp_async16(sV + bo + (uint32_t)((row * FSTR + col * 4) * 4),
                           vg + (size_t)row * Dd + col * 4);
            }
            cp_commit();
            cp_wait1();
        } else {
            cp_wait0();
        }
        __syncthreads();   // K/V of tile kt visible; Pbuf/Vt free

        // mask fragments (start DRAM loads early, overlap with QK mma)
        float2 mk0[8], mk1[8];
        {
            const float* mr0 = Mg + (size_t)(wm + rq) * Ss + kt * 64 + 2 * cq;
            const float* mr1 = mr0 + 8 * Ss;
#pragma unroll
            for (int nt = 0; nt < 8; nt++) {
                mk0[nt] = *(const float2*)(mr0 + nt * 8);
                mk1[nt] = *(const float2*)(mr1 + nt * 8);
            }
        }

        // ---- S = Q K^T (split tf32) ----
        float S[8][4];
#pragma unroll
        for (int nt = 0; nt < 8; nt++)
#pragma unroll
            for (int c = 0; c < 4; c++) S[nt][c] = 0.f;

        const uint32_t kb = sK + (uint32_t)((kt & 1) * KV_TILE * 4)
                          + (uint32_t)((row_add * FSTR + koff) * 4);
#pragma unroll
        for (int ks = 0; ks < 8; ks++) {
#pragma unroll
            for (int p = 0; p < 4; p++) {   // ntile pair
                uint32_t r0, r1, r2, r3;
                ldsm_x4(r0, r1, r2, r3, kb + (uint32_t)((p * 16 * FSTR) * 4 + ks * 32));
                uint32_t b0h = f2tf32(r0), b0l = tf32_lo(r0, b0h);
                uint32_t b1h = f2tf32(r1), b1l = tf32_lo(r1, b1h);
                uint32_t b2h = f2tf32(r2), b2l = tf32_lo(r2, b2h);
                uint32_t b3h = f2tf32(r3), b3l = tf32_lo(r3, b3h);
                const int n0 = 2 * p, n1 = 2 * p + 1;
                mma_tf32(S[n0][0], S[n0][1], S[n0][2], S[n0][3],
                         Qh[ks][0], Qh[ks][1], Qh[ks][2], Qh[ks][3], b0h, b1h);
                mma_tf32(S[n0][0], S[n0][1], S[n0][2], S[n0][3],
                         Qh[ks][0], Qh[ks][1], Qh[ks][2], Qh[ks][3], b0l, b1l);
                mma_tf32(S[n0][0], S[n0][1], S[n0][2], S[n0][3],
                         Ql[ks][0], Ql[ks][1], Ql[ks][2], Ql[ks][3], b0h, b1h);
                mma_tf32(S[n1][0], S[n1][1], S[n1][2], S[n1][3],
                         Qh[ks][0], Qh[ks][1], Qh[ks][2], Qh[ks][3], b2h, b3h);
                mma_tf32(S[n1][0], S[n1][1], S[n1][2], S[n1][3],
                         Qh[ks][0], Qh[ks][1], Qh[ks][2], Qh[ks][3], b2l, b3l);
                mma_tf32(S[n1][0], S[n1][1], S[n1][2], S[n1][3],
                         Ql[ks][0], Ql[ks][1], Ql[ks][2], Ql[ks][3], b2h, b3h);
            }
        }

        // ---- scale + mask + online softmax ----
        float rm0 = NEG_INF, rm1 = NEG_INF;
#pragma unroll
        for (int nt = 0; nt < 8; nt++) {
            S[nt][0] = S[nt][0] * 0.125f + mk0[nt].x * (-1e9f);
            S[nt][1] = S[nt][1] * 0.125f + mk0[nt].y * (-1e9f);
            S[nt][2] = S[nt][2] * 0.125f + mk1[nt].x * (-1e9f);
            S[nt][3] = S[nt][3] * 0.125f + mk1[nt].y * (-1e9f);
            rm0 = fmaxf(rm0, fmaxf(S[nt][0], S[nt][1]));
            rm1 = fmaxf(rm1, fmaxf(S[nt][2], S[nt][3]));
        }
        rm0 = fmaxf(rm0, __shfl_xor_sync(0xffffffffu, rm0, 1));
        rm0 = fmaxf(rm0, __shfl_xor_sync(0xffffffffu, rm0, 2));
        rm1 = fmaxf(rm1, __shfl_xor_sync(0xffffffffu, rm1, 1));
        rm1 = fmaxf(rm1, __shfl_xor_sync(0xffffffffu, rm1, 2));

        const float nm0 = fmaxf(m0r, rm0);
        const float nm1 = fmaxf(m1r, rm1);
        const float sc0 = __expf(m0r - nm0);
        const float sc1 = __expf(m1r - nm1);
        m0r = nm0; m1r = nm1;

        float rs0 = 0.f, rs1 = 0.f;
#pragma unroll
        for (int nt = 0; nt < 8; nt++) {
            S[nt][0] = __expf(S[nt][0] - nm0);
            S[nt][1] = __expf(S[nt][1] - nm0);
            S[nt][2] = __expf(S[nt][2] - nm1);
            S[nt][3] = __expf(S[nt][3] - nm1);
            rs0 += S[nt][0] + S[nt][1];
            rs1 += S[nt][2] + S[nt][3];
        }
        rs0 += __shfl_xor_sync(0xffffffffu, rs0, 1);
        rs0 += __shfl_xor_sync(0xffffffffu, rs0, 2);
        rs1 += __shfl_xor_sync(0xffffffffu, rs1, 1);
        rs1 += __shfl_xor_sync(0xffffffffu, rs1, 2);
        l0r = l0r * sc0 + rs0;
        l1r = l1r * sc1 + rs1;

#pragma unroll
        for (int nt = 0; nt < 8; nt++) {
            O[nt][0] *= sc0; O[nt][1] *= sc0;
            O[nt][2] *= sc1; O[nt][3] *= sc1;
        }

        // ---- store P to smem ----
        {
            float* p0 = Pbuf + (wm + rq) * FSTR + 2 * cq;
            float* p1 = p0 + 8 * FSTR;
#pragma unroll
            for (int nt = 0; nt < 8; nt++) {
                *(float2*)(p0 + nt * 8) = make_float2(S[nt][0], S[nt][1]);
                *(float2*)(p1 + nt * 8) = make_float2(S[nt][2], S[nt][3]);
            }
        }

        // ---- transpose V tile: Vraw[kt&1] -> Vt ----
        {
            const float* vr = Vraw + (kt & 1) * KV_TILE;
#pragma unroll
            for (int i = 0; i < 4; i++) {
                int id = tid + 256 * i;          // 0..1023
                int krow = id & 63;              // key row
                int dch  = id >> 6;              // d chunk 0..15
                float4 v = *(const float4*)(vr + krow * FSTR + dch * 4);
                Vt[(dch * 4 + 0) * FSTR + krow] = v.x;
                Vt[(dch * 4 + 1) * FSTR + krow] = v.y;
                Vt[(dch * 4 + 2) * FSTR + krow] = v.z;
                Vt[(dch * 4 + 3) * FSTR + krow] = v.w;
            }
        }
        __syncthreads();   // P + Vt visible

        // ---- O += P V  (plain tf32) ----
        const uint32_t pb = sP + (uint32_t)(((wm + row_add) * FSTR + koff) * 4);
        const uint32_t vb = sVt + (uint32_t)((row_add * FSTR + koff) * 4);
#pragma unroll
        for (int ks = 0; ks < 8; ks++) {
            uint32_t pr0, pr1, pr2, pr3;
            ldsm_x4(pr0, pr1, pr2, pr3, pb + (uint32_t)(ks * 32));
            uint32_t a0 = f2tf32(pr0), a1 = f2tf32(pr2), a2 = f2tf32(pr1), a3 = f2tf32(pr3);
#pragma unroll
            for (int p = 0; p < 4; p++) {
                uint32_t r0, r1, r2, r3;
                ldsm_x4(r0, r1, r2, r3, vb + (uint32_t)((p * 16 * FSTR) * 4 + ks * 32));
                uint32_t b0 = f2tf32(r0), b1 = f2tf32(r1), b2 = f2tf32(r2), b3 = f2tf32(r3);
                const int n0 = 2 * p, n1 = 2 * p + 1;
                mma_tf32(O[n0][0], O[n0][1], O[n0][2], O[n0][3], a0, a1, a2, a3, b0, b1);
                mma_tf32(O[n1][0], O[n1][1], O[n1][2], O[n1][3], a0, a1, a2, a3, b2, b3);
            }
        }
        __syncthreads();   // PV reads done before next iter overwrites Pbuf/Vt
    }

    // ---- epilogue: attn_products[b, q, h, d] = O / l ----
    const float inv0 = 1.f / l0r;
    const float inv1 = 1.f / l1r;
    float* o0 = Out + ((size_t)b * Ss + q0 + wm + rq) * Dd + h * DP + 2 * cq;
    float* o1 = o0 + (size_t)8 * Dd;
#pragma unroll
    for (int nt = 0; nt < 8; nt++) {
        *(float2*)(o0 + nt * 8) = make_float2(O[nt][0] * inv0, O[nt][1] * inv0);
        *(float2*)(o1 + nt * 8) = make_float2(O[nt][2] * inv1, O[nt][3] * inv1);
    }
}

// ---------------------------------------------------------------------------
extern "C" void kernel_launch(void* const* d_in, const int* in_sizes, int n_in,
                              void* d_out, int out_size)
{
    const float* q    = (const float*)d_in[0];
    const float* k    = (const float*)d_in[1];
    const float* v    = (const float*)d_in[2];
    const float* mask = (const float*)d_in[3];
    const float* wq_w = (const float*)d_in[4];
    const float* wq_b = (const float*)d_in[5];
    const float* wk_w = (const float*)d_in[6];
    const float* wk_b = (const float*)d_in[7];
    const float* wv_w = (const float*)d_in[8];
    const float* wv_b = (const float*)d_in[9];
    const float* fc_w = (const float*)d_in[10];
    const float* fc_b = (const float*)d_in[11];

    float *pQ, *pK, *pV, *pScr;
    cudaGetSymbolAddress((void**)&pQ, g_Qp);
    cudaGetSymbolAddress((void**)&pK, g_Kp);
    cudaGetSymbolAddress((void**)&pV, g_Vp);
    cudaGetSymbolAddress((void**)&pScr, g_attn_scratch);

    float* out_main = (float*)d_out;
    const size_t OUT1 = (size_t)MM * Dd;
    float* attn_out = ((size_t)out_size >= 2 * OUT1) ? (out_main + OUT1) : pScr;

    static bool attr_set = false;
    if (!attr_set) {
        cudaFuncSetAttribute(flash_attn_tc, cudaFuncAttributeMaxDynamicSharedMemorySize,
                             FLASH_SMEM_BYTES);
        attr_set = true;
    }

    dim3 gemm_grid(Dd / GBN, MM / GBM);  // (8, 32)

    gemm_tf32<<<gemm_grid, 256>>>(q, wq_w, wq_b, pQ, MM, Dd, Dd);
    gemm_tf32<<<gemm_grid, 256>>>(k, wk_w, wk_b, pK, MM, Dd, Dd);
    gemm_tf32<<<gemm_grid, 256>>>(v, wv_w, wv_b, pV, MM, Dd, Dd);

    flash_attn_tc<<<dim3(Ss / 128, Hh, Bb), 256, FLASH_SMEM_BYTES>>>(pQ, pK, pV, mask, attn_out);

    gemm_tf32<<<gemm_grid, 256>>>(attn_out, fc_w, fc_b, out_main, MM, Dd, Dd);
}

// round 4
// speedup vs baseline: 2.6207x; 1.0782x over previous
#include <cuda_runtime.h>
#include <cstdint>

// ---------------------------------------------------------------------------
// MultiHeadAttn: B=2, S=2048, D=1024, H=16, depth=64
// Stage 1: projections (gemm_tf32). K stored pre-split (Kh,Kl); V pre-rounded.
// Stage 2: flash attention, tensor-core tf32, cvt-free inner loop.
// Stage 3: fc output projection.
// ---------------------------------------------------------------------------

#define NEG_INF (-3.402823466e38f)

static constexpr int Bb = 2;
static constexpr int Ss = 2048;
static constexpr int Dd = 1024;
static constexpr int Hh = 16;
static constexpr int DP = 64;
static constexpr int MM = Bb * Ss;  // 4096

__device__ float g_Qp[(size_t)MM * Dd];
__device__ float g_Kh[(size_t)MM * Dd];
__device__ float g_Kl[(size_t)MM * Dd];
__device__ float g_Vp[(size_t)MM * Dd];
__device__ float g_attn_scratch[(size_t)MM * Dd];

// ---------------------------------------------------------------------------
// PTX helpers
// ---------------------------------------------------------------------------
__device__ __forceinline__ uint32_t cvta_smem(const void* p) {
    return (uint32_t)__cvta_generic_to_shared(p);
}
__device__ __forceinline__ void cp_async16(uint32_t dst, const void* src) {
    asm volatile("cp.async.cg.shared.global [%0], [%1], 16;\n" :: "r"(dst), "l"(src));
}
__device__ __forceinline__ void cp_commit() {
    asm volatile("cp.async.commit_group;\n");
}
__device__ __forceinline__ void cp_wait0() {
    asm volatile("cp.async.wait_group 0;\n");
}
__device__ __forceinline__ void cp_wait1() {
    asm volatile("cp.async.wait_group 1;\n");
}
__device__ __forceinline__ void ldsm_x4(uint32_t& r0, uint32_t& r1, uint32_t& r2, uint32_t& r3,
                                        uint32_t addr) {
    asm volatile("ldmatrix.sync.aligned.m8n8.x4.shared.b16 {%0,%1,%2,%3}, [%4];\n"
                 : "=r"(r0), "=r"(r1), "=r"(r2), "=r"(r3) : "r"(addr));
}
__device__ __forceinline__ uint32_t f2tf32(uint32_t bits) {
    float f = __uint_as_float(bits);
    uint32_t r;
    asm volatile("cvt.rna.tf32.f32 %0, %1;\n" : "=r"(r) : "f"(f));
    return r;
}
__device__ __forceinline__ float tf32_round(float x) {
    uint32_t r;
    asm volatile("cvt.rna.tf32.f32 %0, %1;\n" : "=r"(r) : "f"(x));
    return __uint_as_float(r);
}
__device__ __forceinline__ uint32_t tf32_lo(uint32_t bits, uint32_t hi) {
    float d = __uint_as_float(bits) - __uint_as_float(hi);
    uint32_t r;
    asm volatile("cvt.rna.tf32.f32 %0, %1;\n" : "=r"(r) : "f"(d));
    return r;
}
__device__ __forceinline__ void mma_tf32(float& d0, float& d1, float& d2, float& d3,
                                         uint32_t a0, uint32_t a1, uint32_t a2, uint32_t a3,
                                         uint32_t b0, uint32_t b1) {
    asm volatile(
        "mma.sync.aligned.m16n8k8.row.col.f32.tf32.tf32.f32 "
        "{%0,%1,%2,%3}, {%4,%5,%6,%7}, {%8,%9}, {%0,%1,%2,%3};\n"
        : "+f"(d0), "+f"(d1), "+f"(d2), "+f"(d3)
        : "r"(a0), "r"(a1), "r"(a2), "r"(a3), "r"(b0), "r"(b1));
}

// ---------------------------------------------------------------------------
// tf32 tensor-core GEMM. MODE 0: C=acc+bias. MODE 1: C=rna(v), C2=rna(v-C).
// MODE 2: C=rna(v).
// ---------------------------------------------------------------------------
#define GBM 128
#define GBN 128
#define GBK 16
#define GSTR 20
#define GTILE_BYTES (GBM * GSTR * 4)

template <int MODE>
__global__ __launch_bounds__(256)
void gemm_tf32(const float* __restrict__ A, const float* __restrict__ W,
               const float* __restrict__ bias, float* __restrict__ C,
               float* __restrict__ C2, int M, int N, int K)
{
    __shared__ __align__(16) float As[2][GBM * GSTR];
    __shared__ __align__(16) float Bs[2][GBN * GSTR];

    const int tid  = threadIdx.x;
    const int lane = tid & 31;
    const int wid  = tid >> 5;
    const int wm   = (wid & 1) * 64;
    const int wn   = (wid >> 1) * 32;
    const int m0   = blockIdx.y * GBM;
    const int n0   = blockIdx.x * GBN;

    const uint32_t sA = cvta_smem(As);
    const uint32_t sB = cvta_smem(Bs);

    const int lr0 = tid >> 2;
    const int lg  = (tid & 3) * 4;
    const float* Ap0 = A + (size_t)(m0 + lr0) * K + lg;
    const float* Ap1 = A + (size_t)(m0 + lr0 + 64) * K + lg;
    const float* Wp0 = W + (size_t)(n0 + lr0) * K + lg;
    const float* Wp1 = W + (size_t)(n0 + lr0 + 64) * K + lg;
    const uint32_t dA0 = sA + (uint32_t)((lr0 * GSTR + lg) * 4);
    const uint32_t dA1 = sA + (uint32_t)(((lr0 + 64) * GSTR + lg) * 4);
    const uint32_t dB0 = sB + (uint32_t)((lr0 * GSTR + lg) * 4);
    const uint32_t dB1 = sB + (uint32_t)(((lr0 + 64) * GSTR + lg) * 4);

    const int g       = lane >> 3;
    const int glr     = lane & 7;
    const int row_add = ((g >> 1) << 3) + glr;
    const int koff    = (g & 1) << 2;
    const uint32_t aBase = sA + (uint32_t)(((wm + row_add) * GSTR + koff) * 4);
    const uint32_t bBase = sB + (uint32_t)(((wn + row_add) * GSTR + koff) * 4);

    float acc[4][4][4];
#pragma unroll
    for (int i = 0; i < 4; i++)
#pragma unroll
        for (int j = 0; j < 4; j++)
#pragma unroll
            for (int c = 0; c < 4; c++) acc[i][j][c] = 0.f;

    const int NSTAGE = K / GBK;

    cp_async16(dA0, Ap0); cp_async16(dA1, Ap1);
    cp_async16(dB0, Wp0); cp_async16(dB1, Wp1);
    cp_commit();

    for (int kt = 0; kt < NSTAGE; kt++) {
        cp_wait0();
        __syncthreads();

        if (kt + 1 < NSTAGE) {
            const int k0 = (kt + 1) * GBK;
            const uint32_t bo = (uint32_t)(((kt + 1) & 1) * GTILE_BYTES);
            cp_async16(dA0 + bo, Ap0 + k0);
            cp_async16(dA1 + bo, Ap1 + k0);
            cp_async16(dB0 + bo, Wp0 + k0);
            cp_async16(dB1 + bo, Wp1 + k0);
            cp_commit();
        }

        const uint32_t bo = (uint32_t)((kt & 1) * GTILE_BYTES);
#pragma unroll
        for (int ks = 0; ks < 2; ks++) {
            const uint32_t ao = aBase + bo + (uint32_t)(ks * 32);
            const uint32_t bb = bBase + bo + (uint32_t)(ks * 32);

            uint32_t af[4][4], bf[4][2];
#pragma unroll
            for (int mt = 0; mt < 4; mt++) {
                uint32_t r0, r1, r2, r3;
                ldsm_x4(r0, r1, r2, r3, ao + (uint32_t)(mt * 16 * GSTR * 4));
                af[mt][0] = f2tf32(r0);
                af[mt][1] = f2tf32(r2);
                af[mt][2] = f2tf32(r1);
                af[mt][3] = f2tf32(r3);
            }
#pragma unroll
            for (int p = 0; p < 2; p++) {
                uint32_t r0, r1, r2, r3;
                ldsm_x4(r0, r1, r2, r3, bb + (uint32_t)(p * 16 * GSTR * 4));
                bf[2 * p][0]     = f2tf32(r0);
                bf[2 * p][1]     = f2tf32(r1);
                bf[2 * p + 1][0] = f2tf32(r2);
                bf[2 * p + 1][1] = f2tf32(r3);
            }
#pragma unroll
            for (int mt = 0; mt < 4; mt++)
#pragma unroll
                for (int nt = 0; nt < 4; nt++)
                    mma_tf32(acc[mt][nt][0], acc[mt][nt][1], acc[mt][nt][2], acc[mt][nt][3],
                             af[mt][0], af[mt][1], af[mt][2], af[mt][3],
                             bf[nt][0], bf[nt][1]);
        }
        __syncthreads();
    }

#pragma unroll
    for (int mt = 0; mt < 4; mt++) {
        const int row = m0 + wm + mt * 16 + (lane >> 2);
#pragma unroll
        for (int nt = 0; nt < 4; nt++) {
            const int col = n0 + wn + nt * 8 + (lane & 3) * 2;
            const float b0 = bias[col], b1 = bias[col + 1];
            float v00 = acc[mt][nt][0] + b0, v01 = acc[mt][nt][1] + b1;
            float v10 = acc[mt][nt][2] + b0, v11 = acc[mt][nt][3] + b1;
            const size_t o0 = (size_t)row * N + col;
            const size_t o1 = (size_t)(row + 8) * N + col;
            if (MODE == 0) {
                *(float2*)&C[o0] = make_float2(v00, v01);
                *(float2*)&C[o1] = make_float2(v10, v11);
            } else if (MODE == 2) {
                *(float2*)&C[o0] = make_float2(tf32_round(v00), tf32_round(v01));
                *(float2*)&C[o1] = make_float2(tf32_round(v10), tf32_round(v11));
            } else {
                float h00 = tf32_round(v00), h01 = tf32_round(v01);
                float h10 = tf32_round(v10), h11 = tf32_round(v11);
                *(float2*)&C[o0]  = make_float2(h00, h01);
                *(float2*)&C[o1]  = make_float2(h10, h11);
                *(float2*)&C2[o0] = make_float2(tf32_round(v00 - h00), tf32_round(v01 - h01));
                *(float2*)&C2[o1] = make_float2(tf32_round(v10 - h10), tf32_round(v11 - h11));
            }
        }
    }
}

// ---------------------------------------------------------------------------
// Tensor-core flash attention, cvt-free inner loop.
// CTA: 128 queries x one (b,h). 8 warps x 16 rows. Key tiles of 64.
// K arrives pre-split (Kh, Kl); V arrives pre-rounded to tf32.
// smem: Kh dbuf | Kl dbuf | Vraw dbuf | Vt | P(=Q stage). Stride 68.
// ---------------------------------------------------------------------------
#define FSTR 68
#define KV_TILE (64 * FSTR)
#define FLASH_SMEM_FLOATS (6 * KV_TILE + KV_TILE + 128 * FSTR)
#define FLASH_SMEM_BYTES (FLASH_SMEM_FLOATS * 4)

__global__ __launch_bounds__(256, 1)
void flash_attn_tc(const float* __restrict__ Qp, const float* __restrict__ Kh_g,
                   const float* __restrict__ Kl_g, const float* __restrict__ Vp,
                   const float* __restrict__ mask, float* __restrict__ Out)
{
    extern __shared__ float fsm[];
    float* Khb  = fsm;                       // 2 * KV_TILE
    float* Klb  = Khb + 2 * KV_TILE;         // 2 * KV_TILE
    float* Vraw = Klb + 2 * KV_TILE;         // 2 * KV_TILE
    float* Vt   = Vraw + 2 * KV_TILE;        // KV_TILE
    float* Pbuf = Vt + KV_TILE;              // 128 * FSTR

    const uint32_t sKh = cvta_smem(Khb);
    const uint32_t sKl = cvta_smem(Klb);
    const uint32_t sV  = cvta_smem(Vraw);
    const uint32_t sVt = cvta_smem(Vt);
    const uint32_t sP  = cvta_smem(Pbuf);

    const int tid  = threadIdx.x;
    const int lane = tid & 31;
    const int wid  = tid >> 5;
    const int wm   = wid * 16;
    const int q0   = blockIdx.x * 128;
    const int h    = blockIdx.y;
    const int b    = blockIdx.z;

    const float* Qg  = Qp   + ((size_t)b * Ss + q0) * Dd + h * DP;
    const float* Khg = Kh_g + ((size_t)b * Ss) * Dd + h * DP;
    const float* Klg = Kl_g + ((size_t)b * Ss) * Dd + h * DP;
    const float* Vg  = Vp   + ((size_t)b * Ss) * Dd + h * DP;
    const float* Mg  = mask + (((size_t)b * Hh + h) * Ss + q0) * Ss;

    const int g       = lane >> 3;
    const int glr     = lane & 7;
    const int row_add = ((g >> 1) << 3) + glr;
    const int koff    = (g & 1) << 2;

    const int rq = lane >> 2;
    const int cq = lane & 3;

    // ---- prefetch tile 0 (Kh, Kl, V) ----
    {
#pragma unroll
        for (int i = 0; i < 4; i++) {
            int id = tid + 256 * i;
            int row = id >> 4, col = id & 15;
            uint32_t so = (uint32_t)((row * FSTR + col * 4) * 4);
            size_t go = (size_t)row * Dd + col * 4;
            cp_async16(sKh + so, Khg + go);
            cp_async16(sKl + so, Klg + go);
            cp_async16(sV + so, Vg + go);
        }
        cp_commit();
    }

    // ---- stage Q into Pbuf, extract hi/lo fragments ----
#pragma unroll
    for (int i = 0; i < 8; i++) {
        int id = tid + 256 * i;
        int row = id >> 4, col = id & 15;
        float4 v = *(const float4*)(Qg + (size_t)row * Dd + col * 4);
        *(float4*)&Pbuf[row * FSTR + col * 4] = v;
    }
    __syncthreads();

    uint32_t Qh[8][4], Ql[8][4];
    {
        const uint32_t base = sP + (uint32_t)(((wm + row_add) * FSTR + koff) * 4);
#pragma unroll
        for (int ks = 0; ks < 8; ks++) {
            uint32_t r0, r1, r2, r3;
            ldsm_x4(r0, r1, r2, r3, base + (uint32_t)(ks * 32));
            Qh[ks][0] = f2tf32(r0); Ql[ks][0] = tf32_lo(r0, Qh[ks][0]);
            Qh[ks][1] = f2tf32(r2); Ql[ks][1] = tf32_lo(r2, Qh[ks][1]);
            Qh[ks][2] = f2tf32(r1); Ql[ks][2] = tf32_lo(r1, Qh[ks][2]);
            Qh[ks][3] = f2tf32(r3); Ql[ks][3] = tf32_lo(r3, Qh[ks][3]);
        }
    }

    float O[8][4];
#pragma unroll
    for (int nt = 0; nt < 8; nt++)
#pragma unroll
        for (int c = 0; c < 4; c++) O[nt][c] = 0.f;
    float m0r = NEG_INF, m1r = NEG_INF, l0r = 0.f, l1r = 0.f;

    for (int kt = 0; kt < 32; kt++) {
        // prefetch next tile
        if (kt + 1 < 32) {
            const uint32_t bo = (uint32_t)(((kt + 1) & 1) * KV_TILE * 4);
            const float* khg = Khg + (size_t)(kt + 1) * 64 * Dd;
            const float* klg = Klg + (size_t)(kt + 1) * 64 * Dd;
            const float* vg  = Vg  + (size_t)(kt + 1) * 64 * Dd;
#pragma unroll
            for (int i = 0; i < 4; i++) {
                int id = tid + 256 * i;
                int row = id >> 4, col = id & 15;
                uint32_t so = (uint32_t)((row * FSTR + col * 4) * 4);
                size_t go = (size_t)row * Dd + col * 4;
                cp_async16(sKh + bo + so, khg + go);
                cp_async16(sKl + bo + so, klg + go);
                cp_async16(sV + bo + so, vg + go);
            }
            cp_commit();
            cp_wait1();
        } else {
            cp_wait0();
        }
        __syncthreads();   // tile kt visible; Pbuf/Vt free (prev PV done)

        // ---- transpose V tile early (hide under QK mma) ----
        {
            const float* vr = Vraw + (kt & 1) * KV_TILE;
#pragma unroll
            for (int i = 0; i < 4; i++) {
                int id = tid + 256 * i;
                int krow = id & 63;
                int dch  = id >> 6;
                float4 v = *(const float4*)(vr + krow * FSTR + dch * 4);
                Vt[(dch * 4 + 0) * FSTR + krow] = v.x;
                Vt[(dch * 4 + 1) * FSTR + krow] = v.y;
                Vt[(dch * 4 + 2) * FSTR + krow] = v.z;
                Vt[(dch * 4 + 3) * FSTR + krow] = v.w;
            }
        }

        // mask fragments (overlap DRAM with QK mma)
        float2 mk0[8], mk1[8];
        {
            const float* mr0 = Mg + (size_t)(wm + rq) * Ss + kt * 64 + 2 * cq;
            const float* mr1 = mr0 + 8 * Ss;
#pragma unroll
            for (int nt = 0; nt < 8; nt++) {
                mk0[nt] = *(const float2*)(mr0 + nt * 8);
                mk1[nt] = *(const float2*)(mr1 + nt * 8);
            }
        }

        // ---- S = Q K^T (split tf32, zero cvt) ----
        float S[8][4];
#pragma unroll
        for (int nt = 0; nt < 8; nt++)
#pragma unroll
            for (int c = 0; c < 4; c++) S[nt][c] = 0.f;

        const uint32_t khb = sKh + (uint32_t)((kt & 1) * KV_TILE * 4)
                           + (uint32_t)((row_add * FSTR + koff) * 4);
        const uint32_t klb = sKl + (uint32_t)((kt & 1) * KV_TILE * 4)
                           + (uint32_t)((row_add * FSTR + koff) * 4);
#pragma unroll
        for (int ks = 0; ks < 8; ks++) {
#pragma unroll
            for (int p = 0; p < 4; p++) {
                const uint32_t off = (uint32_t)((p * 16 * FSTR) * 4 + ks * 32);
                uint32_t h0, h1, h2, h3, l0, l1, l2, l3;
                ldsm_x4(h0, h1, h2, h3, khb + off);
                ldsm_x4(l0, l1, l2, l3, klb + off);
                const int n0 = 2 * p, n1 = 2 * p + 1;
                mma_tf32(S[n0][0], S[n0][1], S[n0][2], S[n0][3],
                         Qh[ks][0], Qh[ks][1], Qh[ks][2], Qh[ks][3], h0, h1);
                mma_tf32(S[n0][0], S[n0][1], S[n0][2], S[n0][3],
                         Qh[ks][0], Qh[ks][1], Qh[ks][2], Qh[ks][3], l0, l1);
                mma_tf32(S[n0][0], S[n0][1], S[n0][2], S[n0][3],
                         Ql[ks][0], Ql[ks][1], Ql[ks][2], Ql[ks][3], h0, h1);
                mma_tf32(S[n1][0], S[n1][1], S[n1][2], S[n1][3],
                         Qh[ks][0], Qh[ks][1], Qh[ks][2], Qh[ks][3], h2, h3);
                mma_tf32(S[n1][0], S[n1][1], S[n1][2], S[n1][3],
                         Qh[ks][0], Qh[ks][1], Qh[ks][2], Qh[ks][3], l2, l3);
                mma_tf32(S[n1][0], S[n1][1], S[n1][2], S[n1][3],
                         Ql[ks][0], Ql[ks][1], Ql[ks][2], Ql[ks][3], h2, h3);
            }
        }

        // ---- scale + mask + online softmax ----
        float rm0 = NEG_INF, rm1 = NEG_INF;
#pragma unroll
        for (int nt = 0; nt < 8; nt++) {
            S[nt][0] = S[nt][0] * 0.125f + mk0[nt].x * (-1e9f);
            S[nt][1] = S[nt][1] * 0.125f + mk0[nt].y * (-1e9f);
            S[nt][2] = S[nt][2] * 0.125f + mk1[nt].x * (-1e9f);
            S[nt][3] = S[nt][3] * 0.125f + mk1[nt].y * (-1e9f);
            rm0 = fmaxf(rm0, fmaxf(S[nt][0], S[nt][1]));
            rm1 = fmaxf(rm1, fmaxf(S[nt][2], S[nt][3]));
        }
        rm0 = fmaxf(rm0, __shfl_xor_sync(0xffffffffu, rm0, 1));
        rm0 = fmaxf(rm0, __shfl_xor_sync(0xffffffffu, rm0, 2));
        rm1 = fmaxf(rm1, __shfl_xor_sync(0xffffffffu, rm1, 1));
        rm1 = fmaxf(rm1, __shfl_xor_sync(0xffffffffu, rm1, 2));

        const float nm0 = fmaxf(m0r, rm0);
        const float nm1 = fmaxf(m1r, rm1);
        const float sc0 = __expf(m0r - nm0);
        const float sc1 = __expf(m1r - nm1);
        m0r = nm0; m1r = nm1;

        float rs0 = 0.f, rs1 = 0.f;
#pragma unroll
        for (int nt = 0; nt < 8; nt++) {
            S[nt][0] = __expf(S[nt][0] - nm0);
            S[nt][1] = __expf(S[nt][1] - nm0);
            S[nt][2] = __expf(S[nt][2] - nm1);
            S[nt][3] = __expf(S[nt][3] - nm1);
            rs0 += S[nt][0] + S[nt][1];
            rs1 += S[nt][2] + S[nt][3];
        }
        rs0 += __shfl_xor_sync(0xffffffffu, rs0, 1);
        rs0 += __shfl_xor_sync(0xffffffffu, rs0, 2);
        rs1 += __shfl_xor_sync(0xffffffffu, rs1, 1);
        rs1 += __shfl_xor_sync(0xffffffffu, rs1, 2);
        l0r = l0r * sc0 + rs0;
        l1r = l1r * sc1 + rs1;

#pragma unroll
        for (int nt = 0; nt < 8; nt++) {
            O[nt][0] *= sc0; O[nt][1] *= sc0;
            O[nt][2] *= sc1; O[nt][3] *= sc1;
        }

        // ---- store P ----
        {
            float* p0 = Pbuf + (wm + rq) * FSTR + 2 * cq;
            float* p1 = p0 + 8 * FSTR;
#pragma unroll
            for (int nt = 0; nt < 8; nt++) {
                *(float2*)(p0 + nt * 8) = make_float2(S[nt][0], S[nt][1]);
                *(float2*)(p1 + nt * 8) = make_float2(S[nt][2], S[nt][3]);
            }
        }
        __syncthreads();   // P + Vt visible

        // ---- O += P V  (V fragments raw — pre-rounded) ----
        const uint32_t pb = sP + (uint32_t)(((wm + row_add) * FSTR + koff) * 4);
        const uint32_t vb = sVt + (uint32_t)((row_add * FSTR + koff) * 4);
#pragma unroll
        for (int ks = 0; ks < 8; ks++) {
            uint32_t pr0, pr1, pr2, pr3;
            ldsm_x4(pr0, pr1, pr2, pr3, pb + (uint32_t)(ks * 32));
            uint32_t a0 = f2tf32(pr0), a1 = f2tf32(pr2), a2 = f2tf32(pr1), a3 = f2tf32(pr3);
#pragma unroll
            for (int p = 0; p < 4; p++) {
                uint32_t v0, v1, v2, v3;
                ldsm_x4(v0, v1, v2, v3, vb + (uint32_t)((p * 16 * FSTR) * 4 + ks * 32));
                const int n0 = 2 * p, n1 = 2 * p + 1;
                mma_tf32(O[n0][0], O[n0][1], O[n0][2], O[n0][3], a0, a1, a2, a3, v0, v1);
                mma_tf32(O[n1][0], O[n1][1], O[n1][2], O[n1][3], a0, a1, a2, a3, v2, v3);
            }
        }
        __syncthreads();   // PV reads done before next iter overwrites Pbuf/Vt
    }

    // ---- epilogue ----
    const float inv0 = 1.f / l0r;
    const float inv1 = 1.f / l1r;
    float* o0 = Out + ((size_t)b * Ss + q0 + wm + rq) * Dd + h * DP + 2 * cq;
    float* o1 = o0 + (size_t)8 * Dd;
#pragma unroll
    for (int nt = 0; nt < 8; nt++) {
        *(float2*)(o0 + nt * 8) = make_float2(O[nt][0] * inv0, O[nt][1] * inv0);
        *(float2*)(o1 + nt * 8) = make_float2(O[nt][2] * inv1, O[nt][3] * inv1);
    }
}

// ---------------------------------------------------------------------------
extern "C" void kernel_launch(void* const* d_in, const int* in_sizes, int n_in,
                              void* d_out, int out_size)
{
    const float* q    = (const float*)d_in[0];
    const float* k    = (const float*)d_in[1];
    const float* v    = (const float*)d_in[2];
    const float* mask = (const float*)d_in[3];
    const float* wq_w = (const float*)d_in[4];
    const float* wq_b = (const float*)d_in[5];
    const float* wk_w = (const float*)d_in[6];
    const float* wk_b = (const float*)d_in[7];
    const float* wv_w = (const float*)d_in[8];
    const float* wv_b = (const float*)d_in[9];
    const float* fc_w = (const float*)d_in[10];
    const float* fc_b = (const float*)d_in[11];

    float *pQ, *pKh, *pKl, *pV, *pScr;
    cudaGetSymbolAddress((void**)&pQ, g_Qp);
    cudaGetSymbolAddress((void**)&pKh, g_Kh);
    cudaGetSymbolAddress((void**)&pKl, g_Kl);
    cudaGetSymbolAddress((void**)&pV, g_Vp);
    cudaGetSymbolAddress((void**)&pScr, g_attn_scratch);

    float* out_main = (float*)d_out;
    const size_t OUT1 = (size_t)MM * Dd;
    float* attn_out = ((size_t)out_size >= 2 * OUT1) ? (out_main + OUT1) : pScr;

    static bool attr_set = false;
    if (!attr_set) {
        cudaFuncSetAttribute(flash_attn_tc, cudaFuncAttributeMaxDynamicSharedMemorySize,
                             FLASH_SMEM_BYTES);
        attr_set = true;
    }

    dim3 gemm_grid(Dd / GBN, MM / GBM);  // (8, 32)

    gemm_tf32<0><<<gemm_grid, 256>>>(q, wq_w, wq_b, pQ, nullptr, MM, Dd, Dd);
    gemm_tf32<1><<<gemm_grid, 256>>>(k, wk_w, wk_b, pKh, pKl, MM, Dd, Dd);
    gemm_tf32<2><<<gemm_grid, 256>>>(v, wv_w, wv_b, pV, nullptr, MM, Dd, Dd);

    flash_attn_tc<<<dim3(Ss / 128, Hh, Bb), 256, FLASH_SMEM_BYTES>>>(
        pQ, pKh, pKl, pV, mask, attn_out);

    gemm_tf32<0><<<gemm_grid, 256>>>(attn_out, fc_w, fc_b, out_main, nullptr, MM, Dd, Dd);
}

// round 6
// speedup vs baseline: 2.7297x; 1.0416x over previous
#include <cuda_runtime.h>
#include <cstdint>

// ---------------------------------------------------------------------------
// MultiHeadAttn: B=2, S=2048, D=1024, H=16, depth=64
// Stage 1: merged QKV projections (one launch, grid.z selects):
//          z=0: Qp fp32     z=1: Kh/Kl split-tf32     z=2: V^T tf32-rounded
// Stage 2: flash attention, tensor-core tf32, 1 syncthreads/iter.
// Stage 3: fc output projection.
// ---------------------------------------------------------------------------

#define NEG_INF (-3.402823466e38f)

static constexpr int Bb = 2;
static constexpr int Ss = 2048;
static constexpr int Dd = 1024;
static constexpr int Hh = 16;
static constexpr int DP = 64;
static constexpr int MM = Bb * Ss;  // 4096

__device__ float g_Qp[(size_t)MM * Dd];
__device__ float g_Kh[(size_t)MM * Dd];
__device__ float g_Kl[(size_t)MM * Dd];
__device__ float g_VT[(size_t)MM * Dd];   // [B, H, DP, Ss]
__device__ float g_attn_scratch[(size_t)MM * Dd];

// ---------------------------------------------------------------------------
// PTX helpers
// ---------------------------------------------------------------------------
__device__ __forceinline__ uint32_t cvta_smem(const void* p) {
    return (uint32_t)__cvta_generic_to_shared(p);
}
__device__ __forceinline__ void cp_async16(uint32_t dst, const void* src) {
    asm volatile("cp.async.cg.shared.global [%0], [%1], 16;\n" :: "r"(dst), "l"(src));
}
__device__ __forceinline__ void cp_commit() {
    asm volatile("cp.async.commit_group;\n");
}
__device__ __forceinline__ void cp_wait0() {
    asm volatile("cp.async.wait_group 0;\n");
}
__device__ __forceinline__ void ldsm_x4(uint32_t& r0, uint32_t& r1, uint32_t& r2, uint32_t& r3,
                                        uint32_t addr) {
    asm volatile("ldmatrix.sync.aligned.m8n8.x4.shared.b16 {%0,%1,%2,%3}, [%4];\n"
                 : "=r"(r0), "=r"(r1), "=r"(r2), "=r"(r3) : "r"(addr));
}
__device__ __forceinline__ uint32_t f2tf32(uint32_t bits) {
    float f = __uint_as_float(bits);
    uint32_t r;
    asm volatile("cvt.rna.tf32.f32 %0, %1;\n" : "=r"(r) : "f"(f));
    return r;
}
__device__ __forceinline__ float tf32_round(float x) {
    uint32_t r;
    asm volatile("cvt.rna.tf32.f32 %0, %1;\n" : "=r"(r) : "f"(x));
    return __uint_as_float(r);
}
__device__ __forceinline__ uint32_t tf32_lo(uint32_t bits, uint32_t hi) {
    float d = __uint_as_float(bits) - __uint_as_float(hi);
    uint32_t r;
    asm volatile("cvt.rna.tf32.f32 %0, %1;\n" : "=r"(r) : "f"(d));
    return r;
}
__device__ __forceinline__ void mma_tf32(float& d0, float& d1, float& d2, float& d3,
                                         uint32_t a0, uint32_t a1, uint32_t a2, uint32_t a3,
                                         uint32_t b0, uint32_t b1) {
    asm volatile(
        "mma.sync.aligned.m16n8k8.row.col.f32.tf32.tf32.f32 "
        "{%0,%1,%2,%3}, {%4,%5,%6,%7}, {%8,%9}, {%0,%1,%2,%3};\n"
        : "+f"(d0), "+f"(d1), "+f"(d2), "+f"(d3)
        : "r"(a0), "r"(a1), "r"(a2), "r"(a3), "r"(b0), "r"(b1));
}

// ---------------------------------------------------------------------------
// GEMM mainloop core (device inline): acc = A @ W^T, 128x128x16 pipeline.
// ---------------------------------------------------------------------------
#define GBM 128
#define GBN 128
#define GBK 16
#define GSTR 20
#define GTILE_BYTES (GBM * GSTR * 4)

struct GemmCtx {
    float acc[4][4][4];
};

__device__ __forceinline__ void gemm_mainloop(
    const float* __restrict__ A, const float* __restrict__ W,
    int m0, int n0, int K, float (*As)[GBM * GSTR], float (*Bs)[GBN * GSTR],
    GemmCtx& ctx)
{
    const int tid  = threadIdx.x;
    const int lane = tid & 31;
    const int wid  = tid >> 5;
    const int wm   = (wid & 1) * 64;
    const int wn   = (wid >> 1) * 32;

    const uint32_t sA = cvta_smem(As);
    const uint32_t sB = cvta_smem(Bs);

    const int lr0 = tid >> 2;
    const int lg  = (tid & 3) * 4;
    const float* Ap0 = A + (size_t)(m0 + lr0) * K + lg;
    const float* Ap1 = A + (size_t)(m0 + lr0 + 64) * K + lg;
    const float* Wp0 = W + (size_t)(n0 + lr0) * K + lg;
    const float* Wp1 = W + (size_t)(n0 + lr0 + 64) * K + lg;
    const uint32_t dA0 = sA + (uint32_t)((lr0 * GSTR + lg) * 4);
    const uint32_t dA1 = sA + (uint32_t)(((lr0 + 64) * GSTR + lg) * 4);
    const uint32_t dB0 = sB + (uint32_t)((lr0 * GSTR + lg) * 4);
    const uint32_t dB1 = sB + (uint32_t)(((lr0 + 64) * GSTR + lg) * 4);

    const int g       = lane >> 3;
    const int glr     = lane & 7;
    const int row_add = ((g >> 1) << 3) + glr;
    const int koff    = (g & 1) << 2;
    const uint32_t aBase = sA + (uint32_t)(((wm + row_add) * GSTR + koff) * 4);
    const uint32_t bBase = sB + (uint32_t)(((wn + row_add) * GSTR + koff) * 4);

#pragma unroll
    for (int i = 0; i < 4; i++)
#pragma unroll
        for (int j = 0; j < 4; j++)
#pragma unroll
            for (int c = 0; c < 4; c++) ctx.acc[i][j][c] = 0.f;

    const int NSTAGE = K / GBK;

    cp_async16(dA0, Ap0); cp_async16(dA1, Ap1);
    cp_async16(dB0, Wp0); cp_async16(dB1, Wp1);
    cp_commit();

    for (int kt = 0; kt < NSTAGE; kt++) {
        cp_wait0();
        __syncthreads();

        if (kt + 1 < NSTAGE) {
            const int k0 = (kt + 1) * GBK;
            const uint32_t bo = (uint32_t)(((kt + 1) & 1) * GTILE_BYTES);
            cp_async16(dA0 + bo, Ap0 + k0);
            cp_async16(dA1 + bo, Ap1 + k0);
            cp_async16(dB0 + bo, Wp0 + k0);
            cp_async16(dB1 + bo, Wp1 + k0);
            cp_commit();
        }

        const uint32_t bo = (uint32_t)((kt & 1) * GTILE_BYTES);
#pragma unroll
        for (int ks = 0; ks < 2; ks++) {
            const uint32_t ao = aBase + bo + (uint32_t)(ks * 32);
            const uint32_t bb = bBase + bo + (uint32_t)(ks * 32);

            uint32_t af[4][4], bf[4][2];
#pragma unroll
            for (int mt = 0; mt < 4; mt++) {
                uint32_t r0, r1, r2, r3;
                ldsm_x4(r0, r1, r2, r3, ao + (uint32_t)(mt * 16 * GSTR * 4));
                af[mt][0] = f2tf32(r0);
                af[mt][1] = f2tf32(r2);
                af[mt][2] = f2tf32(r1);
                af[mt][3] = f2tf32(r3);
            }
#pragma unroll
            for (int p = 0; p < 2; p++) {
                uint32_t r0, r1, r2, r3;
                ldsm_x4(r0, r1, r2, r3, bb + (uint32_t)(p * 16 * GSTR * 4));
                bf[2 * p][0]     = f2tf32(r0);
                bf[2 * p][1]     = f2tf32(r1);
                bf[2 * p + 1][0] = f2tf32(r2);
                bf[2 * p + 1][1] = f2tf32(r3);
            }
#pragma unroll
            for (int mt = 0; mt < 4; mt++)
#pragma unroll
                for (int nt = 0; nt < 4; nt++)
                    mma_tf32(ctx.acc[mt][nt][0], ctx.acc[mt][nt][1],
                             ctx.acc[mt][nt][2], ctx.acc[mt][nt][3],
                             af[mt][0], af[mt][1], af[mt][2], af[mt][3],
                             bf[nt][0], bf[nt][1]);
        }
        __syncthreads();
    }
}

// ---------------------------------------------------------------------------
// Merged QKV projection kernel. grid.z: 0=Q (fp32), 1=K (hi/lo), 2=V (V^T).
// ---------------------------------------------------------------------------
__global__ __launch_bounds__(256, 2)
void qkv_gemm(const float* __restrict__ q, const float* __restrict__ k,
              const float* __restrict__ v,
              const float* __restrict__ wq, const float* __restrict__ wk,
              const float* __restrict__ wv,
              const float* __restrict__ bq, const float* __restrict__ bk,
              const float* __restrict__ bv,
              float* __restrict__ Qout, float* __restrict__ Kh,
              float* __restrict__ Kl, float* __restrict__ VT)
{
    __shared__ __align__(16) float As[2][GBM * GSTR];
    __shared__ __align__(16) float Bs[2][GBN * GSTR];

    const int z  = blockIdx.z;
    const int m0 = blockIdx.y * GBM;
    const int n0 = blockIdx.x * GBN;

    const float* A    = (z == 0) ? q  : (z == 1) ? k  : v;
    const float* W    = (z == 0) ? wq : (z == 1) ? wk : wv;
    const float* bias = (z == 0) ? bq : (z == 1) ? bk : bv;

    GemmCtx ctx;
    gemm_mainloop(A, W, m0, n0, Dd, As, Bs, ctx);

    const int lane = threadIdx.x & 31;
    const int wid  = threadIdx.x >> 5;
    const int wm   = (wid & 1) * 64;
    const int wn   = (wid >> 1) * 32;

#pragma unroll
    for (int mt = 0; mt < 4; mt++) {
        const int row = m0 + wm + mt * 16 + (lane >> 2);
#pragma unroll
        for (int nt = 0; nt < 4; nt++) {
            const int col = n0 + wn + nt * 8 + (lane & 3) * 2;
            const float b0 = bias[col], b1 = bias[col + 1];
            float v00 = ctx.acc[mt][nt][0] + b0, v01 = ctx.acc[mt][nt][1] + b1;
            float v10 = ctx.acc[mt][nt][2] + b0, v11 = ctx.acc[mt][nt][3] + b1;
            if (z == 0) {
                *(float2*)&Qout[(size_t)row * Dd + col]       = make_float2(v00, v01);
                *(float2*)&Qout[(size_t)(row + 8) * Dd + col] = make_float2(v10, v11);
            } else if (z == 1) {
                float h00 = tf32_round(v00), h01 = tf32_round(v01);
                float h10 = tf32_round(v10), h11 = tf32_round(v11);
                const size_t o0 = (size_t)row * Dd + col;
                const size_t o1 = (size_t)(row + 8) * Dd + col;
                *(float2*)&Kh[o0] = make_float2(h00, h01);
                *(float2*)&Kh[o1] = make_float2(h10, h11);
                *(float2*)&Kl[o0] = make_float2(tf32_round(v00 - h00), tf32_round(v01 - h01));
                *(float2*)&Kl[o1] = make_float2(tf32_round(v10 - h10), tf32_round(v11 - h11));
            } else {
                // V^T[b, h, d, s]
                const int b_  = row >> 11, s0 = row & 2047;
                const int h_  = col >> 6,  d0 = col & 63;
                float* base = VT + (((size_t)b_ * Hh + h_) * DP + d0) * Ss + s0;
                base[0]            = tf32_round(v00);
                base[Ss]           = tf32_round(v01);
                base[8]            = tf32_round(v10);
                base[Ss + 8]       = tf32_round(v11);
            }
        }
    }
}

// fc output projection (fp32 epilogue with bias)
__global__ __launch_bounds__(256, 2)
void fc_gemm(const float* __restrict__ A, const float* __restrict__ W,
             const float* __restrict__ bias, float* __restrict__ C)
{
    __shared__ __align__(16) float As[2][GBM * GSTR];
    __shared__ __align__(16) float Bs[2][GBN * GSTR];

    const int m0 = blockIdx.y * GBM;
    const int n0 = blockIdx.x * GBN;

    GemmCtx ctx;
    gemm_mainloop(A, W, m0, n0, Dd, As, Bs, ctx);

    const int lane = threadIdx.x & 31;
    const int wid  = threadIdx.x >> 5;
    const int wm   = (wid & 1) * 64;
    const int wn   = (wid >> 1) * 32;

#pragma unroll
    for (int mt = 0; mt < 4; mt++) {
        const int row = m0 + wm + mt * 16 + (lane >> 2);
#pragma unroll
        for (int nt = 0; nt < 4; nt++) {
            const int col = n0 + wn + nt * 8 + (lane & 3) * 2;
            const float b0 = bias[col], b1 = bias[col + 1];
            *(float2*)&C[(size_t)row * Dd + col] =
                make_float2(ctx.acc[mt][nt][0] + b0, ctx.acc[mt][nt][1] + b1);
            *(float2*)&C[(size_t)(row + 8) * Dd + col] =
                make_float2(ctx.acc[mt][nt][2] + b0, ctx.acc[mt][nt][3] + b1);
        }
    }
}

// ---------------------------------------------------------------------------
// Tensor-core flash attention. 1 syncthreads + 1 syncwarp per iteration.
// CTA: 128 queries x one (b,h). 8 warps x 16 rows. Key tiles of 64.
// K pre-split (Kh,Kl); V^T direct-loaded (no transpose). P is warp-private.
// ---------------------------------------------------------------------------
#define FSTR 68
#define KV_TILE (64 * FSTR)
#define FLASH_SMEM_FLOATS (6 * KV_TILE + 128 * FSTR)
#define FLASH_SMEM_BYTES (FLASH_SMEM_FLOATS * 4)

__global__ __launch_bounds__(256, 1)
void flash_attn_tc(const float* __restrict__ Qp, const float* __restrict__ Kh_g,
                   const float* __restrict__ Kl_g, const float* __restrict__ VT_g,
                   const float* __restrict__ mask, float* __restrict__ Out)
{
    extern __shared__ float fsm[];
    float* Khb = fsm;                        // 2 * KV_TILE
    float* Klb = Khb + 2 * KV_TILE;          // 2 * KV_TILE
    float* Vtb = Klb + 2 * KV_TILE;          // 2 * KV_TILE  (rows=d, cols=key)
    float* Pbuf = Vtb + 2 * KV_TILE;         // 128 * FSTR (Q stage, then P)

    const uint32_t sKh = cvta_smem(Khb);
    const uint32_t sKl = cvta_smem(Klb);
    const uint32_t sVt = cvta_smem(Vtb);
    const uint32_t sP  = cvta_smem(Pbuf);

    const int tid  = threadIdx.x;
    const int lane = tid & 31;
    const int wid  = tid >> 5;
    const int wm   = wid * 16;
    const int q0   = blockIdx.x * 128;
    const int h    = blockIdx.y;
    const int b    = blockIdx.z;

    const float* Qg  = Qp   + ((size_t)b * Ss + q0) * Dd + h * DP;
    const float* Khg = Kh_g + ((size_t)b * Ss) * Dd + h * DP;
    const float* Klg = Kl_g + ((size_t)b * Ss) * Dd + h * DP;
    const float* VTg = VT_g + ((size_t)b * Hh + h) * DP * Ss;  // [d][s]
    const float* Mg  = mask + (((size_t)b * Hh + h) * Ss + q0) * Ss;

    const int g       = lane >> 3;
    const int glr     = lane & 7;
    const int row_add = ((g >> 1) << 3) + glr;
    const int koff    = (g & 1) << 2;

    const int rq = lane >> 2;
    const int cq = lane & 3;

    // per-thread loader coords (64 rows x 16 chunks, 4 per thread)
    const int lrow = tid >> 4;        // 0..15 (+16*i)
    const int lcol = tid & 15;

    // ---- prefetch tile 0 ----
    {
#pragma unroll
        for (int i = 0; i < 4; i++) {
            int row = lrow + 16 * i;
            uint32_t so = (uint32_t)((row * FSTR + lcol * 4) * 4);
            cp_async16(sKh + so, Khg + (size_t)row * Dd + lcol * 4);
            cp_async16(sKl + so, Klg + (size_t)row * Dd + lcol * 4);
            cp_async16(sVt + so, VTg + (size_t)row * Ss + lcol * 4);
        }
        cp_commit();
    }

    // ---- stage Q into Pbuf, extract hi/lo fragments ----
#pragma unroll
    for (int i = 0; i < 8; i++) {
        int id = tid + 256 * i;
        int row = id >> 4, col = id & 15;
        float4 v = *(const float4*)(Qg + (size_t)row * Dd + col * 4);
        *(float4*)&Pbuf[row * FSTR + col * 4] = v;
    }
    __syncthreads();

    uint32_t Qh[8][4], Ql[8][4];
    {
        const uint32_t base = sP + (uint32_t)(((wm + row_add) * FSTR + koff) * 4);
#pragma unroll
        for (int ks = 0; ks < 8; ks++) {
            uint32_t r0, r1, r2, r3;
            ldsm_x4(r0, r1, r2, r3, base + (uint32_t)(ks * 32));
            Qh[ks][0] = f2tf32(r0); Ql[ks][0] = tf32_lo(r0, Qh[ks][0]);
            Qh[ks][1] = f2tf32(r2); Ql[ks][1] = tf32_lo(r2, Qh[ks][1]);
            Qh[ks][2] = f2tf32(r1); Ql[ks][2] = tf32_lo(r1, Qh[ks][2]);
            Qh[ks][3] = f2tf32(r3); Ql[ks][3] = tf32_lo(r3, Qh[ks][3]);
        }
    }
    // NOTE: no extra sync needed — first P store happens after each warp's own
    // extraction; P rows are warp-private from here on.

    float O[8][4];
#pragma unroll
    for (int nt = 0; nt < 8; nt++)
#pragma unroll
        for (int c = 0; c < 4; c++) O[nt][c] = 0.f;
    float m0r = NEG_INF, m1r = NEG_INF, l0r = 0.f, l1r = 0.f;

    for (int kt = 0; kt < 32; kt++) {
        cp_wait0();
        __syncthreads();   // tile kt visible; all warps done reading tile kt-1

        // prefetch tile kt+1 (safe: buffer (kt+1)&1 reads finished before sync)
        if (kt + 1 < 32) {
            const uint32_t bo = (uint32_t)(((kt + 1) & 1) * KV_TILE * 4);
            const float* khg = Khg + (size_t)(kt + 1) * 64 * Dd;
            const float* klg = Klg + (size_t)(kt + 1) * 64 * Dd;
            const float* vtg = VTg + (size_t)(kt + 1) * 64;
#pragma unroll
            for (int i = 0; i < 4; i++) {
                int row = lrow + 16 * i;
                uint32_t so = (uint32_t)((row * FSTR + lcol * 4) * 4);
                cp_async16(sKh + bo + so, khg + (size_t)row * Dd + lcol * 4);
                cp_async16(sKl + bo + so, klg + (size_t)row * Dd + lcol * 4);
                cp_async16(sVt + bo + so, vtg + (size_t)row * Ss + lcol * 4);
            }
            cp_commit();
        }

        // mask fragments (overlap DRAM with QK mma)
        float2 mk0[8], mk1[8];
        {
            const float* mr0 = Mg + (size_t)(wm + rq) * Ss + kt * 64 + 2 * cq;
            const float* mr1 = mr0 + 8 * Ss;
#pragma unroll
            for (int nt = 0; nt < 8; nt++) {
                mk0[nt] = *(const float2*)(mr0 + nt * 8);
                mk1[nt] = *(const float2*)(mr1 + nt * 8);
            }
        }

        // ---- S = Q K^T (split tf32; n0/n1 interleaved for dep distance) ----
        float S[8][4];
#pragma unroll
        for (int nt = 0; nt < 8; nt++)
#pragma unroll
            for (int c = 0; c < 4; c++) S[nt][c] = 0.f;

        const uint32_t kb_off = (uint32_t)((kt & 1) * KV_TILE * 4)
                              + (uint32_t)((row_add * FSTR + koff) * 4);
        const uint32_t khb = sKh + kb_off;
        const uint32_t klb = sKl + kb_off;
#pragma unroll
        for (int ks = 0; ks < 8; ks++) {
#pragma unroll
            for (int p = 0; p < 4; p++) {
                const uint32_t off = (uint32_t)((p * 16 * FSTR) * 4 + ks * 32);
                uint32_t h0, h1, h2, h3, l0, l1, l2, l3;
                ldsm_x4(h0, h1, h2, h3, khb + off);
                ldsm_x4(l0, l1, l2, l3, klb + off);
                const int n0 = 2 * p, n1 = 2 * p + 1;
                mma_tf32(S[n0][0], S[n0][1], S[n0][2], S[n0][3],
                         Qh[ks][0], Qh[ks][1], Qh[ks][2], Qh[ks][3], h0, h1);
                mma_tf32(S[n1][0], S[n1][1], S[n1][2], S[n1][3],
                         Qh[ks][0], Qh[ks][1], Qh[ks][2], Qh[ks][3], h2, h3);
                mma_tf32(S[n0][0], S[n0][1], S[n0][2], S[n0][3],
                         Qh[ks][0], Qh[ks][1], Qh[ks][2], Qh[ks][3], l0, l1);
                mma_tf32(S[n1][0], S[n1][1], S[n1][2], S[n1][3],
                         Qh[ks][0], Qh[ks][1], Qh[ks][2], Qh[ks][3], l2, l3);
                mma_tf32(S[n0][0], S[n0][1], S[n0][2], S[n0][3],
                         Ql[ks][0], Ql[ks][1], Ql[ks][2], Ql[ks][3], h0, h1);
                mma_tf32(S[n1][0], S[n1][1], S[n1][2], S[n1][3],
                         Ql[ks][0], Ql[ks][1], Ql[ks][2], Ql[ks][3], h2, h3);
            }
        }

        // ---- scale + mask + online softmax ----
        float rm0 = NEG_INF, rm1 = NEG_INF;
#pragma unroll
        for (int nt = 0; nt < 8; nt++) {
            S[nt][0] = S[nt][0] * 0.125f + mk0[nt].x * (-1e9f);
            S[nt][1] = S[nt][1] * 0.125f + mk0[nt].y * (-1e9f);
            S[nt][2] = S[nt][2] * 0.125f + mk1[nt].x * (-1e9f);
            S[nt][3] = S[nt][3] * 0.125f + mk1[nt].y * (-1e9f);
            rm0 = fmaxf(rm0, fmaxf(S[nt][0], S[nt][1]));
            rm1 = fmaxf(rm1, fmaxf(S[nt][2], S[nt][3]));
        }
        rm0 = fmaxf(rm0, __shfl_xor_sync(0xffffffffu, rm0, 1));
        rm0 = fmaxf(rm0, __shfl_xor_sync(0xffffffffu, rm0, 2));
        rm1 = fmaxf(rm1, __shfl_xor_sync(0xffffffffu, rm1, 1));
        rm1 = fmaxf(rm1, __shfl_xor_sync(0xffffffffu, rm1, 2));

        const float nm0 = fmaxf(m0r, rm0);
        const float nm1 = fmaxf(m1r, rm1);
        const float sc0 = __expf(m0r - nm0);
        const float sc1 = __expf(m1r - nm1);
        m0r = nm0; m1r = nm1;

        float rs0 = 0.f, rs1 = 0.f;
#pragma unroll
        for (int nt = 0; nt < 8; nt++) {
            S[nt][0] = __expf(S[nt][0] - nm0);
            S[nt][1] = __expf(S[nt][1] - nm0);
            S[nt][2] = __expf(S[nt][2] - nm1);
            S[nt][3] = __expf(S[nt][3] - nm1);
            rs0 += S[nt][0] + S[nt][1];
            rs1 += S[nt][2] + S[nt][3];
        }
        rs0 += __shfl_xor_sync(0xffffffffu, rs0, 1);
        rs0 += __shfl_xor_sync(0xffffffffu, rs0, 2);
        rs1 += __shfl_xor_sync(0xffffffffu, rs1, 1);
        rs1 += __shfl_xor_sync(0xffffffffu, rs1, 2);
        l0r = l0r * sc0 + rs0;
        l1r = l1r * sc1 + rs1;

#pragma unroll
        for (int nt = 0; nt < 8; nt++) {
            O[nt][0] *= sc0; O[nt][1] *= sc0;
            O[nt][2] *= sc1; O[nt][3] *= sc1;
        }

        // ---- store P (warp-private rows) ----
        {
            float* p0 = Pbuf + (wm + rq) * FSTR + 2 * cq;
            float* p1 = p0 + 8 * FSTR;
#pragma unroll
            for (int nt = 0; nt < 8; nt++) {
                *(float2*)(p0 + nt * 8) = make_float2(S[nt][0], S[nt][1]);
                *(float2*)(p1 + nt * 8) = make_float2(S[nt][2], S[nt][3]);
            }
        }
        __syncwarp();   // P rows visible within warp (only reader)

        // ---- O += P V ----
        const uint32_t pb = sP + (uint32_t)(((wm + row_add) * FSTR + koff) * 4);
        const uint32_t vb = sVt + (uint32_t)((kt & 1) * KV_TILE * 4)
                          + (uint32_t)((row_add * FSTR + koff) * 4);
#pragma unroll
        for (int ks = 0; ks < 8; ks++) {
            uint32_t pr0, pr1, pr2, pr3;
            ldsm_x4(pr0, pr1, pr2, pr3, pb + (uint32_t)(ks * 32));
            uint32_t a0 = f2tf32(pr0), a1 = f2tf32(pr2), a2 = f2tf32(pr1), a3 = f2tf32(pr3);
#pragma unroll
            for (int p = 0; p < 4; p++) {
                uint32_t v0, v1, v2, v3;
                ldsm_x4(v0, v1, v2, v3, vb + (uint32_t)((p * 16 * FSTR) * 4 + ks * 32));
                const int n0 = 2 * p, n1 = 2 * p + 1;
                mma_tf32(O[n0][0], O[n0][1], O[n0][2], O[n0][3], a0, a1, a2, a3, v0, v1);
                mma_tf32(O[n1][0], O[n1][1], O[n1][2], O[n1][3], a0, a1, a2, a3, v2, v3);
            }
        }
    }

    // ---- epilogue ----
    const float inv0 = 1.f / l0r;
    const float inv1 = 1.f / l1r;
    float* o0 = Out + ((size_t)b * Ss + q0 + wm + rq) * Dd + h * DP + 2 * cq;
    float* o1 = o0 + (size_t)8 * Dd;
#pragma unroll
    for (int nt = 0; nt < 8; nt++) {
        *(float2*)(o0 + nt * 8) = make_float2(O[nt][0] * inv0, O[nt][1] * inv0);
        *(float2*)(o1 + nt * 8) = make_float2(O[nt][2] * inv1, O[nt][3] * inv1);
    }
}

// ---------------------------------------------------------------------------
extern "C" void kernel_launch(void* const* d_in, const int* in_sizes, int n_in,
                              void* d_out, int out_size)
{
    const float* q    = (const float*)d_in[0];
    const float* k    = (const float*)d_in[1];
    const float* v    = (const float*)d_in[2];
    const float* mask = (const float*)d_in[3];
    const float* wq_w = (const float*)d_in[4];
    const float* wq_b = (const float*)d_in[5];
    const float* wk_w = (const float*)d_in[6];
    const float* wk_b = (const float*)d_in[7];
    const float* wv_w = (const float*)d_in[8];
    const float* wv_b = (const float*)d_in[9];
    const float* fc_w = (const float*)d_in[10];
    const float* fc_b = (const float*)d_in[11];

    float *pQ, *pKh, *pKl, *pVT, *pScr;
    cudaGetSymbolAddress((void**)&pQ, g_Qp);
    cudaGetSymbolAddress((void**)&pKh, g_Kh);
    cudaGetSymbolAddress((void**)&pKl, g_Kl);
    cudaGetSymbolAddress((void**)&pVT, g_VT);
    cudaGetSymbolAddress((void**)&pScr, g_attn_scratch);

    float* out_main = (float*)d_out;
    const size_t OUT1 = (size_t)MM * Dd;
    float* attn_out = ((size_t)out_size >= 2 * OUT1) ? (out_main + OUT1) : pScr;

    static bool attr_set = false;
    if (!attr_set) {
        cudaFuncSetAttribute(flash_attn_tc, cudaFuncAttributeMaxDynamicSharedMemorySize,
                             FLASH_SMEM_BYTES);
        attr_set = true;
    }

    qkv_gemm<<<dim3(Dd / GBN, MM / GBM, 3), 256>>>(
        q, k, v, wq_w, wk_w, wv_w, wq_b, wk_b, wv_b, pQ, pKh, pKl, pVT);

    flash_attn_tc<<<dim3(Ss / 128, Hh, Bb), 256, FLASH_SMEM_BYTES>>>(
        pQ, pKh, pKl, pVT, mask, attn_out);

    fc_gemm<<<dim3(Dd / GBN, MM / GBM), 256>>>(attn_out, fc_w, fc_b, out_main);
}

// round 8
// speedup vs baseline: 2.8142x; 1.0309x over previous
#include <cuda_runtime.h>
#include <cstdint>

// ---------------------------------------------------------------------------
// MultiHeadAttn: B=2, S=2048, D=1024, H=16, depth=64
// Stage 1: merged QKV projections (grid.z): z=0 Q fp32, z=1 K tf32-rounded,
//          z=2 V^T tf32-rounded.
// Stage 2: flash attention: QK = (Qh+Ql)·Khat (2-term split), PV plain tf32.
// Stage 3: fc output projection.
// GEMMs: BK=32, 2-stage cp.async pipeline, dynamic smem (72KB), 2 CTA/SM.
// ---------------------------------------------------------------------------

#define NEG_INF (-3.402823466e38f)

static constexpr int Bb = 2;
static constexpr int Ss = 2048;
static constexpr int Dd = 1024;
static constexpr int Hh = 16;
static constexpr int DP = 64;
static constexpr int MM = Bb * Ss;  // 4096

__device__ float g_Qp[(size_t)MM * Dd];
__device__ float g_Kh[(size_t)MM * Dd];
__device__ float g_VT[(size_t)MM * Dd];   // [B, H, DP, Ss]
__device__ float g_attn_scratch[(size_t)MM * Dd];

// ---------------------------------------------------------------------------
// PTX helpers
// ---------------------------------------------------------------------------
__device__ __forceinline__ uint32_t cvta_smem(const void* p) {
    return (uint32_t)__cvta_generic_to_shared(p);
}
__device__ __forceinline__ void cp_async16(uint32_t dst, const void* src) {
    asm volatile("cp.async.cg.shared.global [%0], [%1], 16;\n" :: "r"(dst), "l"(src));
}
__device__ __forceinline__ void cp_commit() {
    asm volatile("cp.async.commit_group;\n");
}
__device__ __forceinline__ void cp_wait0() {
    asm volatile("cp.async.wait_group 0;\n");
}
__device__ __forceinline__ void ldsm_x4(uint32_t& r0, uint32_t& r1, uint32_t& r2, uint32_t& r3,
                                        uint32_t addr) {
    asm volatile("ldmatrix.sync.aligned.m8n8.x4.shared.b16 {%0,%1,%2,%3}, [%4];\n"
                 : "=r"(r0), "=r"(r1), "=r"(r2), "=r"(r3) : "r"(addr));
}
__device__ __forceinline__ uint32_t f2tf32(uint32_t bits) {
    float f = __uint_as_float(bits);
    uint32_t r;
    asm volatile("cvt.rna.tf32.f32 %0, %1;\n" : "=r"(r) : "f"(f));
    return r;
}
__device__ __forceinline__ float tf32_round(float x) {
    uint32_t r;
    asm volatile("cvt.rna.tf32.f32 %0, %1;\n" : "=r"(r) : "f"(x));
    return __uint_as_float(r);
}
__device__ __forceinline__ uint32_t tf32_lo(uint32_t bits, uint32_t hi) {
    float d = __uint_as_float(bits) - __uint_as_float(hi);
    uint32_t r;
    asm volatile("cvt.rna.tf32.f32 %0, %1;\n" : "=r"(r) : "f"(d));
    return r;
}
__device__ __forceinline__ void mma_tf32(float& d0, float& d1, float& d2, float& d3,
                                         uint32_t a0, uint32_t a1, uint32_t a2, uint32_t a3,
                                         uint32_t b0, uint32_t b1) {
    asm volatile(
        "mma.sync.aligned.m16n8k8.row.col.f32.tf32.tf32.f32 "
        "{%0,%1,%2,%3}, {%4,%5,%6,%7}, {%8,%9}, {%0,%1,%2,%3};\n"
        : "+f"(d0), "+f"(d1), "+f"(d2), "+f"(d3)
        : "r"(a0), "r"(a1), "r"(a2), "r"(a3), "r"(b0), "r"(b1));
}

// ---------------------------------------------------------------------------
// GEMM mainloop core: acc = A @ W^T, 128x128 tile, BK=32, 2-stage pipeline.
// Shared memory is dynamic: [As stage0 | As stage1 | Bs stage0 | Bs stage1].
// ---------------------------------------------------------------------------
#define GBM 128
#define GBN 128
#define GBK 32
#define GSTR 36                       // floats per smem row (32 + 4 pad)
#define GTILE_FLOATS (GBM * GSTR)     // 4608 floats per array per stage
#define GTILE_BYTES (GTILE_FLOATS * 4)
#define GEMM_SMEM_BYTES (4 * GTILE_BYTES)   // 73728

struct GemmCtx {
    float acc[4][4][4];
};

__device__ __forceinline__ void gemm_mainloop(
    const float* __restrict__ A, const float* __restrict__ W,
    int m0, int n0, int K, float* As, float* Bs, GemmCtx& ctx)
{
    const int tid  = threadIdx.x;
    const int lane = tid & 31;
    const int wid  = tid >> 5;
    const int wm   = (wid & 1) * 64;
    const int wn   = (wid >> 1) * 32;

    const uint32_t sA = cvta_smem(As);
    const uint32_t sB = cvta_smem(Bs);

    // loader: 128 rows x 32 floats per array; thread -> row=tid>>1, half=(tid&1)*16
    const int lr = tid >> 1;
    const int hc = (tid & 1) * 16;
    const float* Ap = A + (size_t)(m0 + lr) * K + hc;
    const float* Wp = W + (size_t)(n0 + lr) * K + hc;
    const uint32_t dA = sA + (uint32_t)((lr * GSTR + hc) * 4);
    const uint32_t dB = sB + (uint32_t)((lr * GSTR + hc) * 4);

    const int g       = lane >> 3;
    const int glr     = lane & 7;
    const int row_add = ((g >> 1) << 3) + glr;
    const int koff    = (g & 1) << 2;
    const uint32_t aBase = sA + (uint32_t)(((wm + row_add) * GSTR + koff) * 4);
    const uint32_t bBase = sB + (uint32_t)(((wn + row_add) * GSTR + koff) * 4);

#pragma unroll
    for (int i = 0; i < 4; i++)
#pragma unroll
        for (int j = 0; j < 4; j++)
#pragma unroll
            for (int c = 0; c < 4; c++) ctx.acc[i][j][c] = 0.f;

    const int NSTAGE = K / GBK;

#pragma unroll
    for (int j = 0; j < 4; j++) {
        cp_async16(dA + (uint32_t)(j * 16), Ap + j * 4);
        cp_async16(dB + (uint32_t)(j * 16), Wp + j * 4);
    }
    cp_commit();

    for (int kt = 0; kt < NSTAGE; kt++) {
        cp_wait0();
        __syncthreads();

        if (kt + 1 < NSTAGE) {
            const int k0 = (kt + 1) * GBK;
            const uint32_t bo = (uint32_t)(((kt + 1) & 1) * GTILE_BYTES);
#pragma unroll
            for (int j = 0; j < 4; j++) {
                cp_async16(dA + bo + (uint32_t)(j * 16), Ap + k0 + j * 4);
                cp_async16(dB + bo + (uint32_t)(j * 16), Wp + k0 + j * 4);
            }
            cp_commit();
        }

        const uint32_t bo = (uint32_t)((kt & 1) * GTILE_BYTES);
#pragma unroll
        for (int ks = 0; ks < 4; ks++) {
            const uint32_t ao = aBase + bo + (uint32_t)(ks * 32);
            const uint32_t bb = bBase + bo + (uint32_t)(ks * 32);

            uint32_t af[4][4], bf[4][2];
#pragma unroll
            for (int mt = 0; mt < 4; mt++) {
                uint32_t r0, r1, r2, r3;
                ldsm_x4(r0, r1, r2, r3, ao + (uint32_t)(mt * 16 * GSTR * 4));
                af[mt][0] = f2tf32(r0);
                af[mt][1] = f2tf32(r2);
                af[mt][2] = f2tf32(r1);
                af[mt][3] = f2tf32(r3);
            }
#pragma unroll
            for (int p = 0; p < 2; p++) {
                uint32_t r0, r1, r2, r3;
                ldsm_x4(r0, r1, r2, r3, bb + (uint32_t)(p * 16 * GSTR * 4));
                bf[2 * p][0]     = f2tf32(r0);
                bf[2 * p][1]     = f2tf32(r1);
                bf[2 * p + 1][0] = f2tf32(r2);
                bf[2 * p + 1][1] = f2tf32(r3);
            }
#pragma unroll
            for (int mt = 0; mt < 4; mt++)
#pragma unroll
                for (int nt = 0; nt < 4; nt++)
                    mma_tf32(ctx.acc[mt][nt][0], ctx.acc[mt][nt][1],
                             ctx.acc[mt][nt][2], ctx.acc[mt][nt][3],
                             af[mt][0], af[mt][1], af[mt][2], af[mt][3],
                             bf[nt][0], bf[nt][1]);
        }
        __syncthreads();
    }
}

// ---------------------------------------------------------------------------
// Merged QKV projection. grid.z: 0=Q fp32, 1=K tf32-rounded, 2=V^T rounded.
// ---------------------------------------------------------------------------
__global__ __launch_bounds__(256, 2)
void qkv_gemm(const float* __restrict__ q, const float* __restrict__ k,
              const float* __restrict__ v,
              const float* __restrict__ wq, const float* __restrict__ wk,
              const float* __restrict__ wv,
              const float* __restrict__ bq, const float* __restrict__ bk,
              const float* __restrict__ bv,
              float* __restrict__ Qout, float* __restrict__ Kh,
              float* __restrict__ VT)
{
    extern __shared__ __align__(16) float gsm[];
    float* As = gsm;                     // 2 stages
    float* Bs = gsm + 2 * GTILE_FLOATS;  // 2 stages

    const int z  = blockIdx.z;
    const int m0 = blockIdx.y * GBM;
    const int n0 = blockIdx.x * GBN;

    const float* A    = (z == 0) ? q  : (z == 1) ? k  : v;
    const float* W    = (z == 0) ? wq : (z == 1) ? wk : wv;
    const float* bias = (z == 0) ? bq : (z == 1) ? bk : bv;

    GemmCtx ctx;
    gemm_mainloop(A, W, m0, n0, Dd, As, Bs, ctx);

    const int lane = threadIdx.x & 31;
    const int wid  = threadIdx.x >> 5;
    const int wm   = (wid & 1) * 64;
    const int wn   = (wid >> 1) * 32;

#pragma unroll
    for (int mt = 0; mt < 4; mt++) {
        const int row = m0 + wm + mt * 16 + (lane >> 2);
#pragma unroll
        for (int nt = 0; nt < 4; nt++) {
            const int col = n0 + wn + nt * 8 + (lane & 3) * 2;
            const float b0 = bias[col], b1 = bias[col + 1];
            float v00 = ctx.acc[mt][nt][0] + b0, v01 = ctx.acc[mt][nt][1] + b1;
            float v10 = ctx.acc[mt][nt][2] + b0, v11 = ctx.acc[mt][nt][3] + b1;
            if (z == 0) {
                *(float2*)&Qout[(size_t)row * Dd + col]       = make_float2(v00, v01);
                *(float2*)&Qout[(size_t)(row + 8) * Dd + col] = make_float2(v10, v11);
            } else if (z == 1) {
                *(float2*)&Kh[(size_t)row * Dd + col] =
                    make_float2(tf32_round(v00), tf32_round(v01));
                *(float2*)&Kh[(size_t)(row + 8) * Dd + col] =
                    make_float2(tf32_round(v10), tf32_round(v11));
            } else {
                // V^T[b, h, d, s]
                const int b_  = row >> 11, s0 = row & 2047;
                const int h_  = col >> 6,  d0 = col & 63;
                float* base = VT + (((size_t)b_ * Hh + h_) * DP + d0) * Ss + s0;
                base[0]      = tf32_round(v00);
                base[Ss]     = tf32_round(v01);
                base[8]      = tf32_round(v10);
                base[Ss + 8] = tf32_round(v11);
            }
        }
    }
}

// fc output projection (fp32 epilogue with bias)
__global__ __launch_bounds__(256, 2)
void fc_gemm(const float* __restrict__ A, const float* __restrict__ W,
             const float* __restrict__ bias, float* __restrict__ C)
{
    extern __shared__ __align__(16) float gsm[];
    float* As = gsm;
    float* Bs = gsm + 2 * GTILE_FLOATS;

    const int m0 = blockIdx.y * GBM;
    const int n0 = blockIdx.x * GBN;

    GemmCtx ctx;
    gemm_mainloop(A, W, m0, n0, Dd, As, Bs, ctx);

    const int lane = threadIdx.x & 31;
    const int wid  = threadIdx.x >> 5;
    const int wm   = (wid & 1) * 64;
    const int wn   = (wid >> 1) * 32;

#pragma unroll
    for (int mt = 0; mt < 4; mt++) {
        const int row = m0 + wm + mt * 16 + (lane >> 2);
#pragma unroll
        for (int nt = 0; nt < 4; nt++) {
            const int col = n0 + wn + nt * 8 + (lane & 3) * 2;
            const float b0 = bias[col], b1 = bias[col + 1];
            *(float2*)&C[(size_t)row * Dd + col] =
                make_float2(ctx.acc[mt][nt][0] + b0, ctx.acc[mt][nt][1] + b1);
            *(float2*)&C[(size_t)(row + 8) * Dd + col] =
                make_float2(ctx.acc[mt][nt][2] + b0, ctx.acc[mt][nt][3] + b1);
        }
    }
}

// ---------------------------------------------------------------------------
// Tensor-core flash attention. QK = (Qh + Ql) · Khat; PV plain tf32.
// CTA: 128 queries x one (b,h). 8 warps x 16 rows. Key tiles of 64.
// smem: Kh dbuf | Vt dbuf | P (=Q stage). 1 syncthreads + 1 syncwarp / iter.
// ---------------------------------------------------------------------------
#define FSTR 68
#define KV_TILE (64 * FSTR)
#define FLASH_SMEM_FLOATS (4 * KV_TILE + 128 * FSTR)
#define FLASH_SMEM_BYTES (FLASH_SMEM_FLOATS * 4)

__global__ __launch_bounds__(256, 1)
void flash_attn_tc(const float* __restrict__ Qp, const float* __restrict__ Kh_g,
                   const float* __restrict__ VT_g, const float* __restrict__ mask,
                   float* __restrict__ Out)
{
    extern __shared__ float fsm[];
    float* Khb  = fsm;                       // 2 * KV_TILE
    float* Vtb  = Khb + 2 * KV_TILE;         // 2 * KV_TILE (rows=d, cols=key)
    float* Pbuf = Vtb + 2 * KV_TILE;         // 128 * FSTR (Q stage, then P)

    const uint32_t sKh = cvta_smem(Khb);
    const uint32_t sVt = cvta_smem(Vtb);
    const uint32_t sP  = cvta_smem(Pbuf);

    const int tid  = threadIdx.x;
    const int lane = tid & 31;
    const int wid  = tid >> 5;
    const int wm   = wid * 16;
    const int q0   = blockIdx.x * 128;
    const int h    = blockIdx.y;
    const int b    = blockIdx.z;

    const float* Qg  = Qp   + ((size_t)b * Ss + q0) * Dd + h * DP;
    const float* Khg = Kh_g + ((size_t)b * Ss) * Dd + h * DP;
    const float* VTg = VT_g + ((size_t)b * Hh + h) * DP * Ss;  // [d][s]
    const float* Mg  = mask + (((size_t)b * Hh + h) * Ss + q0) * Ss;

    const int g       = lane >> 3;
    const int glr     = lane & 7;
    const int row_add = ((g >> 1) << 3) + glr;
    const int koff    = (g & 1) << 2;

    const int rq = lane >> 2;
    const int cq = lane & 3;

    const int lrow = tid >> 4;        // 0..15 (+16*i)
    const int lcol = tid & 15;

    // ---- prefetch tile 0 ----
    {
#pragma unroll
        for (int i = 0; i < 4; i++) {
            int row = lrow + 16 * i;
            uint32_t so = (uint32_t)((row * FSTR + lcol * 4) * 4);
            cp_async16(sKh + so, Khg + (size_t)row * Dd + lcol * 4);
            cp_async16(sVt + so, VTg + (size_t)row * Ss + lcol * 4);
        }
        cp_commit();
    }

    // ---- stage Q into Pbuf, extract hi/lo fragments ----
#pragma unroll
    for (int i = 0; i < 8; i++) {
        int id = tid + 256 * i;
        int row = id >> 4, col = id & 15;
        float4 v = *(const float4*)(Qg + (size_t)row * Dd + col * 4);
        *(float4*)&Pbuf[row * FSTR + col * 4] = v;
    }
    __syncthreads();

    uint32_t Qh[8][4], Ql[8][4];
    {
        const uint32_t base = sP + (uint32_t)(((wm + row_add) * FSTR + koff) * 4);
#pragma unroll
        for (int ks = 0; ks < 8; ks++) {
            uint32_t r0, r1, r2, r3;
            ldsm_x4(r0, r1, r2, r3, base + (uint32_t)(ks * 32));
            Qh[ks][0] = f2tf32(r0); Ql[ks][0] = tf32_lo(r0, Qh[ks][0]);
            Qh[ks][1] = f2tf32(r2); Ql[ks][1] = tf32_lo(r2, Qh[ks][1]);
            Qh[ks][2] = f2tf32(r1); Ql[ks][2] = tf32_lo(r1, Qh[ks][2]);
            Qh[ks][3] = f2tf32(r3); Ql[ks][3] = tf32_lo(r3, Qh[ks][3]);
        }
    }

    float O[8][4];
#pragma unroll
    for (int nt = 0; nt < 8; nt++)
#pragma unroll
        for (int c = 0; c < 4; c++) O[nt][c] = 0.f;
    float m0r = NEG_INF, m1r = NEG_INF, l0r = 0.f, l1r = 0.f;

    for (int kt = 0; kt < 32; kt++) {
        cp_wait0();
        __syncthreads();   // tile kt visible; all warps done with buffer (kt+1)&1

        // prefetch tile kt+1
        if (kt + 1 < 32) {
            const uint32_t bo = (uint32_t)(((kt + 1) & 1) * KV_TILE * 4);
            const float* khg = Khg + (size_t)(kt + 1) * 64 * Dd;
            const float* vtg = VTg + (size_t)(kt + 1) * 64;
#pragma unroll
            for (int i = 0; i < 4; i++) {
                int row = lrow + 16 * i;
                uint32_t so = (uint32_t)((row * FSTR + lcol * 4) * 4);
                cp_async16(sKh + bo + so, khg + (size_t)row * Dd + lcol * 4);
                cp_async16(sVt + bo + so, vtg + (size_t)row * Ss + lcol * 4);
            }
            cp_commit();
        }

        // mask fragments (overlap DRAM with QK mma)
        float2 mk0[8], mk1[8];
        {
            const float* mr0 = Mg + (size_t)(wm + rq) * Ss + kt * 64 + 2 * cq;
            const float* mr1 = mr0 + 8 * Ss;
#pragma unroll
            for (int nt = 0; nt < 8; nt++) {
                mk0[nt] = *(const float2*)(mr0 + nt * 8);
                mk1[nt] = *(const float2*)(mr1 + nt * 8);
            }
        }

        // ---- S = (Qh + Ql) · Khat ----
        float S[8][4];
#pragma unroll
        for (int nt = 0; nt < 8; nt++)
#pragma unroll
            for (int c = 0; c < 4; c++) S[nt][c] = 0.f;

        const uint32_t khb = sKh + (uint32_t)((kt & 1) * KV_TILE * 4)
                           + (uint32_t)((row_add * FSTR + koff) * 4);
#pragma unroll
        for (int ks = 0; ks < 8; ks++) {
#pragma unroll
            for (int p = 0; p < 4; p++) {
                const uint32_t off = (uint32_t)((p * 16 * FSTR) * 4 + ks * 32);
                uint32_t h0, h1, h2, h3;
                ldsm_x4(h0, h1, h2, h3, khb + off);
                const int n0 = 2 * p, n1 = 2 * p + 1;
                mma_tf32(S[n0][0], S[n0][1], S[n0][2], S[n0][3],
                         Qh[ks][0], Qh[ks][1], Qh[ks][2], Qh[ks][3], h0, h1);
                mma_tf32(S[n1][0], S[n1][1], S[n1][2], S[n1][3],
                         Qh[ks][0], Qh[ks][1], Qh[ks][2], Qh[ks][3], h2, h3);
                mma_tf32(S[n0][0], S[n0][1], S[n0][2], S[n0][3],
                         Ql[ks][0], Ql[ks][1], Ql[ks][2], Ql[ks][3], h0, h1);
                mma_tf32(S[n1][0], S[n1][1], S[n1][2], S[n1][3],
                         Ql[ks][0], Ql[ks][1], Ql[ks][2], Ql[ks][3], h2, h3);
            }
        }

        // ---- scale + mask + online softmax ----
        float rm0 = NEG_INF, rm1 = NEG_INF;
#pragma unroll
        for (int nt = 0; nt < 8; nt++) {
            S[nt][0] = S[nt][0] * 0.125f + mk0[nt].x * (-1e9f);
            S[nt][1] = S[nt][1] * 0.125f + mk0[nt].y * (-1e9f);
            S[nt][2] = S[nt][2] * 0.125f + mk1[nt].x * (-1e9f);
            S[nt][3] = S[nt][3] * 0.125f + mk1[nt].y * (-1e9f);
            rm0 = fmaxf(rm0, fmaxf(S[nt][0], S[nt][1]));
            rm1 = fmaxf(rm1, fmaxf(S[nt][2], S[nt][3]));
        }
        rm0 = fmaxf(rm0, __shfl_xor_sync(0xffffffffu, rm0, 1));
        rm0 = fmaxf(rm0, __shfl_xor_sync(0xffffffffu, rm0, 2));
        rm1 = fmaxf(rm1, __shfl_xor_sync(0xffffffffu, rm1, 1));
        rm1 = fmaxf(rm1, __shfl_xor_sync(0xffffffffu, rm1, 2));

        const float nm0 = fmaxf(m0r, rm0);
        const float nm1 = fmaxf(m1r, rm1);
        const float sc0 = __expf(m0r - nm0);
        const float sc1 = __expf(m1r - nm1);
        m0r = nm0; m1r = nm1;

        float rs0 = 0.f, rs1 = 0.f;
#pragma unroll
        for (int nt = 0; nt < 8; nt++) {
            S[nt][0] = __expf(S[nt][0] - nm0);
            S[nt][1] = __expf(S[nt][1] - nm0);
            S[nt][2] = __expf(S[nt][2] - nm1);
            S[nt][3] = __expf(S[nt][3] - nm1);
            rs0 += S[nt][0] + S[nt][1];
            rs1 += S[nt][2] + S[nt][3];
        }
        rs0 += __shfl_xor_sync(0xffffffffu, rs0, 1);
        rs0 += __shfl_xor_sync(0xffffffffu, rs0, 2);
        rs1 += __shfl_xor_sync(0xffffffffu, rs1, 1);
        rs1 += __shfl_xor_sync(0xffffffffu, rs1, 2);
        l0r = l0r * sc0 + rs0;
        l1r = l1r * sc1 + rs1;

#pragma unroll
        for (int nt = 0; nt < 8; nt++) {
            O[nt][0] *= sc0; O[nt][1] *= sc0;
            O[nt][2] *= sc1; O[nt][3] *= sc1;
        }

        // ---- store P (warp-private rows) ----
        {
            float* p0 = Pbuf + (wm + rq) * FSTR + 2 * cq;
            float* p1 = p0 + 8 * FSTR;
#pragma unroll
            for (int nt = 0; nt < 8; nt++) {
                *(float2*)(p0 + nt * 8) = make_float2(S[nt][0], S[nt][1]);
                *(float2*)(p1 + nt * 8) = make_float2(S[nt][2], S[nt][3]);
            }
        }
        __syncwarp();

        // ---- O += P V ----
        const uint32_t pb = sP + (uint32_t)(((wm + row_add) * FSTR + koff) * 4);
        const uint32_t vb = sVt + (uint32_t)((kt & 1) * KV_TILE * 4)
                          + (uint32_t)((row_add * FSTR + koff) * 4);
#pragma unroll
        for (int ks = 0; ks < 8; ks++) {
            uint32_t pr0, pr1, pr2, pr3;
            ldsm_x4(pr0, pr1, pr2, pr3, pb + (uint32_t)(ks * 32));
            uint32_t a0 = f2tf32(pr0), a1 = f2tf32(pr2), a2 = f2tf32(pr1), a3 = f2tf32(pr3);
#pragma unroll
            for (int p = 0; p < 4; p++) {
                uint32_t v0, v1, v2, v3;
                ldsm_x4(v0, v1, v2, v3, vb + (uint32_t)((p * 16 * FSTR) * 4 + ks * 32));
                const int n0 = 2 * p, n1 = 2 * p + 1;
                mma_tf32(O[n0][0], O[n0][1], O[n0][2], O[n0][3], a0, a1, a2, a3, v0, v1);
                mma_tf32(O[n1][0], O[n1][1], O[n1][2], O[n1][3], a0, a1, a2, a3, v2, v3);
            }
        }
    }

    // ---- epilogue ----
    const float inv0 = 1.f / l0r;
    const float inv1 = 1.f / l1r;
    float* o0 = Out + ((size_t)b * Ss + q0 + wm + rq) * Dd + h * DP + 2 * cq;
    float* o1 = o0 + (size_t)8 * Dd;
#pragma unroll
    for (int nt = 0; nt < 8; nt++) {
        *(float2*)(o0 + nt * 8) = make_float2(O[nt][0] * inv0, O[nt][1] * inv0);
        *(float2*)(o1 + nt * 8) = make_float2(O[nt][2] * inv1, O[nt][3] * inv1);
    }
}

// ---------------------------------------------------------------------------
extern "C" void kernel_launch(void* const* d_in, const int* in_sizes, int n_in,
                              void* d_out, int out_size)
{
    const float* q    = (const float*)d_in[0];
    const float* k    = (const float*)d_in[1];
    const float* v    = (const float*)d_in[2];
    const float* mask = (const float*)d_in[3];
    const float* wq_w = (const float*)d_in[4];
    const float* wq_b = (const float*)d_in[5];
    const float* wk_w = (const float*)d_in[6];
    const float* wk_b = (const float*)d_in[7];
    const float* wv_w = (const float*)d_in[8];
    const float* wv_b = (const float*)d_in[9];
    const float* fc_w = (const float*)d_in[10];
    const float* fc_b = (const float*)d_in[11];

    float *pQ, *pKh, *pVT, *pScr;
    cudaGetSymbolAddress((void**)&pQ, g_Qp);
    cudaGetSymbolAddress((void**)&pKh, g_Kh);
    cudaGetSymbolAddress((void**)&pVT, g_VT);
    cudaGetSymbolAddress((void**)&pScr, g_attn_scratch);

    float* out_main = (float*)d_out;
    const size_t OUT1 = (size_t)MM * Dd;
    float* attn_out = ((size_t)out_size >= 2 * OUT1) ? (out_main + OUT1) : pScr;

    static bool attr_set = false;
    if (!attr_set) {
        cudaFuncSetAttribute(flash_attn_tc, cudaFuncAttributeMaxDynamicSharedMemorySize,
                             FLASH_SMEM_BYTES);
        cudaFuncSetAttribute(qkv_gemm, cudaFuncAttributeMaxDynamicSharedMemorySize,
                             GEMM_SMEM_BYTES);
        cudaFuncSetAttribute(fc_gemm, cudaFuncAttributeMaxDynamicSharedMemorySize,
                             GEMM_SMEM_BYTES);
        attr_set = true;
    }

    qkv_gemm<<<dim3(Dd / GBN, MM / GBM, 3), 256, GEMM_SMEM_BYTES>>>(
        q, k, v, wq_w, wk_w, wv_w, wq_b, wk_b, wv_b, pQ, pKh, pVT);

    flash_attn_tc<<<dim3(Ss / 128, Hh, Bb), 256, FLASH_SMEM_BYTES>>>(
        pQ, pKh, pVT, mask, attn_out);

    fc_gemm<<<dim3(Dd / GBN, MM / GBM), 256, GEMM_SMEM_BYTES>>>(
        attn_out, fc_w, fc_b, out_main);
}

// round 9
// speedup vs baseline: 3.0666x; 1.0897x over previous
#include <cuda_runtime.h>
#include <cstdint>

// ---------------------------------------------------------------------------
// MultiHeadAttn: B=2, S=2048, D=1024, H=16, depth=64
// Stage 1: merged QKV projections (grid.z): z=0 Q fp32, z=1 K tf32-rounded,
//          z=2 V^T tf32-rounded.  (BK=16 pipeline, proven config)
// Stage 2: flash attention: 64-query CTAs, 4 warps, 2 CTA/SM.
//          QK = (Qh+Ql)·Khat (2-term split), PV plain tf32.
// Stage 3: fc output projection.
// ---------------------------------------------------------------------------

#define NEG_INF (-3.402823466e38f)

static constexpr int Bb = 2;
static constexpr int Ss = 2048;
static constexpr int Dd = 1024;
static constexpr int Hh = 16;
static constexpr int DP = 64;
static constexpr int MM = Bb * Ss;  // 4096

__device__ float g_Qp[(size_t)MM * Dd];
__device__ float g_Kh[(size_t)MM * Dd];
__device__ float g_VT[(size_t)MM * Dd];   // [B, H, DP, Ss]
__device__ float g_attn_scratch[(size_t)MM * Dd];

// ---------------------------------------------------------------------------
// PTX helpers
// ---------------------------------------------------------------------------
__device__ __forceinline__ uint32_t cvta_smem(const void* p) {
    return (uint32_t)__cvta_generic_to_shared(p);
}
__device__ __forceinline__ void cp_async16(uint32_t dst, const void* src) {
    asm volatile("cp.async.cg.shared.global [%0], [%1], 16;\n" :: "r"(dst), "l"(src));
}
__device__ __forceinline__ void cp_commit() {
    asm volatile("cp.async.commit_group;\n");
}
__device__ __forceinline__ void cp_wait0() {
    asm volatile("cp.async.wait_group 0;\n");
}
__device__ __forceinline__ void ldsm_x4(uint32_t& r0, uint32_t& r1, uint32_t& r2, uint32_t& r3,
                                        uint32_t addr) {
    asm volatile("ldmatrix.sync.aligned.m8n8.x4.shared.b16 {%0,%1,%2,%3}, [%4];\n"
                 : "=r"(r0), "=r"(r1), "=r"(r2), "=r"(r3) : "r"(addr));
}
__device__ __forceinline__ uint32_t f2tf32(uint32_t bits) {
    float f = __uint_as_float(bits);
    uint32_t r;
    asm volatile("cvt.rna.tf32.f32 %0, %1;\n" : "=r"(r) : "f"(f));
    return r;
}
__device__ __forceinline__ float tf32_round(float x) {
    uint32_t r;
    asm volatile("cvt.rna.tf32.f32 %0, %1;\n" : "=r"(r) : "f"(x));
    return __uint_as_float(r);
}
__device__ __forceinline__ uint32_t tf32_lo(uint32_t bits, uint32_t hi) {
    float d = __uint_as_float(bits) - __uint_as_float(hi);
    uint32_t r;
    asm volatile("cvt.rna.tf32.f32 %0, %1;\n" : "=r"(r) : "f"(d));
    return r;
}
__device__ __forceinline__ void mma_tf32(float& d0, float& d1, float& d2, float& d3,
                                         uint32_t a0, uint32_t a1, uint32_t a2, uint32_t a3,
                                         uint32_t b0, uint32_t b1) {
    asm volatile(
        "mma.sync.aligned.m16n8k8.row.col.f32.tf32.tf32.f32 "
        "{%0,%1,%2,%3}, {%4,%5,%6,%7}, {%8,%9}, {%0,%1,%2,%3};\n"
        : "+f"(d0), "+f"(d1), "+f"(d2), "+f"(d3)
        : "r"(a0), "r"(a1), "r"(a2), "r"(a3), "r"(b0), "r"(b1));
}

// ---------------------------------------------------------------------------
// GEMM mainloop core (R6 proven config): 128x128 tile, BK=16, 2-stage.
// ---------------------------------------------------------------------------
#define GBM 128
#define GBN 128
#define GBK 16
#define GSTR 20
#define GTILE_BYTES (GBM * GSTR * 4)

struct GemmCtx {
    float acc[4][4][4];
};

__device__ __forceinline__ void gemm_mainloop(
    const float* __restrict__ A, const float* __restrict__ W,
    int m0, int n0, int K, float (*As)[GBM * GSTR], float (*Bs)[GBN * GSTR],
    GemmCtx& ctx)
{
    const int tid  = threadIdx.x;
    const int lane = tid & 31;
    const int wid  = tid >> 5;
    const int wm   = (wid & 1) * 64;
    const int wn   = (wid >> 1) * 32;

    const uint32_t sA = cvta_smem(As);
    const uint32_t sB = cvta_smem(Bs);

    const int lr0 = tid >> 2;
    const int lg  = (tid & 3) * 4;
    const float* Ap0 = A + (size_t)(m0 + lr0) * K + lg;
    const float* Ap1 = A + (size_t)(m0 + lr0 + 64) * K + lg;
    const float* Wp0 = W + (size_t)(n0 + lr0) * K + lg;
    const float* Wp1 = W + (size_t)(n0 + lr0 + 64) * K + lg;
    const uint32_t dA0 = sA + (uint32_t)((lr0 * GSTR + lg) * 4);
    const uint32_t dA1 = sA + (uint32_t)(((lr0 + 64) * GSTR + lg) * 4);
    const uint32_t dB0 = sB + (uint32_t)((lr0 * GSTR + lg) * 4);
    const uint32_t dB1 = sB + (uint32_t)(((lr0 + 64) * GSTR + lg) * 4);

    const int g       = lane >> 3;
    const int glr     = lane & 7;
    const int row_add = ((g >> 1) << 3) + glr;
    const int koff    = (g & 1) << 2;
    const uint32_t aBase = sA + (uint32_t)(((wm + row_add) * GSTR + koff) * 4);
    const uint32_t bBase = sB + (uint32_t)(((wn + row_add) * GSTR + koff) * 4);

#pragma unroll
    for (int i = 0; i < 4; i++)
#pragma unroll
        for (int j = 0; j < 4; j++)
#pragma unroll
            for (int c = 0; c < 4; c++) ctx.acc[i][j][c] = 0.f;

    const int NSTAGE = K / GBK;

    cp_async16(dA0, Ap0); cp_async16(dA1, Ap1);
    cp_async16(dB0, Wp0); cp_async16(dB1, Wp1);
    cp_commit();

    for (int kt = 0; kt < NSTAGE; kt++) {
        cp_wait0();
        __syncthreads();

        if (kt + 1 < NSTAGE) {
            const int k0 = (kt + 1) * GBK;
            const uint32_t bo = (uint32_t)(((kt + 1) & 1) * GTILE_BYTES);
            cp_async16(dA0 + bo, Ap0 + k0);
            cp_async16(dA1 + bo, Ap1 + k0);
            cp_async16(dB0 + bo, Wp0 + k0);
            cp_async16(dB1 + bo, Wp1 + k0);
            cp_commit();
        }

        const uint32_t bo = (uint32_t)((kt & 1) * GTILE_BYTES);
#pragma unroll
        for (int ks = 0; ks < 2; ks++) {
            const uint32_t ao = aBase + bo + (uint32_t)(ks * 32);
            const uint32_t bb = bBase + bo + (uint32_t)(ks * 32);

            uint32_t af[4][4], bf[4][2];
#pragma unroll
            for (int mt = 0; mt < 4; mt++) {
                uint32_t r0, r1, r2, r3;
                ldsm_x4(r0, r1, r2, r3, ao + (uint32_t)(mt * 16 * GSTR * 4));
                af[mt][0] = f2tf32(r0);
                af[mt][1] = f2tf32(r2);
                af[mt][2] = f2tf32(r1);
                af[mt][3] = f2tf32(r3);
            }
#pragma unroll
            for (int p = 0; p < 2; p++) {
                uint32_t r0, r1, r2, r3;
                ldsm_x4(r0, r1, r2, r3, bb + (uint32_t)(p * 16 * GSTR * 4));
                bf[2 * p][0]     = f2tf32(r0);
                bf[2 * p][1]     = f2tf32(r1);
                bf[2 * p + 1][0] = f2tf32(r2);
                bf[2 * p + 1][1] = f2tf32(r3);
            }
#pragma unroll
            for (int mt = 0; mt < 4; mt++)
#pragma unroll
                for (int nt = 0; nt < 4; nt++)
                    mma_tf32(ctx.acc[mt][nt][0], ctx.acc[mt][nt][1],
                             ctx.acc[mt][nt][2], ctx.acc[mt][nt][3],
                             af[mt][0], af[mt][1], af[mt][2], af[mt][3],
                             bf[nt][0], bf[nt][1]);
        }
        __syncthreads();
    }
}

// ---------------------------------------------------------------------------
// Merged QKV projection. grid.z: 0=Q fp32, 1=K tf32-rounded, 2=V^T rounded.
// ---------------------------------------------------------------------------
__global__ __launch_bounds__(256, 2)
void qkv_gemm(const float* __restrict__ q, const float* __restrict__ k,
              const float* __restrict__ v,
              const float* __restrict__ wq, const float* __restrict__ wk,
              const float* __restrict__ wv,
              const float* __restrict__ bq, const float* __restrict__ bk,
              const float* __restrict__ bv,
              float* __restrict__ Qout, float* __restrict__ Kh,
              float* __restrict__ VT)
{
    __shared__ __align__(16) float As[2][GBM * GSTR];
    __shared__ __align__(16) float Bs[2][GBN * GSTR];

    const int z  = blockIdx.z;
    const int m0 = blockIdx.y * GBM;
    const int n0 = blockIdx.x * GBN;

    const float* A    = (z == 0) ? q  : (z == 1) ? k  : v;
    const float* W    = (z == 0) ? wq : (z == 1) ? wk : wv;
    const float* bias = (z == 0) ? bq : (z == 1) ? bk : bv;

    GemmCtx ctx;
    gemm_mainloop(A, W, m0, n0, Dd, As, Bs, ctx);

    const int lane = threadIdx.x & 31;
    const int wid  = threadIdx.x >> 5;
    const int wm   = (wid & 1) * 64;
    const int wn   = (wid >> 1) * 32;

#pragma unroll
    for (int mt = 0; mt < 4; mt++) {
        const int row = m0 + wm + mt * 16 + (lane >> 2);
#pragma unroll
        for (int nt = 0; nt < 4; nt++) {
            const int col = n0 + wn + nt * 8 + (lane & 3) * 2;
            const float b0 = bias[col], b1 = bias[col + 1];
            float v00 = ctx.acc[mt][nt][0] + b0, v01 = ctx.acc[mt][nt][1] + b1;
            float v10 = ctx.acc[mt][nt][2] + b0, v11 = ctx.acc[mt][nt][3] + b1;
            if (z == 0) {
                *(float2*)&Qout[(size_t)row * Dd + col]       = make_float2(v00, v01);
                *(float2*)&Qout[(size_t)(row + 8) * Dd + col] = make_float2(v10, v11);
            } else if (z == 1) {
                *(float2*)&Kh[(size_t)row * Dd + col] =
                    make_float2(tf32_round(v00), tf32_round(v01));
                *(float2*)&Kh[(size_t)(row + 8) * Dd + col] =
                    make_float2(tf32_round(v10), tf32_round(v11));
            } else {
                // V^T[b, h, d, s]
                const int b_  = row >> 11, s0 = row & 2047;
                const int h_  = col >> 6,  d0 = col & 63;
                float* base = VT + (((size_t)b_ * Hh + h_) * DP + d0) * Ss + s0;
                base[0]      = tf32_round(v00);
                base[Ss]     = tf32_round(v01);
                base[8]      = tf32_round(v10);
                base[Ss + 8] = tf32_round(v11);
            }
        }
    }
}

// fc output projection (fp32 epilogue with bias)
__global__ __launch_bounds__(256, 2)
void fc_gemm(const float* __restrict__ A, const float* __restrict__ W,
             const float* __restrict__ bias, float* __restrict__ C)
{
    __shared__ __align__(16) float As[2][GBM * GSTR];
    __shared__ __align__(16) float Bs[2][GBN * GSTR];

    const int m0 = blockIdx.y * GBM;
    const int n0 = blockIdx.x * GBN;

    GemmCtx ctx;
    gemm_mainloop(A, W, m0, n0, Dd, As, Bs, ctx);

    const int lane = threadIdx.x & 31;
    const int wid  = threadIdx.x >> 5;
    const int wm   = (wid & 1) * 64;
    const int wn   = (wid >> 1) * 32;

#pragma unroll
    for (int mt = 0; mt < 4; mt++) {
        const int row = m0 + wm + mt * 16 + (lane >> 2);
#pragma unroll
        for (int nt = 0; nt < 4; nt++) {
            const int col = n0 + wn + nt * 8 + (lane & 3) * 2;
            const float b0 = bias[col], b1 = bias[col + 1];
            *(float2*)&C[(size_t)row * Dd + col] =
                make_float2(ctx.acc[mt][nt][0] + b0, ctx.acc[mt][nt][1] + b1);
            *(float2*)&C[(size_t)(row + 8) * Dd + col] =
                make_float2(ctx.acc[mt][nt][2] + b0, ctx.acc[mt][nt][3] + b1);
        }
    }
}

// ---------------------------------------------------------------------------
// Tensor-core flash attention. 64-query CTA, 4 warps, 2 CTA/SM.
// QK = (Qh + Ql) · Khat; PV plain tf32. Key tiles of 64.
// smem per CTA: Kh dbuf | Vt dbuf | P(=Q stage)  = 87,040 B.
// ---------------------------------------------------------------------------
#define FSTR 68
#define KV_TILE (64 * FSTR)
#define FLASH_SMEM_FLOATS (4 * KV_TILE + 64 * FSTR)
#define FLASH_SMEM_BYTES (FLASH_SMEM_FLOATS * 4)   // 87040

__global__ __launch_bounds__(128, 2)
void flash_attn_tc(const float* __restrict__ Qp, const float* __restrict__ Kh_g,
                   const float* __restrict__ VT_g, const float* __restrict__ mask,
                   float* __restrict__ Out)
{
    extern __shared__ float fsm[];
    float* Khb  = fsm;                       // 2 * KV_TILE
    float* Vtb  = Khb + 2 * KV_TILE;         // 2 * KV_TILE (rows=d, cols=key)
    float* Pbuf = Vtb + 2 * KV_TILE;         // 64 * FSTR (Q stage, then P)

    const uint32_t sKh = cvta_smem(Khb);
    const uint32_t sVt = cvta_smem(Vtb);
    const uint32_t sP  = cvta_smem(Pbuf);

    const int tid  = threadIdx.x;
    const int lane = tid & 31;
    const int wid  = tid >> 5;          // 0..3
    const int wm   = wid * 16;          // warp's first query row in 64-row tile
    const int q0   = blockIdx.x * 64;
    const int h    = blockIdx.y;
    const int b    = blockIdx.z;

    const float* Qg  = Qp   + ((size_t)b * Ss + q0) * Dd + h * DP;
    const float* Khg = Kh_g + ((size_t)b * Ss) * Dd + h * DP;
    const float* VTg = VT_g + ((size_t)b * Hh + h) * DP * Ss;  // [d][s]
    const float* Mg  = mask + (((size_t)b * Hh + h) * Ss + q0) * Ss;

    const int g       = lane >> 3;
    const int glr     = lane & 7;
    const int row_add = ((g >> 1) << 3) + glr;
    const int koff    = (g & 1) << 2;

    const int rq = lane >> 2;
    const int cq = lane & 3;

    // loader coords: 64 rows x 16 float4-chunks per array, 128 threads -> 8 each
    const int lrow = tid >> 4;          // 0..7 (+8*i)
    const int lcol = tid & 15;

    // ---- prefetch tile 0 ----
    {
#pragma unroll
        for (int i = 0; i < 8; i++) {
            int row = lrow + 8 * i;
            uint32_t so = (uint32_t)((row * FSTR + lcol * 4) * 4);
            cp_async16(sKh + so, Khg + (size_t)row * Dd + lcol * 4);
            cp_async16(sVt + so, VTg + (size_t)row * Ss + lcol * 4);
        }
        cp_commit();
    }

    // ---- stage Q into Pbuf, extract hi/lo fragments ----
#pragma unroll
    for (int i = 0; i < 8; i++) {
        int id = tid + 128 * i;              // 0..1023
        int row = id >> 4, col = id & 15;    // 64 rows x 16 chunks
        float4 v = *(const float4*)(Qg + (size_t)row * Dd + col * 4);
        *(float4*)&Pbuf[row * FSTR + col * 4] = v;
    }
    __syncthreads();

    uint32_t Qh[8][4], Ql[8][4];
    {
        const uint32_t base = sP + (uint32_t)(((wm + row_add) * FSTR + koff) * 4);
#pragma unroll
        for (int ks = 0; ks < 8; ks++) {
            uint32_t r0, r1, r2, r3;
            ldsm_x4(r0, r1, r2, r3, base + (uint32_t)(ks * 32));
            Qh[ks][0] = f2tf32(r0); Ql[ks][0] = tf32_lo(r0, Qh[ks][0]);
            Qh[ks][1] = f2tf32(r2); Ql[ks][1] = tf32_lo(r2, Qh[ks][1]);
            Qh[ks][2] = f2tf32(r1); Ql[ks][2] = tf32_lo(r1, Qh[ks][2]);
            Qh[ks][3] = f2tf32(r3); Ql[ks][3] = tf32_lo(r3, Qh[ks][3]);
        }
    }

    float O[8][4];
#pragma unroll
    for (int nt = 0; nt < 8; nt++)
#pragma unroll
        for (int c = 0; c < 4; c++) O[nt][c] = 0.f;
    float m0r = NEG_INF, m1r = NEG_INF, l0r = 0.f, l1r = 0.f;

    for (int kt = 0; kt < 32; kt++) {
        cp_wait0();
        __syncthreads();   // tile kt visible; all warps done with buffer (kt+1)&1

        // prefetch tile kt+1
        if (kt + 1 < 32) {
            const uint32_t bo = (uint32_t)(((kt + 1) & 1) * KV_TILE * 4);
            const float* khg = Khg + (size_t)(kt + 1) * 64 * Dd;
            const float* vtg = VTg + (size_t)(kt + 1) * 64;
#pragma unroll
            for (int i = 0; i < 8; i++) {
                int row = lrow + 8 * i;
                uint32_t so = (uint32_t)((row * FSTR + lcol * 4) * 4);
                cp_async16(sKh + bo + so, khg + (size_t)row * Dd + lcol * 4);
                cp_async16(sVt + bo + so, vtg + (size_t)row * Ss + lcol * 4);
            }
            cp_commit();
        }

        // mask fragments (overlap DRAM with QK mma)
        float2 mk0[8], mk1[8];
        {
            const float* mr0 = Mg + (size_t)(wm + rq) * Ss + kt * 64 + 2 * cq;
            const float* mr1 = mr0 + 8 * Ss;
#pragma unroll
            for (int nt = 0; nt < 8; nt++) {
                mk0[nt] = *(const float2*)(mr0 + nt * 8);
                mk1[nt] = *(const float2*)(mr1 + nt * 8);
            }
        }

        // ---- S = (Qh + Ql) · Khat ----
        float S[8][4];
#pragma unroll
        for (int nt = 0; nt < 8; nt++)
#pragma unroll
            for (int c = 0; c < 4; c++) S[nt][c] = 0.f;

        const uint32_t khb = sKh + (uint32_t)((kt & 1) * KV_TILE * 4)
                           + (uint32_t)((row_add * FSTR + koff) * 4);
#pragma unroll
        for (int ks = 0; ks < 8; ks++) {
#pragma unroll
            for (int p = 0; p < 4; p++) {
                const uint32_t off = (uint32_t)((p * 16 * FSTR) * 4 + ks * 32);
                uint32_t h0, h1, h2, h3;
                ldsm_x4(h0, h1, h2, h3, khb + off);
                const int n0 = 2 * p, n1 = 2 * p + 1;
                mma_tf32(S[n0][0], S[n0][1], S[n0][2], S[n0][3],
                         Qh[ks][0], Qh[ks][1], Qh[ks][2], Qh[ks][3], h0, h1);
                mma_tf32(S[n1][0], S[n1][1], S[n1][2], S[n1][3],
                         Qh[ks][0], Qh[ks][1], Qh[ks][2], Qh[ks][3], h2, h3);
                mma_tf32(S[n0][0], S[n0][1], S[n0][2], S[n0][3],
                         Ql[ks][0], Ql[ks][1], Ql[ks][2], Ql[ks][3], h0, h1);
                mma_tf32(S[n1][0], S[n1][1], S[n1][2], S[n1][3],
                         Ql[ks][0], Ql[ks][1], Ql[ks][2], Ql[ks][3], h2, h3);
            }
        }

        // ---- scale + mask + online softmax ----
        float rm0 = NEG_INF, rm1 = NEG_INF;
#pragma unroll
        for (int nt = 0; nt < 8; nt++) {
            S[nt][0] = S[nt][0] * 0.125f + mk0[nt].x * (-1e9f);
            S[nt][1] = S[nt][1] * 0.125f + mk0[nt].y * (-1e9f);
            S[nt][2] = S[nt][2] * 0.125f + mk1[nt].x * (-1e9f);
            S[nt][3] = S[nt][3] * 0.125f + mk1[nt].y * (-1e9f);
            rm0 = fmaxf(rm0, fmaxf(S[nt][0], S[nt][1]));
            rm1 = fmaxf(rm1, fmaxf(S[nt][2], S[nt][3]));
        }
        rm0 = fmaxf(rm0, __shfl_xor_sync(0xffffffffu, rm0, 1));
        rm0 = fmaxf(rm0, __shfl_xor_sync(0xffffffffu, rm0, 2));
        rm1 = fmaxf(rm1, __shfl_xor_sync(0xffffffffu, rm1, 1));
        rm1 = fmaxf(rm1, __shfl_xor_sync(0xffffffffu, rm1, 2));

        const float nm0 = fmaxf(m0r, rm0);
        const float nm1 = fmaxf(m1r, rm1);
        const float sc0 = __expf(m0r - nm0);
        const float sc1 = __expf(m1r - nm1);
        m0r = nm0; m1r = nm1;

        float rs0 = 0.f, rs1 = 0.f;
#pragma unroll
        for (int nt = 0; nt < 8; nt++) {
            S[nt][0] = __expf(S[nt][0] - nm0);
            S[nt][1] = __expf(S[nt][1] - nm0);
            S[nt][2] = __expf(S[nt][2] - nm1);
            S[nt][3] = __expf(S[nt][3] - nm1);
            rs0 += S[nt][0] + S[nt][1];
            rs1 += S[nt][2] + S[nt][3];
        }
        rs0 += __shfl_xor_sync(0xffffffffu, rs0, 1);
        rs0 += __shfl_xor_sync(0xffffffffu, rs0, 2);
        rs1 += __shfl_xor_sync(0xffffffffu, rs1, 1);
        rs1 += __shfl_xor_sync(0xffffffffu, rs1, 2);
        l0r = l0r * sc0 + rs0;
        l1r = l1r * sc1 + rs1;

#pragma unroll
        for (int nt = 0; nt < 8; nt++) {
            O[nt][0] *= sc0; O[nt][1] *= sc0;
            O[nt][2] *= sc1; O[nt][3] *= sc1;
        }

        // ---- store P (warp-private rows) ----
        {
            float* p0 = Pbuf + (wm + rq) * FSTR + 2 * cq;
            float* p1 = p0 + 8 * FSTR;
#pragma unroll
            for (int nt = 0; nt < 8; nt++) {
                *(float2*)(p0 + nt * 8) = make_float2(S[nt][0], S[nt][1]);
                *(float2*)(p1 + nt * 8) = make_float2(S[nt][2], S[nt][3]);
            }
        }
        __syncwarp();

        // ---- O += P V ----
        const uint32_t pb = sP + (uint32_t)(((wm + row_add) * FSTR + koff) * 4);
        const uint32_t vb = sVt + (uint32_t)((kt & 1) * KV_TILE * 4)
                          + (uint32_t)((row_add * FSTR + koff) * 4);
#pragma unroll
        for (int ks = 0; ks < 8; ks++) {
            uint32_t pr0, pr1, pr2, pr3;
            ldsm_x4(pr0, pr1, pr2, pr3, pb + (uint32_t)(ks * 32));
            uint32_t a0 = f2tf32(pr0), a1 = f2tf32(pr2), a2 = f2tf32(pr1), a3 = f2tf32(pr3);
#pragma unroll
            for (int p = 0; p < 4; p++) {
                uint32_t v0, v1, v2, v3;
                ldsm_x4(v0, v1, v2, v3, vb + (uint32_t)((p * 16 * FSTR) * 4 + ks * 32));
                const int n0 = 2 * p, n1 = 2 * p + 1;
                mma_tf32(O[n0][0], O[n0][1], O[n0][2], O[n0][3], a0, a1, a2, a3, v0, v1);
                mma_tf32(O[n1][0], O[n1][1], O[n1][2], O[n1][3], a0, a1, a2, a3, v2, v3);
            }
        }
    }

    // ---- epilogue ----
    const float inv0 = 1.f / l0r;
    const float inv1 = 1.f / l1r;
    float* o0 = Out + ((size_t)b * Ss + q0 + wm + rq) * Dd + h * DP + 2 * cq;
    float* o1 = o0 + (size_t)8 * Dd;
#pragma unroll
    for (int nt = 0; nt < 8; nt++) {
        *(float2*)(o0 + nt * 8) = make_float2(O[nt][0] * inv0, O[nt][1] * inv0);
        *(float2*)(o1 + nt * 8) = make_float2(O[nt][2] * inv1, O[nt][3] * inv1);
    }
}

// ---------------------------------------------------------------------------
extern "C" void kernel_launch(void* const* d_in, const int* in_sizes, int n_in,
                              void* d_out, int out_size)
{
    const float* q    = (const float*)d_in[0];
    const float* k    = (const float*)d_in[1];
    const float* v    = (const float*)d_in[2];
    const float* mask = (const float*)d_in[3];
    const float* wq_w = (const float*)d_in[4];
    const float* wq_b = (const float*)d_in[5];
    const float* wk_w = (const float*)d_in[6];
    const float* wk_b = (const float*)d_in[7];
    const float* wv_w = (const float*)d_in[8];
    const float* wv_b = (const float*)d_in[9];
    const float* fc_w = (const float*)d_in[10];
    const float* fc_b = (const float*)d_in[11];

    float *pQ, *pKh, *pVT, *pScr;
    cudaGetSymbolAddress((void**)&pQ, g_Qp);
    cudaGetSymbolAddress((void**)&pKh, g_Kh);
    cudaGetSymbolAddress((void**)&pVT, g_VT);
    cudaGetSymbolAddress((void**)&pScr, g_attn_scratch);

    float* out_main = (float*)d_out;
    const size_t OUT1 = (size_t)MM * Dd;
    float* attn_out = ((size_t)out_size >= 2 * OUT1) ? (out_main + OUT1) : pScr;

    static bool attr_set = false;
    if (!attr_set) {
        cudaFuncSetAttribute(flash_attn_tc, cudaFuncAttributeMaxDynamicSharedMemorySize,
                             FLASH_SMEM_BYTES);
        attr_set = true;
    }

    qkv_gemm<<<dim3(Dd / GBN, MM / GBM, 3), 256>>>(
        q, k, v, wq_w, wk_w, wv_w, wq_b, wk_b, wv_b, pQ, pKh, pVT);

    flash_attn_tc<<<dim3(Ss / 64, Hh, Bb), 128, FLASH_SMEM_BYTES>>>(
        pQ, pKh, pVT, mask, attn_out);

    fc_gemm<<<dim3(Dd / GBN, MM / GBM), 256>>>(attn_out, fc_w, fc_b, out_main);
}

// round 10
// speedup vs baseline: 3.1221x; 1.0181x over previous
#include <cuda_runtime.h>
#include <cstdint>

// ---------------------------------------------------------------------------
// MultiHeadAttn: B=2, S=2048, D=1024, H=16, depth=64
// Stage 0: round_tf32 pre-pass: q,k,v + all weights -> tf32-rounded copies.
// Stage 1: merged QKV projections, cvt-free mainloop (grid.z selects output
//          epilogue): z=0 Q fp32, z=1 K tf32-rounded, z=2 V^T tf32-rounded.
// Stage 2: flash attention: 64-query CTAs, 4 warps, 2 CTA/SM.
//          QK = (Qh+Ql)·Khat (2-term split), PV plain tf32.
//          Epilogue writes attn fp32 + tf32-rounded fc-input copy.
// Stage 3: fc output projection, cvt-free mainloop.
// ---------------------------------------------------------------------------

#define NEG_INF (-3.402823466e38f)

static constexpr int Bb = 2;
static constexpr int Ss = 2048;
static constexpr int Dd = 1024;
static constexpr int Hh = 16;
static constexpr int DP = 64;
static constexpr int MM = Bb * Ss;  // 4096

__device__ float g_Qp[(size_t)MM * Dd];
__device__ float g_Kh[(size_t)MM * Dd];
__device__ float g_VT[(size_t)MM * Dd];   // [B, H, DP, Ss]
__device__ float g_attn_scratch[(size_t)MM * Dd];
__device__ float g_FCin[(size_t)MM * Dd];   // tf32-rounded attn (fc input)
// tf32-rounded GEMM operands
__device__ float g_qr[(size_t)MM * Dd];
__device__ float g_kr[(size_t)MM * Dd];
__device__ float g_vr[(size_t)MM * Dd];
__device__ float g_wqr[(size_t)Dd * Dd];
__device__ float g_wkr[(size_t)Dd * Dd];
__device__ float g_wvr[(size_t)Dd * Dd];
__device__ float g_wfr[(size_t)Dd * Dd];

// ---------------------------------------------------------------------------
// PTX helpers
// ---------------------------------------------------------------------------
__device__ __forceinline__ uint32_t cvta_smem(const void* p) {
    return (uint32_t)__cvta_generic_to_shared(p);
}
__device__ __forceinline__ void cp_async16(uint32_t dst, const void* src) {
    asm volatile("cp.async.cg.shared.global [%0], [%1], 16;\n" :: "r"(dst), "l"(src));
}
__device__ __forceinline__ void cp_commit() {
    asm volatile("cp.async.commit_group;\n");
}
__device__ __forceinline__ void cp_wait0() {
    asm volatile("cp.async.wait_group 0;\n");
}
__device__ __forceinline__ void ldsm_x4(uint32_t& r0, uint32_t& r1, uint32_t& r2, uint32_t& r3,
                                        uint32_t addr) {
    asm volatile("ldmatrix.sync.aligned.m8n8.x4.shared.b16 {%0,%1,%2,%3}, [%4];\n"
                 : "=r"(r0), "=r"(r1), "=r"(r2), "=r"(r3) : "r"(addr));
}
__device__ __forceinline__ uint32_t f2tf32(uint32_t bits) {
    float f = __uint_as_float(bits);
    uint32_t r;
    asm volatile("cvt.rna.tf32.f32 %0, %1;\n" : "=r"(r) : "f"(f));
    return r;
}
__device__ __forceinline__ float tf32_round(float x) {
    uint32_t r;
    asm volatile("cvt.rna.tf32.f32 %0, %1;\n" : "=r"(r) : "f"(x));
    return __uint_as_float(r);
}
__device__ __forceinline__ uint32_t tf32_lo(uint32_t bits, uint32_t hi) {
    float d = __uint_as_float(bits) - __uint_as_float(hi);
    uint32_t r;
    asm volatile("cvt.rna.tf32.f32 %0, %1;\n" : "=r"(r) : "f"(d));
    return r;
}
__device__ __forceinline__ void mma_tf32(float& d0, float& d1, float& d2, float& d3,
                                         uint32_t a0, uint32_t a1, uint32_t a2, uint32_t a3,
                                         uint32_t b0, uint32_t b1) {
    asm volatile(
        "mma.sync.aligned.m16n8k8.row.col.f32.tf32.tf32.f32 "
        "{%0,%1,%2,%3}, {%4,%5,%6,%7}, {%8,%9}, {%0,%1,%2,%3};\n"
        : "+f"(d0), "+f"(d1), "+f"(d2), "+f"(d3)
        : "r"(a0), "r"(a1), "r"(a2), "r"(a3), "r"(b0), "r"(b1));
}

// ---------------------------------------------------------------------------
// Stage 0: streaming tf32 rounding pass (float4 vectorized).
// ---------------------------------------------------------------------------
__global__ void round_tf32_kernel(const float4* __restrict__ src,
                                  float4* __restrict__ dst, int n4)
{
    int i = blockIdx.x * blockDim.x + threadIdx.x;
    if (i < n4) {
        float4 v = src[i];
        v.x = tf32_round(v.x);
        v.y = tf32_round(v.y);
        v.z = tf32_round(v.z);
        v.w = tf32_round(v.w);
        dst[i] = v;
    }
}

// ---------------------------------------------------------------------------
// GEMM mainloop core: 128x128 tile, BK=16, 2-stage. CVT=false -> raw bits.
// ---------------------------------------------------------------------------
#define GBM 128
#define GBN 128
#define GBK 16
#define GSTR 20
#define GTILE_BYTES (GBM * GSTR * 4)

struct GemmCtx {
    float acc[4][4][4];
};

template <bool CVT>
__device__ __forceinline__ void gemm_mainloop(
    const float* __restrict__ A, const float* __restrict__ W,
    int m0, int n0, int K, float (*As)[GBM * GSTR], float (*Bs)[GBN * GSTR],
    GemmCtx& ctx)
{
    const int tid  = threadIdx.x;
    const int lane = tid & 31;
    const int wid  = tid >> 5;
    const int wm   = (wid & 1) * 64;
    const int wn   = (wid >> 1) * 32;

    const uint32_t sA = cvta_smem(As);
    const uint32_t sB = cvta_smem(Bs);

    const int lr0 = tid >> 2;
    const int lg  = (tid & 3) * 4;
    const float* Ap0 = A + (size_t)(m0 + lr0) * K + lg;
    const float* Ap1 = A + (size_t)(m0 + lr0 + 64) * K + lg;
    const float* Wp0 = W + (size_t)(n0 + lr0) * K + lg;
    const float* Wp1 = W + (size_t)(n0 + lr0 + 64) * K + lg;
    const uint32_t dA0 = sA + (uint32_t)((lr0 * GSTR + lg) * 4);
    const uint32_t dA1 = sA + (uint32_t)(((lr0 + 64) * GSTR + lg) * 4);
    const uint32_t dB0 = sB + (uint32_t)((lr0 * GSTR + lg) * 4);
    const uint32_t dB1 = sB + (uint32_t)(((lr0 + 64) * GSTR + lg) * 4);

    const int g       = lane >> 3;
    const int glr     = lane & 7;
    const int row_add = ((g >> 1) << 3) + glr;
    const int koff    = (g & 1) << 2;
    const uint32_t aBase = sA + (uint32_t)(((wm + row_add) * GSTR + koff) * 4);
    const uint32_t bBase = sB + (uint32_t)(((wn + row_add) * GSTR + koff) * 4);

#pragma unroll
    for (int i = 0; i < 4; i++)
#pragma unroll
        for (int j = 0; j < 4; j++)
#pragma unroll
            for (int c = 0; c < 4; c++) ctx.acc[i][j][c] = 0.f;

    const int NSTAGE = K / GBK;

    cp_async16(dA0, Ap0); cp_async16(dA1, Ap1);
    cp_async16(dB0, Wp0); cp_async16(dB1, Wp1);
    cp_commit();

    for (int kt = 0; kt < NSTAGE; kt++) {
        cp_wait0();
        __syncthreads();

        if (kt + 1 < NSTAGE) {
            const int k0 = (kt + 1) * GBK;
            const uint32_t bo = (uint32_t)(((kt + 1) & 1) * GTILE_BYTES);
            cp_async16(dA0 + bo, Ap0 + k0);
            cp_async16(dA1 + bo, Ap1 + k0);
            cp_async16(dB0 + bo, Wp0 + k0);
            cp_async16(dB1 + bo, Wp1 + k0);
            cp_commit();
        }

        const uint32_t bo = (uint32_t)((kt & 1) * GTILE_BYTES);
#pragma unroll
        for (int ks = 0; ks < 2; ks++) {
            const uint32_t ao = aBase + bo + (uint32_t)(ks * 32);
            const uint32_t bb = bBase + bo + (uint32_t)(ks * 32);

            uint32_t af[4][4], bf[4][2];
#pragma unroll
            for (int mt = 0; mt < 4; mt++) {
                uint32_t r0, r1, r2, r3;
                ldsm_x4(r0, r1, r2, r3, ao + (uint32_t)(mt * 16 * GSTR * 4));
                af[mt][0] = CVT ? f2tf32(r0) : r0;
                af[mt][1] = CVT ? f2tf32(r2) : r2;
                af[mt][2] = CVT ? f2tf32(r1) : r1;
                af[mt][3] = CVT ? f2tf32(r3) : r3;
            }
#pragma unroll
            for (int p = 0; p < 2; p++) {
                uint32_t r0, r1, r2, r3;
                ldsm_x4(r0, r1, r2, r3, bb + (uint32_t)(p * 16 * GSTR * 4));
                bf[2 * p][0]     = CVT ? f2tf32(r0) : r0;
                bf[2 * p][1]     = CVT ? f2tf32(r1) : r1;
                bf[2 * p + 1][0] = CVT ? f2tf32(r2) : r2;
                bf[2 * p + 1][1] = CVT ? f2tf32(r3) : r3;
            }
#pragma unroll
            for (int mt = 0; mt < 4; mt++)
#pragma unroll
                for (int nt = 0; nt < 4; nt++)
                    mma_tf32(ctx.acc[mt][nt][0], ctx.acc[mt][nt][1],
                             ctx.acc[mt][nt][2], ctx.acc[mt][nt][3],
                             af[mt][0], af[mt][1], af[mt][2], af[mt][3],
                             bf[nt][0], bf[nt][1]);
        }
        __syncthreads();
    }
}

// ---------------------------------------------------------------------------
// Merged QKV projection (pre-rounded inputs). grid.z: 0=Q, 1=K, 2=V^T.
// ---------------------------------------------------------------------------
__global__ __launch_bounds__(256, 2)
void qkv_gemm(const float* __restrict__ q, const float* __restrict__ k,
              const float* __restrict__ v,
              const float* __restrict__ wq, const float* __restrict__ wk,
              const float* __restrict__ wv,
              const float* __restrict__ bq, const float* __restrict__ bk,
              const float* __restrict__ bv,
              float* __restrict__ Qout, float* __restrict__ Kh,
              float* __restrict__ VT)
{
    __shared__ __align__(16) float As[2][GBM * GSTR];
    __shared__ __align__(16) float Bs[2][GBN * GSTR];

    const int z  = blockIdx.z;
    const int m0 = blockIdx.y * GBM;
    const int n0 = blockIdx.x * GBN;

    const float* A    = (z == 0) ? q  : (z == 1) ? k  : v;
    const float* W    = (z == 0) ? wq : (z == 1) ? wk : wv;
    const float* bias = (z == 0) ? bq : (z == 1) ? bk : bv;

    GemmCtx ctx;
    gemm_mainloop<false>(A, W, m0, n0, Dd, As, Bs, ctx);

    const int lane = threadIdx.x & 31;
    const int wid  = threadIdx.x >> 5;
    const int wm   = (wid & 1) * 64;
    const int wn   = (wid >> 1) * 32;

#pragma unroll
    for (int mt = 0; mt < 4; mt++) {
        const int row = m0 + wm + mt * 16 + (lane >> 2);
#pragma unroll
        for (int nt = 0; nt < 4; nt++) {
            const int col = n0 + wn + nt * 8 + (lane & 3) * 2;
            const float b0 = bias[col], b1 = bias[col + 1];
            float v00 = ctx.acc[mt][nt][0] + b0, v01 = ctx.acc[mt][nt][1] + b1;
            float v10 = ctx.acc[mt][nt][2] + b0, v11 = ctx.acc[mt][nt][3] + b1;
            if (z == 0) {
                *(float2*)&Qout[(size_t)row * Dd + col]       = make_float2(v00, v01);
                *(float2*)&Qout[(size_t)(row + 8) * Dd + col] = make_float2(v10, v11);
            } else if (z == 1) {
                *(float2*)&Kh[(size_t)row * Dd + col] =
                    make_float2(tf32_round(v00), tf32_round(v01));
                *(float2*)&Kh[(size_t)(row + 8) * Dd + col] =
                    make_float2(tf32_round(v10), tf32_round(v11));
            } else {
                // V^T[b, h, d, s]
                const int b_  = row >> 11, s0 = row & 2047;
                const int h_  = col >> 6,  d0 = col & 63;
                float* base = VT + (((size_t)b_ * Hh + h_) * DP + d0) * Ss + s0;
                base[0]      = tf32_round(v00);
                base[Ss]     = tf32_round(v01);
                base[8]      = tf32_round(v10);
                base[Ss + 8] = tf32_round(v11);
            }
        }
    }
}

// fc output projection (pre-rounded inputs, fp32 epilogue with bias)
__global__ __launch_bounds__(256, 2)
void fc_gemm(const float* __restrict__ A, const float* __restrict__ W,
             const float* __restrict__ bias, float* __restrict__ C)
{
    __shared__ __align__(16) float As[2][GBM * GSTR];
    __shared__ __align__(16) float Bs[2][GBN * GSTR];

    const int m0 = blockIdx.y * GBM;
    const int n0 = blockIdx.x * GBN;

    GemmCtx ctx;
    gemm_mainloop<false>(A, W, m0, n0, Dd, As, Bs, ctx);

    const int lane = threadIdx.x & 31;
    const int wid  = threadIdx.x >> 5;
    const int wm   = (wid & 1) * 64;
    const int wn   = (wid >> 1) * 32;

#pragma unroll
    for (int mt = 0; mt < 4; mt++) {
        const int row = m0 + wm + mt * 16 + (lane >> 2);
#pragma unroll
        for (int nt = 0; nt < 4; nt++) {
            const int col = n0 + wn + nt * 8 + (lane & 3) * 2;
            const float b0 = bias[col], b1 = bias[col + 1];
            *(float2*)&C[(size_t)row * Dd + col] =
                make_float2(ctx.acc[mt][nt][0] + b0, ctx.acc[mt][nt][1] + b1);
            *(float2*)&C[(size_t)(row + 8) * Dd + col] =
                make_float2(ctx.acc[mt][nt][2] + b0, ctx.acc[mt][nt][3] + b1);
        }
    }
}

// ---------------------------------------------------------------------------
// Tensor-core flash attention. 64-query CTA, 4 warps, 2 CTA/SM.
// QK = (Qh + Ql) · Khat; PV plain tf32. Key tiles of 64.
// Epilogue: attn fp32 to Out, tf32-rounded copy to FCin.
// ---------------------------------------------------------------------------
#define FSTR 68
#define KV_TILE (64 * FSTR)
#define FLASH_SMEM_FLOATS (4 * KV_TILE + 64 * FSTR)
#define FLASH_SMEM_BYTES (FLASH_SMEM_FLOATS * 4)   // 87040

__global__ __launch_bounds__(128, 2)
void flash_attn_tc(const float* __restrict__ Qp, const float* __restrict__ Kh_g,
                   const float* __restrict__ VT_g, const float* __restrict__ mask,
                   float* __restrict__ Out, float* __restrict__ FCin)
{
    extern __shared__ float fsm[];
    float* Khb  = fsm;                       // 2 * KV_TILE
    float* Vtb  = Khb + 2 * KV_TILE;         // 2 * KV_TILE (rows=d, cols=key)
    float* Pbuf = Vtb + 2 * KV_TILE;         // 64 * FSTR (Q stage, then P)

    const uint32_t sKh = cvta_smem(Khb);
    const uint32_t sVt = cvta_smem(Vtb);
    const uint32_t sP  = cvta_smem(Pbuf);

    const int tid  = threadIdx.x;
    const int lane = tid & 31;
    const int wid  = tid >> 5;          // 0..3
    const int wm   = wid * 16;
    const int q0   = blockIdx.x * 64;
    const int h    = blockIdx.y;
    const int b    = blockIdx.z;

    const float* Qg  = Qp   + ((size_t)b * Ss + q0) * Dd + h * DP;
    const float* Khg = Kh_g + ((size_t)b * Ss) * Dd + h * DP;
    const float* VTg = VT_g + ((size_t)b * Hh + h) * DP * Ss;  // [d][s]
    const float* Mg  = mask + (((size_t)b * Hh + h) * Ss + q0) * Ss;

    const int g       = lane >> 3;
    const int glr     = lane & 7;
    const int row_add = ((g >> 1) << 3) + glr;
    const int koff    = (g & 1) << 2;

    const int rq = lane >> 2;
    const int cq = lane & 3;

    const int lrow = tid >> 4;          // 0..7 (+8*i)
    const int lcol = tid & 15;

    // ---- prefetch tile 0 ----
    {
#pragma unroll
        for (int i = 0; i < 8; i++) {
            int row = lrow + 8 * i;
            uint32_t so = (uint32_t)((row * FSTR + lcol * 4) * 4);
            cp_async16(sKh + so, Khg + (size_t)row * Dd + lcol * 4);
            cp_async16(sVt + so, VTg + (size_t)row * Ss + lcol * 4);
        }
        cp_commit();
    }

    // ---- stage Q into Pbuf, extract hi/lo fragments ----
#pragma unroll
    for (int i = 0; i < 8; i++) {
        int id = tid + 128 * i;              // 0..1023
        int row = id >> 4, col = id & 15;    // 64 rows x 16 chunks
        float4 v = *(const float4*)(Qg + (size_t)row * Dd + col * 4);
        *(float4*)&Pbuf[row * FSTR + col * 4] = v;
    }
    __syncthreads();

    uint32_t Qh[8][4], Ql[8][4];
    {
        const uint32_t base = sP + (uint32_t)(((wm + row_add) * FSTR + koff) * 4);
#pragma unroll
        for (int ks = 0; ks < 8; ks++) {
            uint32_t r0, r1, r2, r3;
            ldsm_x4(r0, r1, r2, r3, base + (uint32_t)(ks * 32));
            Qh[ks][0] = f2tf32(r0); Ql[ks][0] = tf32_lo(r0, Qh[ks][0]);
            Qh[ks][1] = f2tf32(r2); Ql[ks][1] = tf32_lo(r2, Qh[ks][1]);
            Qh[ks][2] = f2tf32(r1); Ql[ks][2] = tf32_lo(r1, Qh[ks][2]);
            Qh[ks][3] = f2tf32(r3); Ql[ks][3] = tf32_lo(r3, Qh[ks][3]);
        }
    }

    float O[8][4];
#pragma unroll
    for (int nt = 0; nt < 8; nt++)
#pragma unroll
        for (int c = 0; c < 4; c++) O[nt][c] = 0.f;
    float m0r = NEG_INF, m1r = NEG_INF, l0r = 0.f, l1r = 0.f;

    for (int kt = 0; kt < 32; kt++) {
        cp_wait0();
        __syncthreads();   // tile kt visible; all warps done with buffer (kt+1)&1

        // prefetch tile kt+1
        if (kt + 1 < 32) {
            const uint32_t bo = (uint32_t)(((kt + 1) & 1) * KV_TILE * 4);
            const float* khg = Khg + (size_t)(kt + 1) * 64 * Dd;
            const float* vtg = VTg + (size_t)(kt + 1) * 64;
#pragma unroll
            for (int i = 0; i < 8; i++) {
                int row = lrow + 8 * i;
                uint32_t so = (uint32_t)((row * FSTR + lcol * 4) * 4);
                cp_async16(sKh + bo + so, khg + (size_t)row * Dd + lcol * 4);
                cp_async16(sVt + bo + so, vtg + (size_t)row * Ss + lcol * 4);
            }
            cp_commit();
        }

        // mask fragments (overlap DRAM with QK mma)
        float2 mk0[8], mk1[8];
        {
            const float* mr0 = Mg + (size_t)(wm + rq) * Ss + kt * 64 + 2 * cq;
            const float* mr1 = mr0 + 8 * Ss;
#pragma unroll
            for (int nt = 0; nt < 8; nt++) {
                mk0[nt] = *(const float2*)(mr0 + nt * 8);
                mk1[nt] = *(const float2*)(mr1 + nt * 8);
            }
        }

        // ---- S = (Qh + Ql) · Khat ----
        float S[8][4];
#pragma unroll
        for (int nt = 0; nt < 8; nt++)
#pragma unroll
            for (int c = 0; c < 4; c++) S[nt][c] = 0.f;

        const uint32_t khb = sKh + (uint32_t)((kt & 1) * KV_TILE * 4)
                           + (uint32_t)((row_add * FSTR + koff) * 4);
#pragma unroll
        for (int ks = 0; ks < 8; ks++) {
#pragma unroll
            for (int p = 0; p < 4; p++) {
                const uint32_t off = (uint32_t)((p * 16 * FSTR) * 4 + ks * 32);
                uint32_t h0, h1, h2, h3;
                ldsm_x4(h0, h1, h2, h3, khb + off);
                const int n0 = 2 * p, n1 = 2 * p + 1;
                mma_tf32(S[n0][0], S[n0][1], S[n0][2], S[n0][3],
                         Qh[ks][0], Qh[ks][1], Qh[ks][2], Qh[ks][3], h0, h1);
                mma_tf32(S[n1][0], S[n1][1], S[n1][2], S[n1][3],
                         Qh[ks][0], Qh[ks][1], Qh[ks][2], Qh[ks][3], h2, h3);
                mma_tf32(S[n0][0], S[n0][1], S[n0][2], S[n0][3],
                         Ql[ks][0], Ql[ks][1], Ql[ks][2], Ql[ks][3], h0, h1);
                mma_tf32(S[n1][0], S[n1][1], S[n1][2], S[n1][3],
                         Ql[ks][0], Ql[ks][1], Ql[ks][2], Ql[ks][3], h2, h3);
            }
        }

        // ---- scale + mask + online softmax ----
        float rm0 = NEG_INF, rm1 = NEG_INF;
#pragma unroll
        for (int nt = 0; nt < 8; nt++) {
            S[nt][0] = S[nt][0] * 0.125f + mk0[nt].x * (-1e9f);
            S[nt][1] = S[nt][1] * 0.125f + mk0[nt].y * (-1e9f);
            S[nt][2] = S[nt][2] * 0.125f + mk1[nt].x * (-1e9f);
            S[nt][3] = S[nt][3] * 0.125f + mk1[nt].y * (-1e9f);
            rm0 = fmaxf(rm0, fmaxf(S[nt][0], S[nt][1]));
            rm1 = fmaxf(rm1, fmaxf(S[nt][2], S[nt][3]));
        }
        rm0 = fmaxf(rm0, __shfl_xor_sync(0xffffffffu, rm0, 1));
        rm0 = fmaxf(rm0, __shfl_xor_sync(0xffffffffu, rm0, 2));
        rm1 = fmaxf(rm1, __shfl_xor_sync(0xffffffffu, rm1, 1));
        rm1 = fmaxf(rm1, __shfl_xor_sync(0xffffffffu, rm1, 2));

        const float nm0 = fmaxf(m0r, rm0);
        const float nm1 = fmaxf(m1r, rm1);
        const float sc0 = __expf(m0r - nm0);
        const float sc1 = __expf(m1r - nm1);
        m0r = nm0; m1r = nm1;

        float rs0 = 0.f, rs1 = 0.f;
#pragma unroll
        for (int nt = 0; nt < 8; nt++) {
            S[nt][0] = __expf(S[nt][0] - nm0);
            S[nt][1] = __expf(S[nt][1] - nm0);
            S[nt][2] = __expf(S[nt][2] - nm1);
            S[nt][3] = __expf(S[nt][3] - nm1);
            rs0 += S[nt][0] + S[nt][1];
            rs1 += S[nt][2] + S[nt][3];
        }
        rs0 += __shfl_xor_sync(0xffffffffu, rs0, 1);
        rs0 += __shfl_xor_sync(0xffffffffu, rs0, 2);
        rs1 += __shfl_xor_sync(0xffffffffu, rs1, 1);
        rs1 += __shfl_xor_sync(0xffffffffu, rs1, 2);
        l0r = l0r * sc0 + rs0;
        l1r = l1r * sc1 + rs1;

#pragma unroll
        for (int nt = 0; nt < 8; nt++) {
            O[nt][0] *= sc0; O[nt][1] *= sc0;
            O[nt][2] *= sc1; O[nt][3] *= sc1;
        }

        // ---- store P (warp-private rows) ----
        {
            float* p0 = Pbuf + (wm + rq) * FSTR + 2 * cq;
            float* p1 = p0 + 8 * FSTR;
#pragma unroll
            for (int nt = 0; nt < 8; nt++) {
                *(float2*)(p0 + nt * 8) = make_float2(S[nt][0], S[nt][1]);
                *(float2*)(p1 + nt * 8) = make_float2(S[nt][2], S[nt][3]);
            }
        }
        __syncwarp();

        // ---- O += P V ----
        const uint32_t pb = sP + (uint32_t)(((wm + row_add) * FSTR + koff) * 4);
        const uint32_t vb = sVt + (uint32_t)((kt & 1) * KV_TILE * 4)
                          + (uint32_t)((row_add * FSTR + koff) * 4);
#pragma unroll
        for (int ks = 0; ks < 8; ks++) {
            uint32_t pr0, pr1, pr2, pr3;
            ldsm_x4(pr0, pr1, pr2, pr3, pb + (uint32_t)(ks * 32));
            uint32_t a0 = f2tf32(pr0), a1 = f2tf32(pr2), a2 = f2tf32(pr1), a3 = f2tf32(pr3);
#pragma unroll
            for (int p = 0; p < 4; p++) {
                uint32_t v0, v1, v2, v3;
                ldsm_x4(v0, v1, v2, v3, vb + (uint32_t)((p * 16 * FSTR) * 4 + ks * 32));
                const int n0 = 2 * p, n1 = 2 * p + 1;
                mma_tf32(O[n0][0], O[n0][1], O[n0][2], O[n0][3], a0, a1, a2, a3, v0, v1);
                mma_tf32(O[n1][0], O[n1][1], O[n1][2], O[n1][3], a0, a1, a2, a3, v2, v3);
            }
        }
    }

    // ---- epilogue: attn fp32 + tf32-rounded fc input ----
    const float inv0 = 1.f / l0r;
    const float inv1 = 1.f / l1r;
    const size_t base_off = ((size_t)b * Ss + q0 + wm + rq) * Dd + h * DP + 2 * cq;
    float* o0 = Out + base_off;
    float* o1 = o0 + (size_t)8 * Dd;
    float* f0 = FCin + base_off;
    float* f1 = f0 + (size_t)8 * Dd;
#pragma unroll
    for (int nt = 0; nt < 8; nt++) {
        float a = O[nt][0] * inv0, bb2 = O[nt][1] * inv0;
        float c = O[nt][2] * inv1, d = O[nt][3] * inv1;
        *(float2*)(o0 + nt * 8) = make_float2(a, bb2);
        *(float2*)(o1 + nt * 8) = make_float2(c, d);
        *(float2*)(f0 + nt * 8) = make_float2(tf32_round(a), tf32_round(bb2));
        *(float2*)(f1 + nt * 8) = make_float2(tf32_round(c), tf32_round(d));
    }
}

// ---------------------------------------------------------------------------
extern "C" void kernel_launch(void* const* d_in, const int* in_sizes, int n_in,
                              void* d_out, int out_size)
{
    const float* q    = (const float*)d_in[0];
    const float* k    = (const float*)d_in[1];
    const float* v    = (const float*)d_in[2];
    const float* mask = (const float*)d_in[3];
    const float* wq_w = (const float*)d_in[4];
    const float* wq_b = (const float*)d_in[5];
    const float* wk_w = (const float*)d_in[6];
    const float* wk_b = (const float*)d_in[7];
    const float* wv_w = (const float*)d_in[8];
    const float* wv_b = (const float*)d_in[9];
    const float* fc_w = (const float*)d_in[10];
    const float* fc_b = (const float*)d_in[11];

    float *pQ, *pKh, *pVT, *pScr, *pFC;
    float *pqr, *pkr, *pvr, *pwqr, *pwkr, *pwvr, *pwfr;
    cudaGetSymbolAddress((void**)&pQ, g_Qp);
    cudaGetSymbolAddress((void**)&pKh, g_Kh);
    cudaGetSymbolAddress((void**)&pVT, g_VT);
    cudaGetSymbolAddress((void**)&pScr, g_attn_scratch);
    cudaGetSymbolAddress((void**)&pFC, g_FCin);
    cudaGetSymbolAddress((void**)&pqr, g_qr);
    cudaGetSymbolAddress((void**)&pkr, g_kr);
    cudaGetSymbolAddress((void**)&pvr, g_vr);
    cudaGetSymbolAddress((void**)&pwqr, g_wqr);
    cudaGetSymbolAddress((void**)&pwkr, g_wkr);
    cudaGetSymbolAddress((void**)&pwvr, g_wvr);
    cudaGetSymbolAddress((void**)&pwfr, g_wfr);

    float* out_main = (float*)d_out;
    const size_t OUT1 = (size_t)MM * Dd;
    float* attn_out = ((size_t)out_size >= 2 * OUT1) ? (out_main + OUT1) : pScr;

    static bool attr_set = false;
    if (!attr_set) {
        cudaFuncSetAttribute(flash_attn_tc, cudaFuncAttributeMaxDynamicSharedMemorySize,
                             FLASH_SMEM_BYTES);
        attr_set = true;
    }

    // Stage 0: tf32 rounding pre-pass
    const int NA4 = (MM * Dd) / 4;       // 1M float4
    const int NW4 = (Dd * Dd) / 4;       // 256K float4
    round_tf32_kernel<<<(NA4 + 255) / 256, 256>>>((const float4*)q, (float4*)pqr, NA4);
    round_tf32_kernel<<<(NA4 + 255) / 256, 256>>>((const float4*)k, (float4*)pkr, NA4);
    round_tf32_kernel<<<(NA4 + 255) / 256, 256>>>((const float4*)v, (float4*)pvr, NA4);
    round_tf32_kernel<<<(NW4 + 255) / 256, 256>>>((const float4*)wq_w, (float4*)pwqr, NW4);
    round_tf32_kernel<<<(NW4 + 255) / 256, 256>>>((const float4*)wk_w, (float4*)pwkr, NW4);
    round_tf32_kernel<<<(NW4 + 255) / 256, 256>>>((const float4*)wv_w, (float4*)pwvr, NW4);
    round_tf32_kernel<<<(NW4 + 255) / 256, 256>>>((const float4*)fc_w, (float4*)pwfr, NW4);

    qkv_gemm<<<dim3(Dd / GBN, MM / GBM, 3), 256>>>(
        pqr, pkr, pvr, pwqr, pwkr, pwvr, wq_b, wk_b, wv_b, pQ, pKh, pVT);

    flash_attn_tc<<<dim3(Ss / 64, Hh, Bb), 128, FLASH_SMEM_BYTES>>>(
        pQ, pKh, pVT, mask, attn_out, pFC);

    fc_gemm<<<dim3(Dd / GBN, MM / GBM), 256>>>(pFC, pwfr, fc_b, out_main);
}

// round 11
// speedup vs baseline: 3.4436x; 1.1030x over previous
#include <cuda_runtime.h>
#include <cstdint>

// ---------------------------------------------------------------------------
// MultiHeadAttn: B=2, S=2048, D=1024, H=16, depth=64
// Stage 0: round_tf32 pre-pass: q,k,v + all weights -> tf32-rounded copies.
// Stage 1: merged QKV projections, cvt-free mainloop (grid.z selects output
//          epilogue): z=0 Q tf32-rounded, z=1 K tf32-rounded, z=2 V^T rounded.
// Stage 2: flash attention: 64-query CTAs, 4 warps, 2 CTA/SM.
//          QK = Qhat·Khat (plain tf32), PV plain tf32; fully cvt-free loops.
//          Epilogue writes attn fp32 + tf32-rounded fc-input copy.
// Stage 3: fc output projection, cvt-free mainloop.
// ---------------------------------------------------------------------------

#define NEG_INF (-3.402823466e38f)

static constexpr int Bb = 2;
static constexpr int Ss = 2048;
static constexpr int Dd = 1024;
static constexpr int Hh = 16;
static constexpr int DP = 64;
static constexpr int MM = Bb * Ss;  // 4096

__device__ float g_Qp[(size_t)MM * Dd];
__device__ float g_Kh[(size_t)MM * Dd];
__device__ float g_VT[(size_t)MM * Dd];   // [B, H, DP, Ss]
__device__ float g_attn_scratch[(size_t)MM * Dd];
__device__ float g_FCin[(size_t)MM * Dd];   // tf32-rounded attn (fc input)
// tf32-rounded GEMM operands
__device__ float g_qr[(size_t)MM * Dd];
__device__ float g_kr[(size_t)MM * Dd];
__device__ float g_vr[(size_t)MM * Dd];
__device__ float g_wqr[(size_t)Dd * Dd];
__device__ float g_wkr[(size_t)Dd * Dd];
__device__ float g_wvr[(size_t)Dd * Dd];
__device__ float g_wfr[(size_t)Dd * Dd];

// ---------------------------------------------------------------------------
// PTX helpers
// ---------------------------------------------------------------------------
__device__ __forceinline__ uint32_t cvta_smem(const void* p) {
    return (uint32_t)__cvta_generic_to_shared(p);
}
__device__ __forceinline__ void cp_async16(uint32_t dst, const void* src) {
    asm volatile("cp.async.cg.shared.global [%0], [%1], 16;\n" :: "r"(dst), "l"(src));
}
__device__ __forceinline__ void cp_commit() {
    asm volatile("cp.async.commit_group;\n");
}
__device__ __forceinline__ void cp_wait0() {
    asm volatile("cp.async.wait_group 0;\n");
}
__device__ __forceinline__ void ldsm_x4(uint32_t& r0, uint32_t& r1, uint32_t& r2, uint32_t& r3,
                                        uint32_t addr) {
    asm volatile("ldmatrix.sync.aligned.m8n8.x4.shared.b16 {%0,%1,%2,%3}, [%4];\n"
                 : "=r"(r0), "=r"(r1), "=r"(r2), "=r"(r3) : "r"(addr));
}
__device__ __forceinline__ uint32_t f2tf32(uint32_t bits) {
    float f = __uint_as_float(bits);
    uint32_t r;
    asm volatile("cvt.rna.tf32.f32 %0, %1;\n" : "=r"(r) : "f"(f));
    return r;
}
__device__ __forceinline__ float tf32_round(float x) {
    uint32_t r;
    asm volatile("cvt.rna.tf32.f32 %0, %1;\n" : "=r"(r) : "f"(x));
    return __uint_as_float(r);
}
__device__ __forceinline__ void mma_tf32(float& d0, float& d1, float& d2, float& d3,
                                         uint32_t a0, uint32_t a1, uint32_t a2, uint32_t a3,
                                         uint32_t b0, uint32_t b1) {
    asm volatile(
        "mma.sync.aligned.m16n8k8.row.col.f32.tf32.tf32.f32 "
        "{%0,%1,%2,%3}, {%4,%5,%6,%7}, {%8,%9}, {%0,%1,%2,%3};\n"
        : "+f"(d0), "+f"(d1), "+f"(d2), "+f"(d3)
        : "r"(a0), "r"(a1), "r"(a2), "r"(a3), "r"(b0), "r"(b1));
}

// ---------------------------------------------------------------------------
// Stage 0: streaming tf32 rounding pass (float4 vectorized).
// ---------------------------------------------------------------------------
__global__ void round_tf32_kernel(const float4* __restrict__ src,
                                  float4* __restrict__ dst, int n4)
{
    int i = blockIdx.x * blockDim.x + threadIdx.x;
    if (i < n4) {
        float4 v = src[i];
        v.x = tf32_round(v.x);
        v.y = tf32_round(v.y);
        v.z = tf32_round(v.z);
        v.w = tf32_round(v.w);
        dst[i] = v;
    }
}

// ---------------------------------------------------------------------------
// GEMM mainloop core: 128x128 tile, BK=16, 2-stage, cvt-free (inputs
// pre-rounded in gmem).
// ---------------------------------------------------------------------------
#define GBM 128
#define GBN 128
#define GBK 16
#define GSTR 20
#define GTILE_BYTES (GBM * GSTR * 4)

struct GemmCtx {
    float acc[4][4][4];
};

__device__ __forceinline__ void gemm_mainloop(
    const float* __restrict__ A, const float* __restrict__ W,
    int m0, int n0, int K, float (*As)[GBM * GSTR], float (*Bs)[GBN * GSTR],
    GemmCtx& ctx)
{
    const int tid  = threadIdx.x;
    const int lane = tid & 31;
    const int wid  = tid >> 5;
    const int wm   = (wid & 1) * 64;
    const int wn   = (wid >> 1) * 32;

    const uint32_t sA = cvta_smem(As);
    const uint32_t sB = cvta_smem(Bs);

    const int lr0 = tid >> 2;
    const int lg  = (tid & 3) * 4;
    const float* Ap0 = A + (size_t)(m0 + lr0) * K + lg;
    const float* Ap1 = A + (size_t)(m0 + lr0 + 64) * K + lg;
    const float* Wp0 = W + (size_t)(n0 + lr0) * K + lg;
    const float* Wp1 = W + (size_t)(n0 + lr0 + 64) * K + lg;
    const uint32_t dA0 = sA + (uint32_t)((lr0 * GSTR + lg) * 4);
    const uint32_t dA1 = sA + (uint32_t)(((lr0 + 64) * GSTR + lg) * 4);
    const uint32_t dB0 = sB + (uint32_t)((lr0 * GSTR + lg) * 4);
    const uint32_t dB1 = sB + (uint32_t)(((lr0 + 64) * GSTR + lg) * 4);

    const int g       = lane >> 3;
    const int glr     = lane & 7;
    const int row_add = ((g >> 1) << 3) + glr;
    const int koff    = (g & 1) << 2;
    const uint32_t aBase = sA + (uint32_t)(((wm + row_add) * GSTR + koff) * 4);
    const uint32_t bBase = sB + (uint32_t)(((wn + row_add) * GSTR + koff) * 4);

#pragma unroll
    for (int i = 0; i < 4; i++)
#pragma unroll
        for (int j = 0; j < 4; j++)
#pragma unroll
            for (int c = 0; c < 4; c++) ctx.acc[i][j][c] = 0.f;

    const int NSTAGE = K / GBK;

    cp_async16(dA0, Ap0); cp_async16(dA1, Ap1);
    cp_async16(dB0, Wp0); cp_async16(dB1, Wp1);
    cp_commit();

    for (int kt = 0; kt < NSTAGE; kt++) {
        cp_wait0();
        __syncthreads();

        if (kt + 1 < NSTAGE) {
            const int k0 = (kt + 1) * GBK;
            const uint32_t bo = (uint32_t)(((kt + 1) & 1) * GTILE_BYTES);
            cp_async16(dA0 + bo, Ap0 + k0);
            cp_async16(dA1 + bo, Ap1 + k0);
            cp_async16(dB0 + bo, Wp0 + k0);
            cp_async16(dB1 + bo, Wp1 + k0);
            cp_commit();
        }

        const uint32_t bo = (uint32_t)((kt & 1) * GTILE_BYTES);
#pragma unroll
        for (int ks = 0; ks < 2; ks++) {
            const uint32_t ao = aBase + bo + (uint32_t)(ks * 32);
            const uint32_t bb = bBase + bo + (uint32_t)(ks * 32);

            uint32_t af[4][4], bf[4][2];
#pragma unroll
            for (int mt = 0; mt < 4; mt++) {
                uint32_t r0, r1, r2, r3;
                ldsm_x4(r0, r1, r2, r3, ao + (uint32_t)(mt * 16 * GSTR * 4));
                af[mt][0] = r0;
                af[mt][1] = r2;
                af[mt][2] = r1;
                af[mt][3] = r3;
            }
#pragma unroll
            for (int p = 0; p < 2; p++) {
                uint32_t r0, r1, r2, r3;
                ldsm_x4(r0, r1, r2, r3, bb + (uint32_t)(p * 16 * GSTR * 4));
                bf[2 * p][0]     = r0;
                bf[2 * p][1]     = r1;
                bf[2 * p + 1][0] = r2;
                bf[2 * p + 1][1] = r3;
            }
#pragma unroll
            for (int mt = 0; mt < 4; mt++)
#pragma unroll
                for (int nt = 0; nt < 4; nt++)
                    mma_tf32(ctx.acc[mt][nt][0], ctx.acc[mt][nt][1],
                             ctx.acc[mt][nt][2], ctx.acc[mt][nt][3],
                             af[mt][0], af[mt][1], af[mt][2], af[mt][3],
                             bf[nt][0], bf[nt][1]);
        }
        __syncthreads();
    }
}

// ---------------------------------------------------------------------------
// Merged QKV projection (pre-rounded inputs). grid.z: 0=Q, 1=K, 2=V^T.
// ALL outputs tf32-rounded (flash consumes raw bits everywhere).
// ---------------------------------------------------------------------------
__global__ __launch_bounds__(256, 2)
void qkv_gemm(const float* __restrict__ q, const float* __restrict__ k,
              const float* __restrict__ v,
              const float* __restrict__ wq, const float* __restrict__ wk,
              const float* __restrict__ wv,
              const float* __restrict__ bq, const float* __restrict__ bk,
              const float* __restrict__ bv,
              float* __restrict__ Qout, float* __restrict__ Kh,
              float* __restrict__ VT)
{
    __shared__ __align__(16) float As[2][GBM * GSTR];
    __shared__ __align__(16) float Bs[2][GBN * GSTR];

    const int z  = blockIdx.z;
    const int m0 = blockIdx.y * GBM;
    const int n0 = blockIdx.x * GBN;

    const float* A    = (z == 0) ? q  : (z == 1) ? k  : v;
    const float* W    = (z == 0) ? wq : (z == 1) ? wk : wv;
    const float* bias = (z == 0) ? bq : (z == 1) ? bk : bv;

    GemmCtx ctx;
    gemm_mainloop(A, W, m0, n0, Dd, As, Bs, ctx);

    const int lane = threadIdx.x & 31;
    const int wid  = threadIdx.x >> 5;
    const int wm   = (wid & 1) * 64;
    const int wn   = (wid >> 1) * 32;

#pragma unroll
    for (int mt = 0; mt < 4; mt++) {
        const int row = m0 + wm + mt * 16 + (lane >> 2);
#pragma unroll
        for (int nt = 0; nt < 4; nt++) {
            const int col = n0 + wn + nt * 8 + (lane & 3) * 2;
            const float b0 = bias[col], b1 = bias[col + 1];
            float v00 = tf32_round(ctx.acc[mt][nt][0] + b0);
            float v01 = tf32_round(ctx.acc[mt][nt][1] + b1);
            float v10 = tf32_round(ctx.acc[mt][nt][2] + b0);
            float v11 = tf32_round(ctx.acc[mt][nt][3] + b1);
            if (z == 0) {
                *(float2*)&Qout[(size_t)row * Dd + col]       = make_float2(v00, v01);
                *(float2*)&Qout[(size_t)(row + 8) * Dd + col] = make_float2(v10, v11);
            } else if (z == 1) {
                *(float2*)&Kh[(size_t)row * Dd + col]       = make_float2(v00, v01);
                *(float2*)&Kh[(size_t)(row + 8) * Dd + col] = make_float2(v10, v11);
            } else {
                // V^T[b, h, d, s]
                const int b_  = row >> 11, s0 = row & 2047;
                const int h_  = col >> 6,  d0 = col & 63;
                float* base = VT + (((size_t)b_ * Hh + h_) * DP + d0) * Ss + s0;
                base[0]      = v00;
                base[Ss]     = v01;
                base[8]      = v10;
                base[Ss + 8] = v11;
            }
        }
    }
}

// fc output projection (pre-rounded inputs, fp32 epilogue with bias)
__global__ __launch_bounds__(256, 2)
void fc_gemm(const float* __restrict__ A, const float* __restrict__ W,
             const float* __restrict__ bias, float* __restrict__ C)
{
    __shared__ __align__(16) float As[2][GBM * GSTR];
    __shared__ __align__(16) float Bs[2][GBN * GSTR];

    const int m0 = blockIdx.y * GBM;
    const int n0 = blockIdx.x * GBN;

    GemmCtx ctx;
    gemm_mainloop(A, W, m0, n0, Dd, As, Bs, ctx);

    const int lane = threadIdx.x & 31;
    const int wid  = threadIdx.x >> 5;
    const int wm   = (wid & 1) * 64;
    const int wn   = (wid >> 1) * 32;

#pragma unroll
    for (int mt = 0; mt < 4; mt++) {
        const int row = m0 + wm + mt * 16 + (lane >> 2);
#pragma unroll
        for (int nt = 0; nt < 4; nt++) {
            const int col = n0 + wn + nt * 8 + (lane & 3) * 2;
            const float b0 = bias[col], b1 = bias[col + 1];
            *(float2*)&C[(size_t)row * Dd + col] =
                make_float2(ctx.acc[mt][nt][0] + b0, ctx.acc[mt][nt][1] + b1);
            *(float2*)&C[(size_t)(row + 8) * Dd + col] =
                make_float2(ctx.acc[mt][nt][2] + b0, ctx.acc[mt][nt][3] + b1);
        }
    }
}

// ---------------------------------------------------------------------------
// Tensor-core flash attention. 64-query CTA, 4 warps, 2 CTA/SM.
// QK = Qhat·Khat (plain tf32, 8 mma/ks); PV plain tf32 (8 mma/ks).
// Fully cvt-free inner loops (Q/K/V pre-rounded; P rounded at store).
// ---------------------------------------------------------------------------
#define FSTR 68
#define KV_TILE (64 * FSTR)
#define FLASH_SMEM_FLOATS (4 * KV_TILE + 64 * FSTR)
#define FLASH_SMEM_BYTES (FLASH_SMEM_FLOATS * 4)   // 87040

__global__ __launch_bounds__(128, 2)
void flash_attn_tc(const float* __restrict__ Qp, const float* __restrict__ Kh_g,
                   const float* __restrict__ VT_g, const float* __restrict__ mask,
                   float* __restrict__ Out, float* __restrict__ FCin)
{
    extern __shared__ float fsm[];
    float* Khb  = fsm;                       // 2 * KV_TILE
    float* Vtb  = Khb + 2 * KV_TILE;         // 2 * KV_TILE (rows=d, cols=key)
    float* Pbuf = Vtb + 2 * KV_TILE;         // 64 * FSTR (Q stage, then P)

    const uint32_t sKh = cvta_smem(Khb);
    const uint32_t sVt = cvta_smem(Vtb);
    const uint32_t sP  = cvta_smem(Pbuf);

    const int tid  = threadIdx.x;
    const int lane = tid & 31;
    const int wid  = tid >> 5;          // 0..3
    const int wm   = wid * 16;
    const int q0   = blockIdx.x * 64;
    const int h    = blockIdx.y;
    const int b    = blockIdx.z;

    const float* Qg  = Qp   + ((size_t)b * Ss + q0) * Dd + h * DP;
    const float* Khg = Kh_g + ((size_t)b * Ss) * Dd + h * DP;
    const float* VTg = VT_g + ((size_t)b * Hh + h) * DP * Ss;  // [d][s]
    const float* Mg  = mask + (((size_t)b * Hh + h) * Ss + q0) * Ss;

    const int g       = lane >> 3;
    const int glr     = lane & 7;
    const int row_add = ((g >> 1) << 3) + glr;
    const int koff    = (g & 1) << 2;

    const int rq = lane >> 2;
    const int cq = lane & 3;

    const int lrow = tid >> 4;          // 0..7 (+8*i)
    const int lcol = tid & 15;

    // ---- prefetch tile 0 ----
    {
#pragma unroll
        for (int i = 0; i < 8; i++) {
            int row = lrow + 8 * i;
            uint32_t so = (uint32_t)((row * FSTR + lcol * 4) * 4);
            cp_async16(sKh + so, Khg + (size_t)row * Dd + lcol * 4);
            cp_async16(sVt + so, VTg + (size_t)row * Ss + lcol * 4);
        }
        cp_commit();
    }

    // ---- stage Q into Pbuf, extract fragments (pre-rounded -> raw bits) ----
#pragma unroll
    for (int i = 0; i < 8; i++) {
        int id = tid + 128 * i;              // 0..1023
        int row = id >> 4, col = id & 15;    // 64 rows x 16 chunks
        float4 v = *(const float4*)(Qg + (size_t)row * Dd + col * 4);
        *(float4*)&Pbuf[row * FSTR + col * 4] = v;
    }
    __syncthreads();

    uint32_t Qh[8][4];
    {
        const uint32_t base = sP + (uint32_t)(((wm + row_add) * FSTR + koff) * 4);
#pragma unroll
        for (int ks = 0; ks < 8; ks++) {
            uint32_t r0, r1, r2, r3;
            ldsm_x4(r0, r1, r2, r3, base + (uint32_t)(ks * 32));
            Qh[ks][0] = r0;
            Qh[ks][1] = r2;
            Qh[ks][2] = r1;
            Qh[ks][3] = r3;
        }
    }

    float O[8][4];
#pragma unroll
    for (int nt = 0; nt < 8; nt++)
#pragma unroll
        for (int c = 0; c < 4; c++) O[nt][c] = 0.f;
    float m0r = NEG_INF, m1r = NEG_INF, l0r = 0.f, l1r = 0.f;

    for (int kt = 0; kt < 32; kt++) {
        cp_wait0();
        __syncthreads();   // tile kt visible; all warps done with buffer (kt+1)&1

        // prefetch tile kt+1
        if (kt + 1 < 32) {
            const uint32_t bo = (uint32_t)(((kt + 1) & 1) * KV_TILE * 4);
            const float* khg = Khg + (size_t)(kt + 1) * 64 * Dd;
            const float* vtg = VTg + (size_t)(kt + 1) * 64;
#pragma unroll
            for (int i = 0; i < 8; i++) {
                int row = lrow + 8 * i;
                uint32_t so = (uint32_t)((row * FSTR + lcol * 4) * 4);
                cp_async16(sKh + bo + so, khg + (size_t)row * Dd + lcol * 4);
                cp_async16(sVt + bo + so, vtg + (size_t)row * Ss + lcol * 4);
            }
            cp_commit();
        }

        // mask fragments (overlap DRAM with QK mma)
        float2 mk0[8], mk1[8];
        {
            const float* mr0 = Mg + (size_t)(wm + rq) * Ss + kt * 64 + 2 * cq;
            const float* mr1 = mr0 + 8 * Ss;
#pragma unroll
            for (int nt = 0; nt < 8; nt++) {
                mk0[nt] = *(const float2*)(mr0 + nt * 8);
                mk1[nt] = *(const float2*)(mr1 + nt * 8);
            }
        }

        // ---- S = Qhat · Khat (plain tf32, cvt-free) ----
        float S[8][4];
#pragma unroll
        for (int nt = 0; nt < 8; nt++)
#pragma unroll
            for (int c = 0; c < 4; c++) S[nt][c] = 0.f;

        const uint32_t khb = sKh + (uint32_t)((kt & 1) * KV_TILE * 4)
                           + (uint32_t)((row_add * FSTR + koff) * 4);
#pragma unroll
        for (int ks = 0; ks < 8; ks++) {
#pragma unroll
            for (int p = 0; p < 4; p++) {
                const uint32_t off = (uint32_t)((p * 16 * FSTR) * 4 + ks * 32);
                uint32_t h0, h1, h2, h3;
                ldsm_x4(h0, h1, h2, h3, khb + off);
                const int n0 = 2 * p, n1 = 2 * p + 1;
                mma_tf32(S[n0][0], S[n0][1], S[n0][2], S[n0][3],
                         Qh[ks][0], Qh[ks][1], Qh[ks][2], Qh[ks][3], h0, h1);
                mma_tf32(S[n1][0], S[n1][1], S[n1][2], S[n1][3],
                         Qh[ks][0], Qh[ks][1], Qh[ks][2], Qh[ks][3], h2, h3);
            }
        }

        // ---- scale + mask + online softmax ----
        float rm0 = NEG_INF, rm1 = NEG_INF;
#pragma unroll
        for (int nt = 0; nt < 8; nt++) {
            S[nt][0] = S[nt][0] * 0.125f + mk0[nt].x * (-1e9f);
            S[nt][1] = S[nt][1] * 0.125f + mk0[nt].y * (-1e9f);
            S[nt][2] = S[nt][2] * 0.125f + mk1[nt].x * (-1e9f);
            S[nt][3] = S[nt][3] * 0.125f + mk1[nt].y * (-1e9f);
            rm0 = fmaxf(rm0, fmaxf(S[nt][0], S[nt][1]));
            rm1 = fmaxf(rm1, fmaxf(S[nt][2], S[nt][3]));
        }
        rm0 = fmaxf(rm0, __shfl_xor_sync(0xffffffffu, rm0, 1));
        rm0 = fmaxf(rm0, __shfl_xor_sync(0xffffffffu, rm0, 2));
        rm1 = fmaxf(rm1, __shfl_xor_sync(0xffffffffu, rm1, 1));
        rm1 = fmaxf(rm1, __shfl_xor_sync(0xffffffffu, rm1, 2));

        const float nm0 = fmaxf(m0r, rm0);
        const float nm1 = fmaxf(m1r, rm1);
        const float sc0 = __expf(m0r - nm0);
        const float sc1 = __expf(m1r - nm1);
        m0r = nm0; m1r = nm1;

        float rs0 = 0.f, rs1 = 0.f;
#pragma unroll
        for (int nt = 0; nt < 8; nt++) {
            S[nt][0] = __expf(S[nt][0] - nm0);
            S[nt][1] = __expf(S[nt][1] - nm0);
            S[nt][2] = __expf(S[nt][2] - nm1);
            S[nt][3] = __expf(S[nt][3] - nm1);
            rs0 += S[nt][0] + S[nt][1];
            rs1 += S[nt][2] + S[nt][3];
        }
        rs0 += __shfl_xor_sync(0xffffffffu, rs0, 1);
        rs0 += __shfl_xor_sync(0xffffffffu, rs0, 2);
        rs1 += __shfl_xor_sync(0xffffffffu, rs1, 1);
        rs1 += __shfl_xor_sync(0xffffffffu, rs1, 2);
        l0r = l0r * sc0 + rs0;
        l1r = l1r * sc1 + rs1;

#pragma unroll
        for (int nt = 0; nt < 8; nt++) {
            O[nt][0] *= sc0; O[nt][1] *= sc0;
            O[nt][2] *= sc1; O[nt][3] *= sc1;
        }

        // ---- store P tf32-rounded (bit-identical to rounding after load) ----
        {
            float* p0 = Pbuf + (wm + rq) * FSTR + 2 * cq;
            float* p1 = p0 + 8 * FSTR;
#pragma unroll
            for (int nt = 0; nt < 8; nt++) {
                *(float2*)(p0 + nt * 8) =
                    make_float2(tf32_round(S[nt][0]), tf32_round(S[nt][1]));
                *(float2*)(p1 + nt * 8) =
                    make_float2(tf32_round(S[nt][2]), tf32_round(S[nt][3]));
            }
        }
        __syncwarp();

        // ---- O += P V (cvt-free) ----
        const uint32_t pb = sP + (uint32_t)(((wm + row_add) * FSTR + koff) * 4);
        const uint32_t vb = sVt + (uint32_t)((kt & 1) * KV_TILE * 4)
                          + (uint32_t)((row_add * FSTR + koff) * 4);
#pragma unroll
        for (int ks = 0; ks < 8; ks++) {
            uint32_t pr0, pr1, pr2, pr3;
            ldsm_x4(pr0, pr1, pr2, pr3, pb + (uint32_t)(ks * 32));
            uint32_t a0 = pr0, a1 = pr2, a2 = pr1, a3 = pr3;
#pragma unroll
            for (int p = 0; p < 4; p++) {
                uint32_t v0, v1, v2, v3;
                ldsm_x4(v0, v1, v2, v3, vb + (uint32_t)((p * 16 * FSTR) * 4 + ks * 32));
                const int n0 = 2 * p, n1 = 2 * p + 1;
                mma_tf32(O[n0][0], O[n0][1], O[n0][2], O[n0][3], a0, a1, a2, a3, v0, v1);
                mma_tf32(O[n1][0], O[n1][1], O[n1][2], O[n1][3], a0, a1, a2, a3, v2, v3);
            }
        }
    }

    // ---- epilogue: attn fp32 + tf32-rounded fc input ----
    const float inv0 = 1.f / l0r;
    const float inv1 = 1.f / l1r;
    const size_t base_off = ((size_t)b * Ss + q0 + wm + rq) * Dd + h * DP + 2 * cq;
    float* o0 = Out + base_off;
    float* o1 = o0 + (size_t)8 * Dd;
    float* f0 = FCin + base_off;
    float* f1 = f0 + (size_t)8 * Dd;
#pragma unroll
    for (int nt = 0; nt < 8; nt++) {
        float a = O[nt][0] * inv0, bb2 = O[nt][1] * inv0;
        float c = O[nt][2] * inv1, d = O[nt][3] * inv1;
        *(float2*)(o0 + nt * 8) = make_float2(a, bb2);
        *(float2*)(o1 + nt * 8) = make_float2(c, d);
        *(float2*)(f0 + nt * 8) = make_float2(tf32_round(a), tf32_round(bb2));
        *(float2*)(f1 + nt * 8) = make_float2(tf32_round(c), tf32_round(d));
    }
}

// ---------------------------------------------------------------------------
extern "C" void kernel_launch(void* const* d_in, const int* in_sizes, int n_in,
                              void* d_out, int out_size)
{
    const float* q    = (const float*)d_in[0];
    const float* k    = (const float*)d_in[1];
    const float* v    = (const float*)d_in[2];
    const float* mask = (const float*)d_in[3];
    const float* wq_w = (const float*)d_in[4];
    const float* wq_b = (const float*)d_in[5];
    const float* wk_w = (const float*)d_in[6];
    const float* wk_b = (const float*)d_in[7];
    const float* wv_w = (const float*)d_in[8];
    const float* wv_b = (const float*)d_in[9];
    const float* fc_w = (const float*)d_in[10];
    const float* fc_b = (const float*)d_in[11];

    float *pQ, *pKh, *pVT, *pScr, *pFC;
    float *pqr, *pkr, *pvr, *pwqr, *pwkr, *pwvr, *pwfr;
    cudaGetSymbolAddress((void**)&pQ, g_Qp);
    cudaGetSymbolAddress((void**)&pKh, g_Kh);
    cudaGetSymbolAddress((void**)&pVT, g_VT);
    cudaGetSymbolAddress((void**)&pScr, g_attn_scratch);
    cudaGetSymbolAddress((void**)&pFC, g_FCin);
    cudaGetSymbolAddress((void**)&pqr, g_qr);
    cudaGetSymbolAddress((void**)&pkr, g_kr);
    cudaGetSymbolAddress((void**)&pvr, g_vr);
    cudaGetSymbolAddress((void**)&pwqr, g_wqr);
    cudaGetSymbolAddress((void**)&pwkr, g_wkr);
    cudaGetSymbolAddress((void**)&pwvr, g_wvr);
    cudaGetSymbolAddress((void**)&pwfr, g_wfr);

    float* out_main = (float*)d_out;
    const size_t OUT1 = (size_t)MM * Dd;
    float* attn_out = ((size_t)out_size >= 2 * OUT1) ? (out_main + OUT1) : pScr;

    static bool attr_set = false;
    if (!attr_set) {
        cudaFuncSetAttribute(flash_attn_tc, cudaFuncAttributeMaxDynamicSharedMemorySize,
                             FLASH_SMEM_BYTES);
        attr_set = true;
    }

    // Stage 0: tf32 rounding pre-pass
    const int NA4 = (MM * Dd) / 4;       // 1M float4
    const int NW4 = (Dd * Dd) / 4;       // 256K float4
    round_tf32_kernel<<<(NA4 + 255) / 256, 256>>>((const float4*)q, (float4*)pqr, NA4);
    round_tf32_kernel<<<(NA4 + 255) / 256, 256>>>((const float4*)k, (float4*)pkr, NA4);
    round_tf32_kernel<<<(NA4 + 255) / 256, 256>>>((const float4*)v, (float4*)pvr, NA4);
    round_tf32_kernel<<<(NW4 + 255) / 256, 256>>>((const float4*)wq_w, (float4*)pwqr, NW4);
    round_tf32_kernel<<<(NW4 + 255) / 256, 256>>>((const float4*)wk_w, (float4*)pwkr, NW4);
    round_tf32_kernel<<<(NW4 + 255) / 256, 256>>>((const float4*)wv_w, (float4*)pwvr, NW4);
    round_tf32_kernel<<<(NW4 + 255) / 256, 256>>>((const float4*)fc_w, (float4*)pwfr, NW4);

    qkv_gemm<<<dim3(Dd / GBN, MM / GBM, 3), 256>>>(
        pqr, pkr, pvr, pwqr, pwkr, pwvr, wq_b, wk_b, wv_b, pQ, pKh, pVT);

    flash_attn_tc<<<dim3(Ss / 64, Hh, Bb), 128, FLASH_SMEM_BYTES>>>(
        pQ, pKh, pVT, mask, attn_out, pFC);

    fc_gemm<<<dim3(Dd / GBN, MM / GBM), 256>>>(pFC, pwfr, fc_b, out_main);
}